// round 1
// baseline (speedup 1.0000x reference)
#include <cuda_runtime.h>
#include <math.h>

// Problem constants
#define BB 4
#define SS 1024
#define DD 1024
#define HH 16
#define DKK 64
#define DFFF 4096
#define ROWS 16   // attention rows per block

// ---------------- scratch (device globals: allocation-guard-safe) ------------
__device__ float g_q[BB*SS*DD];
__device__ float g_k[BB*SS*DD];
__device__ float g_v[BB*SS*DD];
__device__ float g_concat[BB*SS*DD];
__device__ float g_attnout[BB*SS*DD];
__device__ float g_x[BB*SS*DD];
__device__ float g_h[BB*SS*DFFF];
__device__ float g_f[BB*SS*DD];

// ---------------- NT SGEMM: C[M,N] = A[M,K] @ W[N,K]^T + bias (opt ReLU) -----
template<bool RELU>
__global__ void __launch_bounds__(256) gemm_nt_bias(
    const float* __restrict__ A, const float* __restrict__ W,
    const float* __restrict__ bias, float* __restrict__ C,
    int M, int N, int K)
{
    const int BM = 128, BN = 128, BK = 8;
    __shared__ float As[BK][BM];
    __shared__ float Ws[BK][BN];

    int t  = threadIdx.x;
    int bm = blockIdx.y * BM;
    int bn = blockIdx.x * BN;

    int lr = t >> 1;          // 0..127
    int lc = (t & 1) * 4;     // 0 or 4
    const float* Ap = A + (size_t)(bm + lr) * K + lc;
    const float* Wp = W + (size_t)(bn + lr) * K + lc;

    float4 av = *(const float4*)Ap;
    float4 wv = *(const float4*)Wp;

    int tx = t & 15, ty = t >> 4;
    float acc[8][8];
#pragma unroll
    for (int i = 0; i < 8; i++)
#pragma unroll
        for (int j = 0; j < 8; j++) acc[i][j] = 0.f;

    for (int k0 = 0; k0 < K; k0 += BK) {
        __syncthreads();
        As[lc+0][lr] = av.x; As[lc+1][lr] = av.y; As[lc+2][lr] = av.z; As[lc+3][lr] = av.w;
        Ws[lc+0][lr] = wv.x; Ws[lc+1][lr] = wv.y; Ws[lc+2][lr] = wv.z; Ws[lc+3][lr] = wv.w;
        __syncthreads();
        if (k0 + BK < K) {
            av = *(const float4*)(Ap + k0 + BK);
            wv = *(const float4*)(Wp + k0 + BK);
        }
#pragma unroll
        for (int kk = 0; kk < BK; kk++) {
            float a[8], b[8];
            *(float4*)&a[0] = *(const float4*)&As[kk][ty*8];
            *(float4*)&a[4] = *(const float4*)&As[kk][ty*8+4];
            *(float4*)&b[0] = *(const float4*)&Ws[kk][tx*8];
            *(float4*)&b[4] = *(const float4*)&Ws[kk][tx*8+4];
#pragma unroll
            for (int i = 0; i < 8; i++)
#pragma unroll
                for (int j = 0; j < 8; j++)
                    acc[i][j] = fmaf(a[i], b[j], acc[i][j]);
        }
    }

#pragma unroll
    for (int i = 0; i < 8; i++) {
        size_t row = (size_t)(bm + ty*8 + i);
#pragma unroll
        for (int j = 0; j < 8; j += 4) {
            int col = bn + tx*8 + j;
            float4 o;
            o.x = acc[i][j+0] + bias[col+0];
            o.y = acc[i][j+1] + bias[col+1];
            o.z = acc[i][j+2] + bias[col+2];
            o.w = acc[i][j+3] + bias[col+3];
            if (RELU) {
                o.x = fmaxf(o.x, 0.f); o.y = fmaxf(o.y, 0.f);
                o.z = fmaxf(o.z, 0.f); o.w = fmaxf(o.w, 0.f);
            }
            *(float4*)&C[row * N + col] = o;
        }
    }
}

// ---------------- fused distance-decay attention ----------------------------
// grid: (S/ROWS, H, B), 256 threads.
// smem: q[ROWS*DK] | sc[ROWS*S] | kt[32*65]
__global__ void __launch_bounds__(256) attn_kernel(
    const float* __restrict__ gq, const float* __restrict__ gk,
    const float* __restrict__ gv, const float* __restrict__ gammas,
    float* __restrict__ outp)
{
    extern __shared__ float sm[];
    float* q  = sm;                       // ROWS*DKK
    float* sc = q + ROWS*DKK;             // ROWS*SS
    float* kt = sc + ROWS*SS;             // 32*65

    int b  = blockIdx.z;
    int h  = blockIdx.y;
    int i0 = blockIdx.x * ROWS;
    int t  = threadIdx.x;

    const float* Qb = gq + (size_t)b*SS*DD + h*DKK;
    const float* Kb = gk + (size_t)b*SS*DD + h*DKK;
    const float* Vb = gv + (size_t)b*SS*DD + h*DKK;

    // load Q tile
    {
        int r = t >> 4;           // 0..15
        int c = (t & 15) * 4;     // 0..60
        float4 v4 = *(const float4*)&Qb[(size_t)(i0 + r)*DD + c];
        *(float4*)&q[r*DKK + c] = v4;
    }
    __syncthreads();

    // ---- scores: sc[r][j] = (q_r . k_j) / 8 over ALL j (unmasked softmax #1)
    const float scale = 0.125f;
    int si = t >> 4;      // row 0..15
    int jl = t & 15;      // 0..15 -> handles jl and jl+16
    for (int j0 = 0; j0 < SS; j0 += 32) {
        __syncthreads();
        {   // stage K tile 32x64 (row pad 65 for conflict-free reads)
            int r  = t >> 3;          // 0..31
            int c0 = (t & 7) * 8;     // 0..56
            float4 v0 = *(const float4*)&Kb[(size_t)(j0 + r)*DD + c0];
            float4 v1 = *(const float4*)&Kb[(size_t)(j0 + r)*DD + c0 + 4];
            float* dst = &kt[r*65 + c0];
            dst[0]=v0.x; dst[1]=v0.y; dst[2]=v0.z; dst[3]=v0.w;
            dst[4]=v1.x; dst[5]=v1.y; dst[6]=v1.z; dst[7]=v1.w;
        }
        __syncthreads();
        float s0 = 0.f, s1 = 0.f;
#pragma unroll
        for (int kk = 0; kk < DKK; kk++) {
            float qa = q[si*DKK + kk];
            s0 = fmaf(qa, kt[jl*65 + kk],      s0);
            s1 = fmaf(qa, kt[(jl+16)*65 + kk], s1);
        }
        sc[si*SS + j0 + jl]      = s0 * scale;
        sc[si*SS + j0 + jl + 16] = s1 * scale;
    }
    __syncthreads();

    // ---- per-row math: softmax#1 (full row) -> masked cumsum -> decay -> softmax#2
    {
        int warp = t >> 5, lane = t & 31;
        float gamma = -log1pf(__expf(gammas[h]));   // -softplus
        for (int rr = 0; rr < 2; rr++) {
            int r  = warp*2 + rr;
            int ig = i0 + r;
            float* row = sc + r*SS;

            // max over all j
            float m = -INFINITY;
            for (int j = lane; j < SS; j += 32) m = fmaxf(m, row[j]);
#pragma unroll
            for (int o = 16; o > 0; o >>= 1) m = fmaxf(m, __shfl_xor_sync(0xffffffffu, m, o));

            // sums: full (softmax denom) and masked (disttot numerator)
            float sum1 = 0.f, summ = 0.f;
            for (int j = lane; j < SS; j += 32) {
                float p = __expf(row[j] - m);
                sum1 += p;
                if (j <= ig) summ += p;
            }
#pragma unroll
            for (int o = 16; o > 0; o >>= 1) {
                sum1 += __shfl_xor_sync(0xffffffffu, sum1, o);
                summ += __shfl_xor_sync(0xffffffffu, summ, o);
            }
            float inv1    = 1.f / sum1;
            float disttot = summ * inv1;

            // masked cumsum (inclusive) + decay transform, track max of s2
            float carry = 0.f, m2 = -INFINITY;
            for (int j0 = 0; j0 < SS; j0 += 32) {
                int j = j0 + lane;
                float sraw = row[j];
                float pj = (j <= ig) ? __expf(sraw - m) * inv1 : 0.f;
                float x = pj;
#pragma unroll
                for (int o = 1; o < 32; o <<= 1) {
                    float y = __shfl_up_sync(0xffffffffu, x, o);
                    if (lane >= o) x += y;
                }
                float distcum = carry + x;
                carry += __shfl_sync(0xffffffffu, x, 31);
                float pos  = fabsf((float)(ig - j));
                float dd   = (disttot - distcum) * pos;
                float dist = sqrtf(fmaxf(dd, 0.f));
                float eff  = __expf(dist * gamma);        // in (0,1]
                eff = fminf(fmaxf(eff, 1e-5f), 1e5f);
                float s2 = (j <= ig) ? sraw * eff : -INFINITY;
                row[j] = s2;
                m2 = fmaxf(m2, s2);
            }
#pragma unroll
            for (int o = 16; o > 0; o >>= 1) m2 = fmaxf(m2, __shfl_xor_sync(0xffffffffu, m2, o));

            // softmax #2
            float sum2 = 0.f;
            for (int j = lane; j < SS; j += 32) {
                float e = (j <= ig) ? __expf(row[j] - m2) : 0.f;
                row[j] = e;
                sum2 += e;
            }
#pragma unroll
            for (int o = 16; o > 0; o >>= 1) sum2 += __shfl_xor_sync(0xffffffffu, sum2, o);
            float inv2 = 1.f / sum2;
            for (int j = lane; j < SS; j += 32) row[j] *= inv2;
        }
    }
    __syncthreads();

    // ---- PV: out[r][d] = sum_j attn[r][j] * V[j][d] (skip fully-masked tiles)
    {
        int d  = t & 63;
        int rg = t >> 6;           // 0..3 -> rows rg, rg+4, rg+8, rg+12
        float acc[4] = {0.f, 0.f, 0.f, 0.f};
        int jmax = i0 + ROWS;      // attn == 0 beyond the last row's diagonal
        for (int j0 = 0; j0 < jmax; j0 += 32) {
            __syncthreads();
            {   // stage V tile
                int r  = t >> 3;
                int c0 = (t & 7) * 8;
                float4 v0 = *(const float4*)&Vb[(size_t)(j0 + r)*DD + c0];
                float4 v1 = *(const float4*)&Vb[(size_t)(j0 + r)*DD + c0 + 4];
                float* dst = &kt[r*65 + c0];
                dst[0]=v0.x; dst[1]=v0.y; dst[2]=v0.z; dst[3]=v0.w;
                dst[4]=v1.x; dst[5]=v1.y; dst[6]=v1.z; dst[7]=v1.w;
            }
            __syncthreads();
#pragma unroll
            for (int jj = 0; jj < 32; jj++) {
                float vv = kt[jj*65 + d];
                acc[0] = fmaf(sc[(rg     )*SS + j0 + jj], vv, acc[0]);
                acc[1] = fmaf(sc[(rg +  4)*SS + j0 + jj], vv, acc[1]);
                acc[2] = fmaf(sc[(rg +  8)*SS + j0 + jj], vv, acc[2]);
                acc[3] = fmaf(sc[(rg + 12)*SS + j0 + jj], vv, acc[3]);
            }
        }
#pragma unroll
        for (int rr = 0; rr < 4; rr++) {
            int r = rg + rr*4;
            outp[((size_t)b*SS + (i0 + r))*DD + h*DKK + d] = acc[rr];
        }
    }
}

// ---------------- residual add + LayerNorm (one block per row of D=1024) ----
__global__ void __launch_bounds__(256) add_ln_kernel(
    const float* __restrict__ A, const float* __restrict__ Bres,
    const float* __restrict__ w, const float* __restrict__ bias,
    float* __restrict__ outp)
{
    __shared__ float red1[8], red2[8];
    int row = blockIdx.x;
    int t   = threadIdx.x;
    const float* pa = A    + (size_t)row*DD;
    const float* pb = Bres + (size_t)row*DD;

    float4 a4 = *(const float4*)&pa[t*4];
    float4 b4 = *(const float4*)&pb[t*4];
    float v0 = a4.x + b4.x, v1 = a4.y + b4.y, v2 = a4.z + b4.z, v3 = a4.w + b4.w;

    int lane = t & 31, wp = t >> 5;
    float s = v0 + v1 + v2 + v3;
#pragma unroll
    for (int o = 16; o > 0; o >>= 1) s += __shfl_xor_sync(0xffffffffu, s, o);
    if (lane == 0) red1[wp] = s;
    __syncthreads();
    float tot = 0.f;
#pragma unroll
    for (int i = 0; i < 8; i++) tot += red1[i];
    float mu = tot * (1.f / DD);

    float d0 = v0-mu, d1 = v1-mu, d2 = v2-mu, d3 = v3-mu;
    float q2 = d0*d0 + d1*d1 + d2*d2 + d3*d3;
#pragma unroll
    for (int o = 16; o > 0; o >>= 1) q2 += __shfl_xor_sync(0xffffffffu, q2, o);
    if (lane == 0) red2[wp] = q2;
    __syncthreads();
    float tv = 0.f;
#pragma unroll
    for (int i = 0; i < 8; i++) tv += red2[i];
    float inv = rsqrtf(tv * (1.f / DD) + 1e-5f);

    float4 w4  = *(const float4*)&w[t*4];
    float4 bi4 = *(const float4*)&bias[t*4];
    float4 o4;
    o4.x = d0*inv*w4.x + bi4.x;
    o4.y = d1*inv*w4.y + bi4.y;
    o4.z = d2*inv*w4.z + bi4.z;
    o4.w = d3*inv*w4.w + bi4.w;
    *(float4*)&outp[(size_t)row*DD + t*4] = o4;
}

// ---------------- launcher ---------------------------------------------------
extern "C" void kernel_launch(void* const* d_in, const int* in_sizes, int n_in,
                              void* d_out, int out_size)
{
    // If the static python int `mask` is materialized as input 0 (size 1),
    // real tensors start at index 1; otherwise at 0. mask is always 1 here.
    int off = (in_sizes[0] == 1) ? 1 : 0;
    const float* query  = (const float*)d_in[off + 0];
    const float* key    = (const float*)d_in[off + 1];
    const float* values = (const float*)d_in[off + 2];
    const float* Wq = (const float*)d_in[off + 3];
    const float* bq = (const float*)d_in[off + 4];
    const float* Wk = (const float*)d_in[off + 5];
    const float* bk = (const float*)d_in[off + 6];
    const float* Wv = (const float*)d_in[off + 7];
    const float* bv = (const float*)d_in[off + 8];
    const float* Wo = (const float*)d_in[off + 9];
    const float* bo = (const float*)d_in[off + 10];
    const float* gammas = (const float*)d_in[off + 11];
    const float* ln1w = (const float*)d_in[off + 12];
    const float* ln1b = (const float*)d_in[off + 13];
    const float* W1 = (const float*)d_in[off + 14];
    const float* b1 = (const float*)d_in[off + 15];
    const float* W2 = (const float*)d_in[off + 16];
    const float* b2 = (const float*)d_in[off + 17];
    const float* ln2w = (const float*)d_in[off + 18];
    const float* ln2b = (const float*)d_in[off + 19];

    float *pq, *pk, *pv, *pconcat, *pattnout, *px, *ph, *pf;
    cudaGetSymbolAddress((void**)&pq, g_q);
    cudaGetSymbolAddress((void**)&pk, g_k);
    cudaGetSymbolAddress((void**)&pv, g_v);
    cudaGetSymbolAddress((void**)&pconcat, g_concat);
    cudaGetSymbolAddress((void**)&pattnout, g_attnout);
    cudaGetSymbolAddress((void**)&px, g_x);
    cudaGetSymbolAddress((void**)&ph, g_h);
    cudaGetSymbolAddress((void**)&pf, g_f);

    const int M = BB * SS;   // 4096

    // QKV projections
    dim3 gD(DD/128, M/128);
    gemm_nt_bias<false><<<gD, 256>>>(query,  Wq, bq, pq, M, DD, DD);
    gemm_nt_bias<false><<<gD, 256>>>(key,    Wk, bk, pk, M, DD, DD);
    gemm_nt_bias<false><<<gD, 256>>>(values, Wv, bv, pv, M, DD, DD);

    // attention
    size_t smem = (size_t)(ROWS*DKK + ROWS*SS + 32*65) * sizeof(float);
    cudaFuncSetAttribute(attn_kernel, cudaFuncAttributeMaxDynamicSharedMemorySize, (int)smem);
    attn_kernel<<<dim3(SS/ROWS, HH, BB), 256, smem>>>(pq, pk, pv, gammas, pconcat);

    // output projection
    gemm_nt_bias<false><<<gD, 256>>>(pconcat, Wo, bo, pattnout, M, DD, DD);

    // LN1
    add_ln_kernel<<<M, 256>>>(query, pattnout, ln1w, ln1b, px);

    // FFN
    gemm_nt_bias<true ><<<dim3(DFFF/128, M/128), 256>>>(px, W1, b1, ph, M, DFFF, DD);
    gemm_nt_bias<false><<<dim3(DD/128,   M/128), 256>>>(ph, W2, b2, pf, M, DD, DFFF);

    // LN2 -> final output
    add_ln_kernel<<<M, 256>>>(px, pf, ln2w, ln2b, (float*)d_out);
}

// round 3
// speedup vs baseline: 1.5746x; 1.5746x over previous
#include <cuda_runtime.h>
#include <cuda_bf16.h>
#include <math.h>
#include <stdint.h>

// Problem constants
#define BB 4
#define SS 1024
#define DD 1024
#define HH 16
#define DKK 64
#define DFFF 4096
#define ROWS 16   // attention rows per block

// ---------------- scratch (device globals) -----------------------------------
__device__ float g_q[BB*SS*DD];
__device__ float g_k[BB*SS*DD];
__device__ float g_v[BB*SS*DD];
__device__ float g_concat[BB*SS*DD];
__device__ float g_attnout[BB*SS*DD];
__device__ float g_x[BB*SS*DD];
__device__ float g_h[BB*SS*DFFF];
__device__ float g_f[BB*SS*DD];
// bf16 split buffers
__device__ __nv_bfloat16 g_ahi[BB*SS*DFFF];
__device__ __nv_bfloat16 g_alo[BB*SS*DFFF];
__device__ __nv_bfloat16 g_whi[DFFF*DD];
__device__ __nv_bfloat16 g_wlo[DFFF*DD];

// ======================= PTX helpers (plain sm_80+ path) ====================
__device__ __forceinline__ uint32_t smem_u32(const void* p) {
    uint32_t a;
    asm("{ .reg .u64 t; cvta.to.shared.u64 t, %1; cvt.u32.u64 %0, t; }" : "=r"(a) : "l"(p));
    return a;
}

#define CPASYNC16(dst, src) asm volatile("cp.async.cg.shared.global [%0], [%1], 16;" :: "r"(dst), "l"(src) : "memory")
#define CPCOMMIT() asm volatile("cp.async.commit_group;" ::: "memory")
#define CPWAIT1()  asm volatile("cp.async.wait_group 1;" ::: "memory")
#define CPWAIT0()  asm volatile("cp.async.wait_group 0;" ::: "memory")

#define LDSM_X4(R, A) \
    asm volatile("ldmatrix.sync.aligned.m8n8.x4.shared.b16 {%0,%1,%2,%3}, [%4];" \
        : "=r"((R)[0]), "=r"((R)[1]), "=r"((R)[2]), "=r"((R)[3]) : "r"(A))

__device__ __forceinline__ void mma_bf16(float* c, const uint32_t* a, const uint32_t* b) {
    asm volatile(
        "mma.sync.aligned.m16n8k16.row.col.f32.bf16.bf16.f32 "
        "{%0,%1,%2,%3}, {%4,%5,%6,%7}, {%8,%9}, {%0,%1,%2,%3};"
        : "+f"(c[0]), "+f"(c[1]), "+f"(c[2]), "+f"(c[3])
        : "r"(a[0]), "r"(a[1]), "r"(a[2]), "r"(a[3]), "r"(b[0]), "r"(b[1]));
}

// ================ split fp32 -> bf16 hi/lo ==================================
__global__ void __launch_bounds__(256) split_kernel(
    const float* __restrict__ in, __nv_bfloat16* __restrict__ hi,
    __nv_bfloat16* __restrict__ lo, int n4)
{
    int i = blockIdx.x * 256 + threadIdx.x;
    if (i >= n4) return;
    float4 v = ((const float4*)in)[i];
    __nv_bfloat16 h0 = __float2bfloat16(v.x);
    __nv_bfloat16 h1 = __float2bfloat16(v.y);
    __nv_bfloat16 h2 = __float2bfloat16(v.z);
    __nv_bfloat16 h3 = __float2bfloat16(v.w);
    __nv_bfloat16 l0 = __float2bfloat16(v.x - __bfloat162float(h0));
    __nv_bfloat16 l1 = __float2bfloat16(v.y - __bfloat162float(h1));
    __nv_bfloat16 l2 = __float2bfloat16(v.z - __bfloat162float(h2));
    __nv_bfloat16 l3 = __float2bfloat16(v.w - __bfloat162float(h3));
    __nv_bfloat162 hp0; hp0.x = h0; hp0.y = h1;
    __nv_bfloat162 hp1; hp1.x = h2; hp1.y = h3;
    __nv_bfloat162 lp0; lp0.x = l0; lp0.y = l1;
    __nv_bfloat162 lp1; lp1.x = l2; lp1.y = l3;
    ((__nv_bfloat162*)hi)[i*2+0] = hp0;
    ((__nv_bfloat162*)hi)[i*2+1] = hp1;
    ((__nv_bfloat162*)lo)[i*2+0] = lp0;
    ((__nv_bfloat162*)lo)[i*2+1] = lp1;
}

// ============ mma.sync bf16x3 GEMM: C[M,N] = A @ W^T + bias (opt ReLU) =======
// A ~ Ah+Al [M,K]; W ~ Wh+Wl [N,K], both row-major bf16.
// Tile 128x128, K-chunk 32. 8 warps: 4 in M (32 rows) x 2 in N (64 cols).
// smem per stage: 4 tiles x 128 rows x 80B (64B data + 16B pad) = 40960B; x2 stages.
#define TROW 80
#define TILE_B (128 * TROW)          // 10240
#define STAGE_B (4 * TILE_B)         // 40960

template<bool RELU>
__global__ void __launch_bounds__(256, 1) gemm_mma(
    const __nv_bfloat16* __restrict__ Ah, const __nv_bfloat16* __restrict__ Al,
    const __nv_bfloat16* __restrict__ Wh, const __nv_bfloat16* __restrict__ Wl,
    const float* __restrict__ bias, float* __restrict__ C,
    int M, int N, int K)
{
    extern __shared__ __align__(128) char smem[];
    uint32_t sb = smem_u32(smem);

    int tid  = threadIdx.x;
    int lane = tid & 31;
    int wid  = tid >> 5;
    int wm   = wid & 3;        // 0..3  (M)
    int wn   = wid >> 2;       // 0..1  (N)
    int bm = blockIdx.y * 128;
    int bn = blockIdx.x * 128;

    const int nch = K >> 5;    // K chunks of 32

    // ---- stage loader: 4 tiles (Ah,Al,Wh,Wl) of 128x32 bf16
    auto load_stage = [&](int c) {
        uint32_t st = sb + (c & 1) * STAGE_B;
        size_t kof = (size_t)c * 32;
        const __nv_bfloat16* bases[4];
        bases[0] = Ah + (size_t)bm * K + kof;
        bases[1] = Al + (size_t)bm * K + kof;
        bases[2] = Wh + (size_t)bn * K + kof;
        bases[3] = Wl + (size_t)bn * K + kof;
#pragma unroll
        for (int tI = 0; tI < 4; tI++) {
            uint32_t smtile = st + tI * TILE_B;
            const __nv_bfloat16* base = bases[tI];
#pragma unroll
            for (int u = 0; u < 2; u++) {
                int l   = tid + u * 256;        // 0..511
                int row = l >> 2;               // 0..127
                int ch  = l & 3;                // 16B chunk
                uint32_t dst = smtile + row * TROW + ch * 16;
                const char* src = (const char*)(base + (size_t)row * K) + ch * 16;
                CPASYNC16(dst, src);
            }
        }
        CPCOMMIT();
    };

    // per-lane ldmatrix offsets
    uint32_t aoff = ((((lane >> 3) & 1) * 8 + (lane & 7)) * TROW) + (lane >> 4) * 16;
    uint32_t boff = (((lane >> 4) * 8 + (lane & 7)) * TROW) + ((lane >> 3) & 1) * 16;

    float acc[2][8][4];
#pragma unroll
    for (int mt = 0; mt < 2; mt++)
#pragma unroll
        for (int n8 = 0; n8 < 8; n8++)
#pragma unroll
            for (int k = 0; k < 4; k++) acc[mt][n8][k] = 0.f;

    load_stage(0);
    for (int c = 0; c < nch; c++) {
        if (c + 1 < nch) { load_stage(c + 1); CPWAIT1(); }
        else             { CPWAIT0(); }
        __syncthreads();

        uint32_t st = sb + (c & 1) * STAGE_B;
        uint32_t aBaseH = st             + (wm * 32) * TROW + aoff;
        uint32_t aBaseL = st + TILE_B    + (wm * 32) * TROW + aoff;
        uint32_t bBaseH = st + 2*TILE_B  + (wn * 64) * TROW + boff;
        uint32_t bBaseL = st + 3*TILE_B  + (wn * 64) * TROW + boff;

#pragma unroll
        for (int ks = 0; ks < 2; ks++) {
            uint32_t ah[2][4], al[2][4], bh[4][4], bl[4][4];
#pragma unroll
            for (int mt = 0; mt < 2; mt++) {
                LDSM_X4(ah[mt], aBaseH + mt * (16 * TROW) + ks * 32);
                LDSM_X4(al[mt], aBaseL + mt * (16 * TROW) + ks * 32);
            }
#pragma unroll
            for (int g = 0; g < 4; g++) {
                LDSM_X4(bh[g], bBaseH + g * (16 * TROW) + ks * 32);
                LDSM_X4(bl[g], bBaseL + g * (16 * TROW) + ks * 32);
            }
#pragma unroll
            for (int mt = 0; mt < 2; mt++)
#pragma unroll
                for (int g = 0; g < 4; g++)
#pragma unroll
                    for (int hf = 0; hf < 2; hf++) {
                        int n8 = g * 2 + hf;
                        mma_bf16(acc[mt][n8], ah[mt], &bh[g][hf*2]);
                        mma_bf16(acc[mt][n8], ah[mt], &bl[g][hf*2]);
                        mma_bf16(acc[mt][n8], al[mt], &bh[g][hf*2]);
                    }
        }
        __syncthreads();
    }

    // ---- epilogue: direct stores with bias (+ReLU)
    int r_in = lane >> 2;
    int c_in = (lane & 3) * 2;
#pragma unroll
    for (int mt = 0; mt < 2; mt++) {
        int R0 = bm + wm * 32 + mt * 16 + r_in;
        int R1 = R0 + 8;
#pragma unroll
        for (int n8 = 0; n8 < 8; n8++) {
            int col = bn + wn * 64 + n8 * 8 + c_in;
            float b0 = bias[col], b1 = bias[col + 1];
            float2 o0, o1;
            o0.x = acc[mt][n8][0] + b0; o0.y = acc[mt][n8][1] + b1;
            o1.x = acc[mt][n8][2] + b0; o1.y = acc[mt][n8][3] + b1;
            if (RELU) {
                o0.x = fmaxf(o0.x, 0.f); o0.y = fmaxf(o0.y, 0.f);
                o1.x = fmaxf(o1.x, 0.f); o1.y = fmaxf(o1.y, 0.f);
            }
            *(float2*)&C[(size_t)R0 * N + col] = o0;
            *(float2*)&C[(size_t)R1 * N + col] = o1;
        }
    }
}

// ---------------- fused distance-decay attention (fp32) ----------------------
__global__ void __launch_bounds__(256) attn_kernel(
    const float* __restrict__ gq, const float* __restrict__ gk,
    const float* __restrict__ gv, const float* __restrict__ gammas,
    float* __restrict__ outp)
{
    extern __shared__ float sm[];
    float* q  = sm;
    float* sc = q + ROWS*DKK;
    float* kt = sc + ROWS*SS;

    int b  = blockIdx.z;
    int h  = blockIdx.y;
    int i0 = blockIdx.x * ROWS;
    int t  = threadIdx.x;

    const float* Qb = gq + (size_t)b*SS*DD + h*DKK;
    const float* Kb = gk + (size_t)b*SS*DD + h*DKK;
    const float* Vb = gv + (size_t)b*SS*DD + h*DKK;

    {
        int r = t >> 4;
        int c = (t & 15) * 4;
        float4 v4 = *(const float4*)&Qb[(size_t)(i0 + r)*DD + c];
        *(float4*)&q[r*DKK + c] = v4;
    }
    __syncthreads();

    const float scale = 0.125f;
    int si = t >> 4;
    int jl = t & 15;
    for (int j0 = 0; j0 < SS; j0 += 32) {
        __syncthreads();
        {
            int r  = t >> 3;
            int c0 = (t & 7) * 8;
            float4 v0 = *(const float4*)&Kb[(size_t)(j0 + r)*DD + c0];
            float4 v1 = *(const float4*)&Kb[(size_t)(j0 + r)*DD + c0 + 4];
            float* dst = &kt[r*65 + c0];
            dst[0]=v0.x; dst[1]=v0.y; dst[2]=v0.z; dst[3]=v0.w;
            dst[4]=v1.x; dst[5]=v1.y; dst[6]=v1.z; dst[7]=v1.w;
        }
        __syncthreads();
        float s0 = 0.f, s1 = 0.f;
#pragma unroll
        for (int kk = 0; kk < DKK; kk++) {
            float qa = q[si*DKK + kk];
            s0 = fmaf(qa, kt[jl*65 + kk],      s0);
            s1 = fmaf(qa, kt[(jl+16)*65 + kk], s1);
        }
        sc[si*SS + j0 + jl]      = s0 * scale;
        sc[si*SS + j0 + jl + 16] = s1 * scale;
    }
    __syncthreads();

    {
        int warp = t >> 5, lane = t & 31;
        float gamma = -log1pf(__expf(gammas[h]));
        for (int rr = 0; rr < 2; rr++) {
            int r  = warp*2 + rr;
            int ig = i0 + r;
            float* row = sc + r*SS;

            float m = -INFINITY;
            for (int j = lane; j < SS; j += 32) m = fmaxf(m, row[j]);
#pragma unroll
            for (int o = 16; o > 0; o >>= 1) m = fmaxf(m, __shfl_xor_sync(0xffffffffu, m, o));

            float sum1 = 0.f, summ = 0.f;
            for (int j = lane; j < SS; j += 32) {
                float p = __expf(row[j] - m);
                sum1 += p;
                if (j <= ig) summ += p;
            }
#pragma unroll
            for (int o = 16; o > 0; o >>= 1) {
                sum1 += __shfl_xor_sync(0xffffffffu, sum1, o);
                summ += __shfl_xor_sync(0xffffffffu, summ, o);
            }
            float inv1    = 1.f / sum1;
            float disttot = summ * inv1;

            float carry = 0.f, m2 = -INFINITY;
            for (int j0 = 0; j0 < SS; j0 += 32) {
                int j = j0 + lane;
                float sraw = row[j];
                float pj = (j <= ig) ? __expf(sraw - m) * inv1 : 0.f;
                float x = pj;
#pragma unroll
                for (int o = 1; o < 32; o <<= 1) {
                    float y = __shfl_up_sync(0xffffffffu, x, o);
                    if (lane >= o) x += y;
                }
                float distcum = carry + x;
                carry += __shfl_sync(0xffffffffu, x, 31);
                float pos  = fabsf((float)(ig - j));
                float dd   = (disttot - distcum) * pos;
                float dist = sqrtf(fmaxf(dd, 0.f));
                float eff  = __expf(dist * gamma);
                eff = fminf(fmaxf(eff, 1e-5f), 1e5f);
                float s2 = (j <= ig) ? sraw * eff : -INFINITY;
                row[j] = s2;
                m2 = fmaxf(m2, s2);
            }
#pragma unroll
            for (int o = 16; o > 0; o >>= 1) m2 = fmaxf(m2, __shfl_xor_sync(0xffffffffu, m2, o));

            float sum2 = 0.f;
            for (int j = lane; j < SS; j += 32) {
                float e = (j <= ig) ? __expf(row[j] - m2) : 0.f;
                row[j] = e;
                sum2 += e;
            }
#pragma unroll
            for (int o = 16; o > 0; o >>= 1) sum2 += __shfl_xor_sync(0xffffffffu, sum2, o);
            float inv2 = 1.f / sum2;
            for (int j = lane; j < SS; j += 32) row[j] *= inv2;
        }
    }
    __syncthreads();

    {
        int d  = t & 63;
        int rg = t >> 6;
        float acc[4] = {0.f, 0.f, 0.f, 0.f};
        int jmax = i0 + ROWS;
        for (int j0 = 0; j0 < jmax; j0 += 32) {
            __syncthreads();
            {
                int r  = t >> 3;
                int c0 = (t & 7) * 8;
                float4 v0 = *(const float4*)&Vb[(size_t)(j0 + r)*DD + c0];
                float4 v1 = *(const float4*)&Vb[(size_t)(j0 + r)*DD + c0 + 4];
                float* dst = &kt[r*65 + c0];
                dst[0]=v0.x; dst[1]=v0.y; dst[2]=v0.z; dst[3]=v0.w;
                dst[4]=v1.x; dst[5]=v1.y; dst[6]=v1.z; dst[7]=v1.w;
            }
            __syncthreads();
#pragma unroll
            for (int jj = 0; jj < 32; jj++) {
                float vv = kt[jj*65 + d];
                acc[0] = fmaf(sc[(rg     )*SS + j0 + jj], vv, acc[0]);
                acc[1] = fmaf(sc[(rg +  4)*SS + j0 + jj], vv, acc[1]);
                acc[2] = fmaf(sc[(rg +  8)*SS + j0 + jj], vv, acc[2]);
                acc[3] = fmaf(sc[(rg + 12)*SS + j0 + jj], vv, acc[3]);
            }
        }
#pragma unroll
        for (int rr = 0; rr < 4; rr++) {
            int r = rg + rr*4;
            outp[((size_t)b*SS + (i0 + r))*DD + h*DKK + d] = acc[rr];
        }
    }
}

// ---------------- residual add + LayerNorm ----------------------------------
__global__ void __launch_bounds__(256) add_ln_kernel(
    const float* __restrict__ A, const float* __restrict__ Bres,
    const float* __restrict__ w, const float* __restrict__ bias,
    float* __restrict__ outp)
{
    __shared__ float red1[8], red2[8];
    int row = blockIdx.x;
    int t   = threadIdx.x;
    const float* pa = A    + (size_t)row*DD;
    const float* pb = Bres + (size_t)row*DD;

    float4 a4 = *(const float4*)&pa[t*4];
    float4 b4 = *(const float4*)&pb[t*4];
    float v0 = a4.x + b4.x, v1 = a4.y + b4.y, v2 = a4.z + b4.z, v3 = a4.w + b4.w;

    int lane = t & 31, wp = t >> 5;
    float s = v0 + v1 + v2 + v3;
#pragma unroll
    for (int o = 16; o > 0; o >>= 1) s += __shfl_xor_sync(0xffffffffu, s, o);
    if (lane == 0) red1[wp] = s;
    __syncthreads();
    float tot = 0.f;
#pragma unroll
    for (int i = 0; i < 8; i++) tot += red1[i];
    float mu = tot * (1.f / DD);

    float d0 = v0-mu, d1 = v1-mu, d2 = v2-mu, d3 = v3-mu;
    float q2 = d0*d0 + d1*d1 + d2*d2 + d3*d3;
#pragma unroll
    for (int o = 16; o > 0; o >>= 1) q2 += __shfl_xor_sync(0xffffffffu, q2, o);
    if (lane == 0) red2[wp] = q2;
    __syncthreads();
    float tv = 0.f;
#pragma unroll
    for (int i = 0; i < 8; i++) tv += red2[i];
    float inv = rsqrtf(tv * (1.f / DD) + 1e-5f);

    float4 w4  = *(const float4*)&w[t*4];
    float4 bi4 = *(const float4*)&bias[t*4];
    float4 o4;
    o4.x = d0*inv*w4.x + bi4.x;
    o4.y = d1*inv*w4.y + bi4.y;
    o4.z = d2*inv*w4.z + bi4.z;
    o4.w = d3*inv*w4.w + bi4.w;
    *(float4*)&outp[(size_t)row*DD + t*4] = o4;
}

// ---------------- launcher ---------------------------------------------------
extern "C" void kernel_launch(void* const* d_in, const int* in_sizes, int n_in,
                              void* d_out, int out_size)
{
    int off = (in_sizes[0] == 1) ? 1 : 0;
    const float* query  = (const float*)d_in[off + 0];
    const float* key    = (const float*)d_in[off + 1];
    const float* values = (const float*)d_in[off + 2];
    const float* Wq = (const float*)d_in[off + 3];
    const float* bq = (const float*)d_in[off + 4];
    const float* Wk = (const float*)d_in[off + 5];
    const float* bk = (const float*)d_in[off + 6];
    const float* Wv = (const float*)d_in[off + 7];
    const float* bv = (const float*)d_in[off + 8];
    const float* Wo = (const float*)d_in[off + 9];
    const float* bo = (const float*)d_in[off + 10];
    const float* gammas = (const float*)d_in[off + 11];
    const float* ln1w = (const float*)d_in[off + 12];
    const float* ln1b = (const float*)d_in[off + 13];
    const float* W1 = (const float*)d_in[off + 14];
    const float* b1 = (const float*)d_in[off + 15];
    const float* W2 = (const float*)d_in[off + 16];
    const float* b2 = (const float*)d_in[off + 17];
    const float* ln2w = (const float*)d_in[off + 18];
    const float* ln2b = (const float*)d_in[off + 19];

    float *pq, *pk, *pv, *pconcat, *pattnout, *px, *ph, *pf;
    cudaGetSymbolAddress((void**)&pq, g_q);
    cudaGetSymbolAddress((void**)&pk, g_k);
    cudaGetSymbolAddress((void**)&pv, g_v);
    cudaGetSymbolAddress((void**)&pconcat, g_concat);
    cudaGetSymbolAddress((void**)&pattnout, g_attnout);
    cudaGetSymbolAddress((void**)&px, g_x);
    cudaGetSymbolAddress((void**)&ph, g_h);
    cudaGetSymbolAddress((void**)&pf, g_f);
    __nv_bfloat16 *ahi, *alo, *whi, *wlo;
    cudaGetSymbolAddress((void**)&ahi, g_ahi);
    cudaGetSymbolAddress((void**)&alo, g_alo);
    cudaGetSymbolAddress((void**)&whi, g_whi);
    cudaGetSymbolAddress((void**)&wlo, g_wlo);

    const int M = BB * SS;   // 4096
    const int GEMM_SMEM = 2 * STAGE_B;   // 81920
    cudaFuncSetAttribute(gemm_mma<false>, cudaFuncAttributeMaxDynamicSharedMemorySize, GEMM_SMEM);
    cudaFuncSetAttribute(gemm_mma<true>,  cudaFuncAttributeMaxDynamicSharedMemorySize, GEMM_SMEM);

    auto split = [&](const float* src, __nv_bfloat16* hi, __nv_bfloat16* lo, int n) {
        split_kernel<<<(n/4 + 255) / 256, 256>>>(src, hi, lo, n / 4);
    };

    dim3 gD(DD/128, M/128);          // N=1024 GEMMs
    dim3 gF(DFFF/128, M/128);        // N=4096 GEMM

    // Q projection
    split(query, ahi, alo, M*DD);
    split(Wq, whi, wlo, DD*DD);
    gemm_mma<false><<<gD, 256, GEMM_SMEM>>>(ahi, alo, whi, wlo, bq, pq, M, DD, DD);
    // K projection
    split(key, ahi, alo, M*DD);
    split(Wk, whi, wlo, DD*DD);
    gemm_mma<false><<<gD, 256, GEMM_SMEM>>>(ahi, alo, whi, wlo, bk, pk, M, DD, DD);
    // V projection
    split(values, ahi, alo, M*DD);
    split(Wv, whi, wlo, DD*DD);
    gemm_mma<false><<<gD, 256, GEMM_SMEM>>>(ahi, alo, whi, wlo, bv, pv, M, DD, DD);

    // attention (fp32)
    size_t smem = (size_t)(ROWS*DKK + ROWS*SS + 32*65) * sizeof(float);
    cudaFuncSetAttribute(attn_kernel, cudaFuncAttributeMaxDynamicSharedMemorySize, (int)smem);
    attn_kernel<<<dim3(SS/ROWS, HH, BB), 256, smem>>>(pq, pk, pv, gammas, pconcat);

    // output projection
    split(pconcat, ahi, alo, M*DD);
    split(Wo, whi, wlo, DD*DD);
    gemm_mma<false><<<gD, 256, GEMM_SMEM>>>(ahi, alo, whi, wlo, bo, pattnout, M, DD, DD);

    // LN1
    add_ln_kernel<<<M, 256>>>(query, pattnout, ln1w, ln1b, px);

    // FFN1 (+ReLU)
    split(px, ahi, alo, M*DD);
    split(W1, whi, wlo, DFFF*DD);
    gemm_mma<true><<<gF, 256, GEMM_SMEM>>>(ahi, alo, whi, wlo, b1, ph, M, DFFF, DD);

    // FFN2
    split(ph, ahi, alo, M*DFFF);
    split(W2, whi, wlo, DD*DFFF);
    gemm_mma<false><<<gD, 256, GEMM_SMEM>>>(ahi, alo, whi, wlo, b2, pf, M, DD, DFFF);

    // LN2 -> final output
    add_ln_kernel<<<M, 256>>>(px, pf, ln2w, ln2b, (float*)d_out);
}

// round 4
// speedup vs baseline: 1.8222x; 1.1572x over previous
#include <cuda_runtime.h>
#include <cuda_bf16.h>
#include <math.h>
#include <stdint.h>

// Problem constants
#define BB 4
#define SS 1024
#define DD 1024
#define HH 16
#define DKK 64
#define DFFF 4096
#define ROWS 16   // attention rows per block

// ---------------- scratch (device globals) -----------------------------------
__device__ float g_q[BB*SS*DD];
__device__ float g_k[BB*SS*DD];
__device__ float g_v[BB*SS*DD];
__device__ float g_attnout[BB*SS*DD];
__device__ float g_x[BB*SS*DD];
__device__ float g_f[BB*SS*DD];
// bf16 split buffers
__device__ __nv_bfloat16 g_ahi[BB*SS*DFFF];
__device__ __nv_bfloat16 g_alo[BB*SS*DFFF];
__device__ __nv_bfloat16 g_whi[DFFF*DD];
__device__ __nv_bfloat16 g_wlo[DFFF*DD];
__device__ __nv_bfloat16 g_hhi[BB*SS*DFFF];
__device__ __nv_bfloat16 g_hlo[BB*SS*DFFF];

// ======================= PTX helpers ========================================
__device__ __forceinline__ uint32_t smem_u32(const void* p) {
    uint32_t a;
    asm("{ .reg .u64 t; cvta.to.shared.u64 t, %1; cvt.u32.u64 %0, t; }" : "=r"(a) : "l"(p));
    return a;
}

#define CPASYNC16(dst, src) asm volatile("cp.async.cg.shared.global [%0], [%1], 16;" :: "r"(dst), "l"(src) : "memory")
#define CPCOMMIT() asm volatile("cp.async.commit_group;" ::: "memory")
#define CPWAIT1()  asm volatile("cp.async.wait_group 1;" ::: "memory")
#define CPWAIT0()  asm volatile("cp.async.wait_group 0;" ::: "memory")

#define LDSM_X4(R, A) \
    asm volatile("ldmatrix.sync.aligned.m8n8.x4.shared.b16 {%0,%1,%2,%3}, [%4];" \
        : "=r"((R)[0]), "=r"((R)[1]), "=r"((R)[2]), "=r"((R)[3]) : "r"(A))

__device__ __forceinline__ void mma_bf16(float* c, const uint32_t* a, const uint32_t* b) {
    asm volatile(
        "mma.sync.aligned.m16n8k16.row.col.f32.bf16.bf16.f32 "
        "{%0,%1,%2,%3}, {%4,%5,%6,%7}, {%8,%9}, {%0,%1,%2,%3};"
        : "+f"(c[0]), "+f"(c[1]), "+f"(c[2]), "+f"(c[3])
        : "r"(a[0]), "r"(a[1]), "r"(a[2]), "r"(a[3]), "r"(b[0]), "r"(b[1]));
}

// ================ split fp32 -> bf16 hi/lo ==================================
__global__ void __launch_bounds__(256) split_kernel(
    const float* __restrict__ in, __nv_bfloat16* __restrict__ hi,
    __nv_bfloat16* __restrict__ lo, int n4)
{
    int i = blockIdx.x * 256 + threadIdx.x;
    if (i >= n4) return;
    float4 v = ((const float4*)in)[i];
    __nv_bfloat16 h0 = __float2bfloat16(v.x);
    __nv_bfloat16 h1 = __float2bfloat16(v.y);
    __nv_bfloat16 h2 = __float2bfloat16(v.z);
    __nv_bfloat16 h3 = __float2bfloat16(v.w);
    __nv_bfloat16 l0 = __float2bfloat16(v.x - __bfloat162float(h0));
    __nv_bfloat16 l1 = __float2bfloat16(v.y - __bfloat162float(h1));
    __nv_bfloat16 l2 = __float2bfloat16(v.z - __bfloat162float(h2));
    __nv_bfloat16 l3 = __float2bfloat16(v.w - __bfloat162float(h3));
    __nv_bfloat162 hp0; hp0.x = h0; hp0.y = h1;
    __nv_bfloat162 hp1; hp1.x = h2; hp1.y = h3;
    __nv_bfloat162 lp0; lp0.x = l0; lp0.y = l1;
    __nv_bfloat162 lp1; lp1.x = l2; lp1.y = l3;
    ((__nv_bfloat162*)hi)[i*2+0] = hp0;
    ((__nv_bfloat162*)hi)[i*2+1] = hp1;
    ((__nv_bfloat162*)lo)[i*2+0] = lp0;
    ((__nv_bfloat162*)lo)[i*2+1] = lp1;
}

// ============ mma.sync bf16x3 GEMM: C[M,N] = A @ W^T + bias =================
// Tile 128x128, K-chunk 32. 8 warps: 4 in M x 2 in N (warp tile 32x64).
#define TROW 80
#define TILE_B (128 * TROW)
#define STAGE_B (4 * TILE_B)         // 40960

template<bool RELU, bool SPLITOUT>
__global__ void __launch_bounds__(256, 2) gemm_mma(
    const __nv_bfloat16* __restrict__ Ah, const __nv_bfloat16* __restrict__ Al,
    const __nv_bfloat16* __restrict__ Wh, const __nv_bfloat16* __restrict__ Wl,
    const float* __restrict__ bias, float* __restrict__ C,
    __nv_bfloat16* __restrict__ Chi, __nv_bfloat16* __restrict__ Clo,
    int M, int N, int K)
{
    extern __shared__ __align__(128) char smem[];
    uint32_t sb = smem_u32(smem);

    int tid  = threadIdx.x;
    int lane = tid & 31;
    int wid  = tid >> 5;
    int wm   = wid & 3;
    int wn   = wid >> 2;
    int bm = blockIdx.y * 128;
    int bn = blockIdx.x * 128;

    const int nch = K >> 5;

    auto load_stage = [&](int c) {
        uint32_t st = sb + (c & 1) * STAGE_B;
        size_t kof = (size_t)c * 32;
        const __nv_bfloat16* bases[4];
        bases[0] = Ah + (size_t)bm * K + kof;
        bases[1] = Al + (size_t)bm * K + kof;
        bases[2] = Wh + (size_t)bn * K + kof;
        bases[3] = Wl + (size_t)bn * K + kof;
#pragma unroll
        for (int tI = 0; tI < 4; tI++) {
            uint32_t smtile = st + tI * TILE_B;
            const __nv_bfloat16* base = bases[tI];
#pragma unroll
            for (int u = 0; u < 2; u++) {
                int l   = tid + u * 256;
                int row = l >> 2;
                int ch  = l & 3;
                uint32_t dst = smtile + row * TROW + ch * 16;
                const char* src = (const char*)(base + (size_t)row * K) + ch * 16;
                CPASYNC16(dst, src);
            }
        }
        CPCOMMIT();
    };

    uint32_t aoff = ((((lane >> 3) & 1) * 8 + (lane & 7)) * TROW) + (lane >> 4) * 16;
    uint32_t boff = (((lane >> 4) * 8 + (lane & 7)) * TROW) + ((lane >> 3) & 1) * 16;

    float acc[2][8][4];
#pragma unroll
    for (int mt = 0; mt < 2; mt++)
#pragma unroll
        for (int n8 = 0; n8 < 8; n8++)
#pragma unroll
            for (int k = 0; k < 4; k++) acc[mt][n8][k] = 0.f;

    load_stage(0);
    for (int c = 0; c < nch; c++) {
        if (c + 1 < nch) { load_stage(c + 1); CPWAIT1(); }
        else             { CPWAIT0(); }
        __syncthreads();

        uint32_t st = sb + (c & 1) * STAGE_B;
        uint32_t aBaseH = st             + (wm * 32) * TROW + aoff;
        uint32_t aBaseL = st + TILE_B    + (wm * 32) * TROW + aoff;
        uint32_t bBaseH = st + 2*TILE_B  + (wn * 64) * TROW + boff;
        uint32_t bBaseL = st + 3*TILE_B  + (wn * 64) * TROW + boff;

#pragma unroll
        for (int ks = 0; ks < 2; ks++) {
            uint32_t ah[2][4], al[2][4];
#pragma unroll
            for (int mt = 0; mt < 2; mt++) {
                LDSM_X4(ah[mt], aBaseH + mt * (16 * TROW) + ks * 32);
                LDSM_X4(al[mt], aBaseL + mt * (16 * TROW) + ks * 32);
            }
#pragma unroll
            for (int g = 0; g < 4; g++) {
                uint32_t bh[4], bl[4];
                LDSM_X4(bh, bBaseH + g * (16 * TROW) + ks * 32);
                LDSM_X4(bl, bBaseL + g * (16 * TROW) + ks * 32);
#pragma unroll
                for (int mt = 0; mt < 2; mt++)
#pragma unroll
                    for (int hf = 0; hf < 2; hf++) {
                        int n8 = g * 2 + hf;
                        mma_bf16(acc[mt][n8], ah[mt], &bh[hf*2]);
                        mma_bf16(acc[mt][n8], ah[mt], &bl[hf*2]);
                        mma_bf16(acc[mt][n8], al[mt], &bh[hf*2]);
                    }
            }
        }
        __syncthreads();
    }

    // ---- epilogue
    int r_in = lane >> 2;
    int c_in = (lane & 3) * 2;
#pragma unroll
    for (int mt = 0; mt < 2; mt++) {
        int R0 = bm + wm * 32 + mt * 16 + r_in;
        int R1 = R0 + 8;
#pragma unroll
        for (int n8 = 0; n8 < 8; n8++) {
            int col = bn + wn * 64 + n8 * 8 + c_in;
            float b0 = bias[col], b1 = bias[col + 1];
            float o00 = acc[mt][n8][0] + b0, o01 = acc[mt][n8][1] + b1;
            float o10 = acc[mt][n8][2] + b0, o11 = acc[mt][n8][3] + b1;
            if (RELU) {
                o00 = fmaxf(o00, 0.f); o01 = fmaxf(o01, 0.f);
                o10 = fmaxf(o10, 0.f); o11 = fmaxf(o11, 0.f);
            }
            if (SPLITOUT) {
                __nv_bfloat162 h0, h1, l0, l1;
                h0.x = __float2bfloat16(o00); h0.y = __float2bfloat16(o01);
                h1.x = __float2bfloat16(o10); h1.y = __float2bfloat16(o11);
                l0.x = __float2bfloat16(o00 - __bfloat162float(h0.x));
                l0.y = __float2bfloat16(o01 - __bfloat162float(h0.y));
                l1.x = __float2bfloat16(o10 - __bfloat162float(h1.x));
                l1.y = __float2bfloat16(o11 - __bfloat162float(h1.y));
                *(__nv_bfloat162*)&Chi[(size_t)R0 * N + col] = h0;
                *(__nv_bfloat162*)&Chi[(size_t)R1 * N + col] = h1;
                *(__nv_bfloat162*)&Clo[(size_t)R0 * N + col] = l0;
                *(__nv_bfloat162*)&Clo[(size_t)R1 * N + col] = l1;
            } else {
                float2 o0, o1;
                o0.x = o00; o0.y = o01; o1.x = o10; o1.y = o11;
                *(float2*)&C[(size_t)R0 * N + col] = o0;
                *(float2*)&C[(size_t)R1 * N + col] = o1;
            }
        }
    }
}

// ---------------- fused distance-decay attention (fp32 math) -----------------
// Emits concat output as bf16 hi/lo directly (feeds Wo GEMM).
__global__ void __launch_bounds__(256) attn_kernel(
    const float* __restrict__ gq, const float* __restrict__ gk,
    const float* __restrict__ gv, const float* __restrict__ gammas,
    __nv_bfloat16* __restrict__ ohi, __nv_bfloat16* __restrict__ olo)
{
    extern __shared__ float sm[];
    float* q  = sm;
    float* sc = q + ROWS*DKK;
    float* kt = sc + ROWS*SS;

    int b  = blockIdx.z;
    int h  = blockIdx.y;
    int i0 = blockIdx.x * ROWS;
    int t  = threadIdx.x;

    const float* Qb = gq + (size_t)b*SS*DD + h*DKK;
    const float* Kb = gk + (size_t)b*SS*DD + h*DKK;
    const float* Vb = gv + (size_t)b*SS*DD + h*DKK;

    {
        int r = t >> 4;
        int c = (t & 15) * 4;
        float4 v4 = *(const float4*)&Qb[(size_t)(i0 + r)*DD + c];
        *(float4*)&q[r*DKK + c] = v4;
    }
    __syncthreads();

    // ---- QK^T scores (full row, fp32)
    const float scale = 0.125f;
    int si = t >> 4;
    int jl = t & 15;
    for (int j0 = 0; j0 < SS; j0 += 32) {
        __syncthreads();
        {
            int r  = t >> 3;
            int c0 = (t & 7) * 8;
            float4 v0 = *(const float4*)&Kb[(size_t)(j0 + r)*DD + c0];
            float4 v1 = *(const float4*)&Kb[(size_t)(j0 + r)*DD + c0 + 4];
            float* dst = &kt[r*65 + c0];
            dst[0]=v0.x; dst[1]=v0.y; dst[2]=v0.z; dst[3]=v0.w;
            dst[4]=v1.x; dst[5]=v1.y; dst[6]=v1.z; dst[7]=v1.w;
        }
        __syncthreads();
        float s0 = 0.f, s1 = 0.f;
#pragma unroll
        for (int kk = 0; kk < DKK; kk++) {
            float qa = q[si*DKK + kk];
            s0 = fmaf(qa, kt[jl*65 + kk],      s0);
            s1 = fmaf(qa, kt[(jl+16)*65 + kk], s1);
        }
        sc[si*SS + j0 + jl]      = s0 * scale;
        sc[si*SS + j0 + jl + 16] = s1 * scale;
    }
    __syncthreads();

    // ---- register-resident row math (one warp -> 2 rows) --------------------
    {
        int warp = t >> 5, lane = t & 31;
        float gamma = -log1pf(__expf(gammas[h]));
        for (int rr = 0; rr < 2; rr++) {
            int r  = warp*2 + rr;
            int ig = i0 + r;
            float* row = sc + r*SS;

            float s[32], p[32];
            float m = -INFINITY;
#pragma unroll
            for (int c = 0; c < 32; c++) {
                s[c] = row[c*32 + lane];
                m = fmaxf(m, s[c]);
            }
#pragma unroll
            for (int o = 16; o > 0; o >>= 1) m = fmaxf(m, __shfl_xor_sync(0xffffffffu, m, o));

            float sum1 = 0.f, summ = 0.f;
#pragma unroll
            for (int c = 0; c < 32; c++) {
                p[c] = __expf(s[c] - m);
                sum1 += p[c];
                if (c*32 + lane <= ig) summ += p[c];
            }
#pragma unroll
            for (int o = 16; o > 0; o >>= 1) {
                sum1 += __shfl_xor_sync(0xffffffffu, sum1, o);
                summ += __shfl_xor_sync(0xffffffffu, summ, o);
            }
            float inv1 = 1.f / sum1;

            // masked cumsum + decay (skip fully-masked chunks: warp-uniform)
            float carry = 0.f, m2 = -INFINITY;
#pragma unroll
            for (int c = 0; c < 32; c++) {
                if (c*32 <= ig) {
                    int j = c*32 + lane;
                    float pm = (j <= ig) ? p[c] : 0.f;
                    float x = pm;
#pragma unroll
                    for (int o = 1; o < 32; o <<= 1) {
                        float y = __shfl_up_sync(0xffffffffu, x, o);
                        if (lane >= o) x += y;
                    }
                    float distraw = carry + x;
                    carry += __shfl_sync(0xffffffffu, x, 31);
                    float pos  = fabsf((float)(ig - j));
                    float dd   = (summ - distraw) * inv1 * pos;
                    float dist = sqrtf(fmaxf(dd, 0.f));
                    float eff  = __expf(dist * gamma);
                    eff = fminf(fmaxf(eff, 1e-5f), 1e5f);
                    float s2 = (j <= ig) ? s[c] * eff : -INFINITY;
                    s[c] = s2;
                    m2 = fmaxf(m2, s2);
                } else {
                    s[c] = -INFINITY;
                }
            }
#pragma unroll
            for (int o = 16; o > 0; o >>= 1) m2 = fmaxf(m2, __shfl_xor_sync(0xffffffffu, m2, o));

            // softmax #2
            float sum2 = 0.f;
#pragma unroll
            for (int c = 0; c < 32; c++) {
                float e = 0.f;
                if (c*32 <= ig) {
                    int j = c*32 + lane;
                    e = (j <= ig) ? __expf(s[c] - m2) : 0.f;
                }
                p[c] = e;
                sum2 += e;
            }
#pragma unroll
            for (int o = 16; o > 0; o >>= 1) sum2 += __shfl_xor_sync(0xffffffffu, sum2, o);
            float inv2 = 1.f / sum2;
#pragma unroll
            for (int c = 0; c < 32; c++) row[c*32 + lane] = p[c] * inv2;
        }
    }
    __syncthreads();

    // ---- PV (skip fully-masked j tiles), emit bf16 hi/lo --------------------
    {
        int d  = t & 63;
        int rg = t >> 6;
        float acc[4] = {0.f, 0.f, 0.f, 0.f};
        int jmax = i0 + ROWS;
        for (int j0 = 0; j0 < jmax; j0 += 32) {
            __syncthreads();
            {
                int r  = t >> 3;
                int c0 = (t & 7) * 8;
                float4 v0 = *(const float4*)&Vb[(size_t)(j0 + r)*DD + c0];
                float4 v1 = *(const float4*)&Vb[(size_t)(j0 + r)*DD + c0 + 4];
                float* dst = &kt[r*65 + c0];
                dst[0]=v0.x; dst[1]=v0.y; dst[2]=v0.z; dst[3]=v0.w;
                dst[4]=v1.x; dst[5]=v1.y; dst[6]=v1.z; dst[7]=v1.w;
            }
            __syncthreads();
#pragma unroll
            for (int jj = 0; jj < 32; jj++) {
                float vv = kt[jj*65 + d];
                acc[0] = fmaf(sc[(rg     )*SS + j0 + jj], vv, acc[0]);
                acc[1] = fmaf(sc[(rg +  4)*SS + j0 + jj], vv, acc[1]);
                acc[2] = fmaf(sc[(rg +  8)*SS + j0 + jj], vv, acc[2]);
                acc[3] = fmaf(sc[(rg + 12)*SS + j0 + jj], vv, acc[3]);
            }
        }
#pragma unroll
        for (int rr = 0; rr < 4; rr++) {
            int r = rg + rr*4;
            size_t idx = ((size_t)b*SS + (i0 + r))*DD + h*DKK + d;
            float o = acc[rr];
            __nv_bfloat16 hv = __float2bfloat16(o);
            __nv_bfloat16 lv = __float2bfloat16(o - __bfloat162float(hv));
            ohi[idx] = hv;
            olo[idx] = lv;
        }
    }
}

// ---------------- residual add + LayerNorm (opt bf16 hi/lo side-out) ---------
template<bool SPLITOUT>
__global__ void __launch_bounds__(256) add_ln_kernel(
    const float* __restrict__ A, const float* __restrict__ Bres,
    const float* __restrict__ w, const float* __restrict__ bias,
    float* __restrict__ outp,
    __nv_bfloat16* __restrict__ ohi, __nv_bfloat16* __restrict__ olo)
{
    __shared__ float red1[8], red2[8];
    int row = blockIdx.x;
    int t   = threadIdx.x;
    const float* pa = A    + (size_t)row*DD;
    const float* pb = Bres + (size_t)row*DD;

    float4 a4 = *(const float4*)&pa[t*4];
    float4 b4 = *(const float4*)&pb[t*4];
    float v0 = a4.x + b4.x, v1 = a4.y + b4.y, v2 = a4.z + b4.z, v3 = a4.w + b4.w;

    int lane = t & 31, wp = t >> 5;
    float s = v0 + v1 + v2 + v3;
#pragma unroll
    for (int o = 16; o > 0; o >>= 1) s += __shfl_xor_sync(0xffffffffu, s, o);
    if (lane == 0) red1[wp] = s;
    __syncthreads();
    float tot = 0.f;
#pragma unroll
    for (int i = 0; i < 8; i++) tot += red1[i];
    float mu = tot * (1.f / DD);

    float d0 = v0-mu, d1 = v1-mu, d2 = v2-mu, d3 = v3-mu;
    float q2 = d0*d0 + d1*d1 + d2*d2 + d3*d3;
#pragma unroll
    for (int o = 16; o > 0; o >>= 1) q2 += __shfl_xor_sync(0xffffffffu, q2, o);
    if (lane == 0) red2[wp] = q2;
    __syncthreads();
    float tv = 0.f;
#pragma unroll
    for (int i = 0; i < 8; i++) tv += red2[i];
    float inv = rsqrtf(tv * (1.f / DD) + 1e-5f);

    float4 w4  = *(const float4*)&w[t*4];
    float4 bi4 = *(const float4*)&bias[t*4];
    float4 o4;
    o4.x = d0*inv*w4.x + bi4.x;
    o4.y = d1*inv*w4.y + bi4.y;
    o4.z = d2*inv*w4.z + bi4.z;
    o4.w = d3*inv*w4.w + bi4.w;
    *(float4*)&outp[(size_t)row*DD + t*4] = o4;

    if (SPLITOUT) {
        __nv_bfloat162 h0, h1, l0, l1;
        h0.x = __float2bfloat16(o4.x); h0.y = __float2bfloat16(o4.y);
        h1.x = __float2bfloat16(o4.z); h1.y = __float2bfloat16(o4.w);
        l0.x = __float2bfloat16(o4.x - __bfloat162float(h0.x));
        l0.y = __float2bfloat16(o4.y - __bfloat162float(h0.y));
        l1.x = __float2bfloat16(o4.z - __bfloat162float(h1.x));
        l1.y = __float2bfloat16(o4.w - __bfloat162float(h1.y));
        size_t base2 = (size_t)row * (DD/2) + t*2;
        ((__nv_bfloat162*)ohi)[base2]     = h0;
        ((__nv_bfloat162*)ohi)[base2 + 1] = h1;
        ((__nv_bfloat162*)olo)[base2]     = l0;
        ((__nv_bfloat162*)olo)[base2 + 1] = l1;
    }
}

// ---------------- launcher ---------------------------------------------------
extern "C" void kernel_launch(void* const* d_in, const int* in_sizes, int n_in,
                              void* d_out, int out_size)
{
    int off = (in_sizes[0] == 1) ? 1 : 0;
    const float* query  = (const float*)d_in[off + 0];
    const float* key    = (const float*)d_in[off + 1];
    const float* values = (const float*)d_in[off + 2];
    const float* Wq = (const float*)d_in[off + 3];
    const float* bq = (const float*)d_in[off + 4];
    const float* Wk = (const float*)d_in[off + 5];
    const float* bk = (const float*)d_in[off + 6];
    const float* Wv = (const float*)d_in[off + 7];
    const float* bv = (const float*)d_in[off + 8];
    const float* Wo = (const float*)d_in[off + 9];
    const float* bo = (const float*)d_in[off + 10];
    const float* gammas = (const float*)d_in[off + 11];
    const float* ln1w = (const float*)d_in[off + 12];
    const float* ln1b = (const float*)d_in[off + 13];
    const float* W1 = (const float*)d_in[off + 14];
    const float* b1 = (const float*)d_in[off + 15];
    const float* W2 = (const float*)d_in[off + 16];
    const float* b2 = (const float*)d_in[off + 17];
    const float* ln2w = (const float*)d_in[off + 18];
    const float* ln2b = (const float*)d_in[off + 19];

    float *pq, *pk, *pv, *pattnout, *px, *pf;
    cudaGetSymbolAddress((void**)&pq, g_q);
    cudaGetSymbolAddress((void**)&pk, g_k);
    cudaGetSymbolAddress((void**)&pv, g_v);
    cudaGetSymbolAddress((void**)&pattnout, g_attnout);
    cudaGetSymbolAddress((void**)&px, g_x);
    cudaGetSymbolAddress((void**)&pf, g_f);
    __nv_bfloat16 *ahi, *alo, *whi, *wlo, *hhi, *hlo;
    cudaGetSymbolAddress((void**)&ahi, g_ahi);
    cudaGetSymbolAddress((void**)&alo, g_alo);
    cudaGetSymbolAddress((void**)&whi, g_whi);
    cudaGetSymbolAddress((void**)&wlo, g_wlo);
    cudaGetSymbolAddress((void**)&hhi, g_hhi);
    cudaGetSymbolAddress((void**)&hlo, g_hlo);

    const int M = BB * SS;   // 4096
    const int GEMM_SMEM = 2 * STAGE_B;   // 81920
    cudaFuncSetAttribute(gemm_mma<false,false>, cudaFuncAttributeMaxDynamicSharedMemorySize, GEMM_SMEM);
    cudaFuncSetAttribute(gemm_mma<true,true>,   cudaFuncAttributeMaxDynamicSharedMemorySize, GEMM_SMEM);

    auto split = [&](const float* src, __nv_bfloat16* hi, __nv_bfloat16* lo, int n) {
        split_kernel<<<(n/4 + 255) / 256, 256>>>(src, hi, lo, n / 4);
    };

    dim3 gD(DD/128, M/128);
    dim3 gF(DFFF/128, M/128);

    // QKV projections (fp32 out for fp32 attention)
    split(query, ahi, alo, M*DD);
    split(Wq, whi, wlo, DD*DD);
    gemm_mma<false,false><<<gD, 256, GEMM_SMEM>>>(ahi, alo, whi, wlo, bq, pq, nullptr, nullptr, M, DD, DD);
    split(key, ahi, alo, M*DD);
    split(Wk, whi, wlo, DD*DD);
    gemm_mma<false,false><<<gD, 256, GEMM_SMEM>>>(ahi, alo, whi, wlo, bk, pk, nullptr, nullptr, M, DD, DD);
    split(values, ahi, alo, M*DD);
    split(Wv, whi, wlo, DD*DD);
    gemm_mma<false,false><<<gD, 256, GEMM_SMEM>>>(ahi, alo, whi, wlo, bv, pv, nullptr, nullptr, M, DD, DD);

    // attention -> concat emitted directly as bf16 hi/lo into (ahi, alo)
    size_t smem = (size_t)(ROWS*DKK + ROWS*SS + 32*65) * sizeof(float);
    cudaFuncSetAttribute(attn_kernel, cudaFuncAttributeMaxDynamicSharedMemorySize, (int)smem);
    attn_kernel<<<dim3(SS/ROWS, HH, BB), 256, smem>>>(pq, pk, pv, gammas, ahi, alo);

    // output projection
    split(Wo, whi, wlo, DD*DD);
    gemm_mma<false,false><<<gD, 256, GEMM_SMEM>>>(ahi, alo, whi, wlo, bo, pattnout, nullptr, nullptr, M, DD, DD);

    // LN1 -> px (fp32) + (ahi, alo) for FFN1
    add_ln_kernel<true><<<M, 256>>>(query, pattnout, ln1w, ln1b, px, ahi, alo);

    // FFN1 (+ReLU) -> bf16 hi/lo directly
    split(W1, whi, wlo, DFFF*DD);
    gemm_mma<true,true><<<gF, 256, GEMM_SMEM>>>(ahi, alo, whi, wlo, b1, nullptr, hhi, hlo, M, DFFF, DD);

    // FFN2
    split(W2, whi, wlo, DD*DFFF);
    gemm_mma<false,false><<<gD, 256, GEMM_SMEM>>>(hhi, hlo, whi, wlo, b2, pf, nullptr, nullptr, M, DD, DFFF);

    // LN2 -> final output
    add_ln_kernel<false><<<M, 256>>>(px, pf, ln2w, ln2b, (float*)d_out, nullptr, nullptr);
}

// round 5
// speedup vs baseline: 2.2159x; 1.2161x over previous
#include <cuda_runtime.h>
#include <cuda_bf16.h>
#include <math.h>
#include <stdint.h>

// Problem constants
#define BB 4
#define SS 1024
#define DD 1024
#define HH 16
#define DKK 64
#define DFFF 4096
#define ROWS 16
#define SCP 1032   // score row pitch (floats)

// ---------------- scratch (device globals) -----------------------------------
__device__ float g_attnout[BB*SS*DD];
__device__ float g_x[BB*SS*DD];
__device__ float g_f[BB*SS*DD];
__device__ __nv_bfloat16 g_ahi[BB*SS*DFFF];
__device__ __nv_bfloat16 g_alo[BB*SS*DFFF];
__device__ __nv_bfloat16 g_whi[DFFF*DD];
__device__ __nv_bfloat16 g_wlo[DFFF*DD];
__device__ __nv_bfloat16 g_hhi[BB*SS*DFFF];
__device__ __nv_bfloat16 g_hlo[BB*SS*DFFF];
__device__ __nv_bfloat16 g_qhi[BB*SS*DD];
__device__ __nv_bfloat16 g_qlo[BB*SS*DD];
__device__ __nv_bfloat16 g_khi[BB*SS*DD];
__device__ __nv_bfloat16 g_klo[BB*SS*DD];
__device__ __nv_bfloat16 g_vhi[BB*SS*DD];
__device__ __nv_bfloat16 g_vlo[BB*SS*DD];

// ======================= PTX helpers ========================================
__device__ __forceinline__ uint32_t smem_u32(const void* p) {
    uint32_t a;
    asm("{ .reg .u64 t; cvta.to.shared.u64 t, %1; cvt.u32.u64 %0, t; }" : "=r"(a) : "l"(p));
    return a;
}

#define CPASYNC16(dst, src) asm volatile("cp.async.cg.shared.global [%0], [%1], 16;" :: "r"(dst), "l"(src) : "memory")
#define CPCOMMIT() asm volatile("cp.async.commit_group;" ::: "memory")
#define CPWAIT1()  asm volatile("cp.async.wait_group 1;" ::: "memory")
#define CPWAIT0()  asm volatile("cp.async.wait_group 0;" ::: "memory")

#define LDSM_X4(R, A) \
    asm volatile("ldmatrix.sync.aligned.m8n8.x4.shared.b16 {%0,%1,%2,%3}, [%4];" \
        : "=r"((R)[0]), "=r"((R)[1]), "=r"((R)[2]), "=r"((R)[3]) : "r"(A))

#define LDSM_X2T(R, A) \
    asm volatile("ldmatrix.sync.aligned.m8n8.x2.trans.shared.b16 {%0,%1}, [%2];" \
        : "=r"((R)[0]), "=r"((R)[1]) : "r"(A))

__device__ __forceinline__ void mma_bf16(float* c, const uint32_t* a, const uint32_t* b) {
    asm volatile(
        "mma.sync.aligned.m16n8k16.row.col.f32.bf16.bf16.f32 "
        "{%0,%1,%2,%3}, {%4,%5,%6,%7}, {%8,%9}, {%0,%1,%2,%3};"
        : "+f"(c[0]), "+f"(c[1]), "+f"(c[2]), "+f"(c[3])
        : "r"(a[0]), "r"(a[1]), "r"(a[2]), "r"(a[3]), "r"(b[0]), "r"(b[1]));
}

__device__ __forceinline__ uint32_t packbf2(float x, float y) {
    __nv_bfloat162 t = __floats2bfloat162_rn(x, y);
    return *reinterpret_cast<uint32_t*>(&t);
}
__device__ __forceinline__ uint32_t packlo2(float x, float y, uint32_t hi) {
    __nv_bfloat162 h = *reinterpret_cast<__nv_bfloat162*>(&hi);
    return packbf2(x - __bfloat162float(h.x), y - __bfloat162float(h.y));
}

// ================ split fp32 -> bf16 hi/lo ==================================
__global__ void __launch_bounds__(256) split_kernel(
    const float* __restrict__ in, __nv_bfloat16* __restrict__ hi,
    __nv_bfloat16* __restrict__ lo, int n4)
{
    int i = blockIdx.x * 256 + threadIdx.x;
    if (i >= n4) return;
    float4 v = ((const float4*)in)[i];
    __nv_bfloat16 h0 = __float2bfloat16(v.x);
    __nv_bfloat16 h1 = __float2bfloat16(v.y);
    __nv_bfloat16 h2 = __float2bfloat16(v.z);
    __nv_bfloat16 h3 = __float2bfloat16(v.w);
    __nv_bfloat162 hp0; hp0.x = h0; hp0.y = h1;
    __nv_bfloat162 hp1; hp1.x = h2; hp1.y = h3;
    __nv_bfloat162 lp0, lp1;
    lp0.x = __float2bfloat16(v.x - __bfloat162float(h0));
    lp0.y = __float2bfloat16(v.y - __bfloat162float(h1));
    lp1.x = __float2bfloat16(v.z - __bfloat162float(h2));
    lp1.y = __float2bfloat16(v.w - __bfloat162float(h3));
    ((__nv_bfloat162*)hi)[i*2+0] = hp0;
    ((__nv_bfloat162*)hi)[i*2+1] = hp1;
    ((__nv_bfloat162*)lo)[i*2+0] = lp0;
    ((__nv_bfloat162*)lo)[i*2+1] = lp1;
}

// ============ mma.sync bf16x3 GEMM: C[M,N] = A @ W^T + bias =================
#define TROW 80
#define TILE_B (128 * TROW)
#define STAGE_B (4 * TILE_B)

template<bool RELU, bool SPLITOUT>
__global__ void __launch_bounds__(256, 2) gemm_mma(
    const __nv_bfloat16* __restrict__ Ah, const __nv_bfloat16* __restrict__ Al,
    const __nv_bfloat16* __restrict__ Wh, const __nv_bfloat16* __restrict__ Wl,
    const float* __restrict__ bias, float* __restrict__ C,
    __nv_bfloat16* __restrict__ Chi, __nv_bfloat16* __restrict__ Clo,
    int M, int N, int K)
{
    extern __shared__ __align__(128) char smem[];
    uint32_t sb = smem_u32(smem);

    int tid  = threadIdx.x;
    int lane = tid & 31;
    int wid  = tid >> 5;
    int wm   = wid & 3;
    int wn   = wid >> 2;
    int bm = blockIdx.y * 128;
    int bn = blockIdx.x * 128;

    const int nch = K >> 5;

    auto load_stage = [&](int c) {
        uint32_t st = sb + (c & 1) * STAGE_B;
        size_t kof = (size_t)c * 32;
        const __nv_bfloat16* bases[4];
        bases[0] = Ah + (size_t)bm * K + kof;
        bases[1] = Al + (size_t)bm * K + kof;
        bases[2] = Wh + (size_t)bn * K + kof;
        bases[3] = Wl + (size_t)bn * K + kof;
#pragma unroll
        for (int tI = 0; tI < 4; tI++) {
            uint32_t smtile = st + tI * TILE_B;
            const __nv_bfloat16* base = bases[tI];
#pragma unroll
            for (int u = 0; u < 2; u++) {
                int l   = tid + u * 256;
                int row = l >> 2;
                int ch  = l & 3;
                uint32_t dst = smtile + row * TROW + ch * 16;
                const char* src = (const char*)(base + (size_t)row * K) + ch * 16;
                CPASYNC16(dst, src);
            }
        }
        CPCOMMIT();
    };

    uint32_t aoff = ((((lane >> 3) & 1) * 8 + (lane & 7)) * TROW) + (lane >> 4) * 16;
    uint32_t boff = (((lane >> 4) * 8 + (lane & 7)) * TROW) + ((lane >> 3) & 1) * 16;

    float acc[2][8][4];
#pragma unroll
    for (int mt = 0; mt < 2; mt++)
#pragma unroll
        for (int n8 = 0; n8 < 8; n8++)
#pragma unroll
            for (int k = 0; k < 4; k++) acc[mt][n8][k] = 0.f;

    load_stage(0);
    for (int c = 0; c < nch; c++) {
        if (c + 1 < nch) { load_stage(c + 1); CPWAIT1(); }
        else             { CPWAIT0(); }
        __syncthreads();

        uint32_t st = sb + (c & 1) * STAGE_B;
        uint32_t aBaseH = st             + (wm * 32) * TROW + aoff;
        uint32_t aBaseL = st + TILE_B    + (wm * 32) * TROW + aoff;
        uint32_t bBaseH = st + 2*TILE_B  + (wn * 64) * TROW + boff;
        uint32_t bBaseL = st + 3*TILE_B  + (wn * 64) * TROW + boff;

#pragma unroll
        for (int ks = 0; ks < 2; ks++) {
            uint32_t ah[2][4], al[2][4];
#pragma unroll
            for (int mt = 0; mt < 2; mt++) {
                LDSM_X4(ah[mt], aBaseH + mt * (16 * TROW) + ks * 32);
                LDSM_X4(al[mt], aBaseL + mt * (16 * TROW) + ks * 32);
            }
#pragma unroll
            for (int g = 0; g < 4; g++) {
                uint32_t bh[4], bl[4];
                LDSM_X4(bh, bBaseH + g * (16 * TROW) + ks * 32);
                LDSM_X4(bl, bBaseL + g * (16 * TROW) + ks * 32);
#pragma unroll
                for (int mt = 0; mt < 2; mt++)
#pragma unroll
                    for (int hf = 0; hf < 2; hf++) {
                        int n8 = g * 2 + hf;
                        mma_bf16(acc[mt][n8], ah[mt], &bh[hf*2]);
                        mma_bf16(acc[mt][n8], ah[mt], &bl[hf*2]);
                        mma_bf16(acc[mt][n8], al[mt], &bh[hf*2]);
                    }
            }
        }
        __syncthreads();
    }

    int r_in = lane >> 2;
    int c_in = (lane & 3) * 2;
#pragma unroll
    for (int mt = 0; mt < 2; mt++) {
        int R0 = bm + wm * 32 + mt * 16 + r_in;
        int R1 = R0 + 8;
#pragma unroll
        for (int n8 = 0; n8 < 8; n8++) {
            int col = bn + wn * 64 + n8 * 8 + c_in;
            float b0 = bias[col], b1 = bias[col + 1];
            float o00 = acc[mt][n8][0] + b0, o01 = acc[mt][n8][1] + b1;
            float o10 = acc[mt][n8][2] + b0, o11 = acc[mt][n8][3] + b1;
            if (RELU) {
                o00 = fmaxf(o00, 0.f); o01 = fmaxf(o01, 0.f);
                o10 = fmaxf(o10, 0.f); o11 = fmaxf(o11, 0.f);
            }
            if (SPLITOUT) {
                uint32_t h0 = packbf2(o00, o01), h1 = packbf2(o10, o11);
                uint32_t l0 = packlo2(o00, o01, h0), l1 = packlo2(o10, o11, h1);
                *(uint32_t*)&Chi[(size_t)R0 * N + col] = h0;
                *(uint32_t*)&Chi[(size_t)R1 * N + col] = h1;
                *(uint32_t*)&Clo[(size_t)R0 * N + col] = l0;
                *(uint32_t*)&Clo[(size_t)R1 * N + col] = l1;
            } else {
                float2 o0, o1;
                o0.x = o00; o0.y = o01; o1.x = o10; o1.y = o11;
                *(float2*)&C[(size_t)R0 * N + col] = o0;
                *(float2*)&C[(size_t)R1 * N + col] = o1;
            }
        }
    }
}

// ================= tensor-core distance-decay attention ======================
// grid (S/16, H, B), 256 threads (8 warps).
// smem: sc[16][SCP] fp32 | qh,ql 16x144B | kh,kl 128x144B (reused for V)
#define AT_QH 66048
#define AT_QL (AT_QH + 2304)
#define AT_KH (AT_QL + 2304)
#define AT_KL (AT_KH + 18432)
#define AT_SMEM (AT_KL + 18432)   // 107520

__global__ void __launch_bounds__(256, 1) attn_kernel(
    const __nv_bfloat16* __restrict__ qhi, const __nv_bfloat16* __restrict__ qlo,
    const __nv_bfloat16* __restrict__ khi, const __nv_bfloat16* __restrict__ klo,
    const __nv_bfloat16* __restrict__ vhi, const __nv_bfloat16* __restrict__ vlo,
    const float* __restrict__ gammas,
    __nv_bfloat16* __restrict__ ohi, __nv_bfloat16* __restrict__ olo)
{
    extern __shared__ __align__(128) char smx[];
    float* sc = (float*)smx;
    uint32_t sb = smem_u32(smx);
    const uint32_t QH = sb + AT_QH;
    const uint32_t QL = sb + AT_QL;
    const uint32_t KH = sb + AT_KH;
    const uint32_t KL = sb + AT_KL;

    int b = blockIdx.z, h = blockIdx.y, i0 = blockIdx.x * 16;
    int t = threadIdx.x, lane = t & 31, w = t >> 5;

    size_t base_q = ((size_t)b*SS + i0)*DD + h*64;
    size_t base_k = (size_t)b*SS*DD + h*64;

    // ---- load Q tile hi/lo (16 rows x 128B each; 256 chunks total)
    {
        int sel = t >> 7;
        int idx = t & 127;
        int row = idx >> 3, ch = idx & 7;
        const __nv_bfloat16* src = (sel ? qlo : qhi) + base_q + (size_t)row*DD + ch*8;
        char* dst = smx + (sel ? AT_QL : AT_QH) + row*144 + ch*16;
        *(float4*)dst = *(const float4*)src;
    }
    __syncthreads();

    uint32_t aoff = ((((lane >> 3) & 1) * 8 + (lane & 7)) * 144) + (lane >> 4) * 16;
    uint32_t boff = (((lane >> 4) * 8 + (lane & 7)) * 144) + ((lane >> 3) & 1) * 16;

    uint32_t ah[4][4], al[4][4];
#pragma unroll
    for (int ks = 0; ks < 4; ks++) {
        LDSM_X4(ah[ks], QH + aoff + ks*32);
        LDSM_X4(al[ks], QL + aoff + ks*32);
    }

    // ---- QK^T via bf16x3 MMA: 8 tiles of 128 cols
    for (int jt = 0; jt < 8; jt++) {
        int jbase = jt * 128;
        __syncthreads();
#pragma unroll
        for (int u = 0; u < 4; u++) {
            int l = t + u * 256;          // 0..1023
            int row = l >> 3, ch = l & 7;
            const char* sh = (const char*)(khi + base_k + (size_t)(jbase+row)*DD) + ch*16;
            const char* sl = (const char*)(klo + base_k + (size_t)(jbase+row)*DD) + ch*16;
            CPASYNC16(KH + row*144 + ch*16, sh);
            CPASYNC16(KL + row*144 + ch*16, sl);
        }
        CPCOMMIT(); CPWAIT0();
        __syncthreads();

        float c0[4] = {0,0,0,0}, c1[4] = {0,0,0,0};
        uint32_t bb = (uint32_t)(w*16)*144 + boff;
#pragma unroll
        for (int ks = 0; ks < 4; ks++) {
            uint32_t bh[4], bl[4];
            LDSM_X4(bh, KH + bb + ks*32);
            LDSM_X4(bl, KL + bb + ks*32);
            mma_bf16(c0, ah[ks], &bh[0]);
            mma_bf16(c0, ah[ks], &bl[0]);
            mma_bf16(c0, al[ks], &bh[0]);
            mma_bf16(c1, ah[ks], &bh[2]);
            mma_bf16(c1, ah[ks], &bl[2]);
            mma_bf16(c1, al[ks], &bh[2]);
        }
        int r = lane >> 2, cb = jbase + w*16 + (lane & 3)*2;
        float2 v2;
        v2.x = c0[0]*0.125f; v2.y = c0[1]*0.125f; *(float2*)&sc[r*SCP + cb] = v2;
        v2.x = c0[2]*0.125f; v2.y = c0[3]*0.125f; *(float2*)&sc[(r+8)*SCP + cb] = v2;
        v2.x = c1[0]*0.125f; v2.y = c1[1]*0.125f; *(float2*)&sc[r*SCP + cb + 8] = v2;
        v2.x = c1[2]*0.125f; v2.y = c1[3]*0.125f; *(float2*)&sc[(r+8)*SCP + cb + 8] = v2;
    }
    __syncthreads();

    // ---- per-row math: softmax#1 -> masked cumsum -> decay -> softmax#2
    {
        float gamma = -log1pf(__expf(gammas[h]));
        for (int rr2 = 0; rr2 < 2; rr2++) {
            int r  = w*2 + rr2;
            int ig = i0 + r;
            float* row = sc + r*SCP;

            float s[32], p[32];
            float m = -INFINITY;
#pragma unroll
            for (int c = 0; c < 32; c++) {
                s[c] = row[c*32 + lane];
                m = fmaxf(m, s[c]);
            }
#pragma unroll
            for (int o = 16; o > 0; o >>= 1) m = fmaxf(m, __shfl_xor_sync(0xffffffffu, m, o));

            float sum1 = 0.f, summ = 0.f;
#pragma unroll
            for (int c = 0; c < 32; c++) {
                p[c] = __expf(s[c] - m);
                sum1 += p[c];
                if (c*32 + lane <= ig) summ += p[c];
            }
#pragma unroll
            for (int o = 16; o > 0; o >>= 1) {
                sum1 += __shfl_xor_sync(0xffffffffu, sum1, o);
                summ += __shfl_xor_sync(0xffffffffu, summ, o);
            }
            float inv1 = 1.f / sum1;

            float carry = 0.f, m2 = -INFINITY;
#pragma unroll
            for (int c = 0; c < 32; c++) {
                if (c*32 <= ig) {
                    int j = c*32 + lane;
                    float pm = (j <= ig) ? p[c] : 0.f;
                    float x = pm;
#pragma unroll
                    for (int o = 1; o < 32; o <<= 1) {
                        float y = __shfl_up_sync(0xffffffffu, x, o);
                        if (lane >= o) x += y;
                    }
                    float distraw = carry + x;
                    carry += __shfl_sync(0xffffffffu, x, 31);
                    float pos  = fabsf((float)(ig - j));
                    float dd   = (summ - distraw) * inv1 * pos;
                    float dist = sqrtf(fmaxf(dd, 0.f));
                    float eff  = __expf(dist * gamma);
                    eff = fminf(fmaxf(eff, 1e-5f), 1e5f);
                    float s2 = (j <= ig) ? s[c] * eff : -INFINITY;
                    s[c] = s2;
                    m2 = fmaxf(m2, s2);
                } else {
                    s[c] = -INFINITY;
                }
            }
#pragma unroll
            for (int o = 16; o > 0; o >>= 1) m2 = fmaxf(m2, __shfl_xor_sync(0xffffffffu, m2, o));

            float sum2 = 0.f;
#pragma unroll
            for (int c = 0; c < 32; c++) {
                float e = 0.f;
                if (c*32 <= ig) {
                    int j = c*32 + lane;
                    e = (j <= ig) ? __expf(s[c] - m2) : 0.f;
                }
                p[c] = e;
                sum2 += e;
            }
#pragma unroll
            for (int o = 16; o > 0; o >>= 1) sum2 += __shfl_xor_sync(0xffffffffu, sum2, o);
            float inv2 = 1.f / sum2;
#pragma unroll
            for (int c = 0; c < 32; c++) row[c*32 + lane] = p[c] * inv2;
        }
    }

    // ---- PV via bf16x3 MMA (warp w owns cols d = w*8..w*8+7)
    int jmax = i0 + 16;
    float acc[4] = {0.f, 0.f, 0.f, 0.f};
    int rr = lane >> 2, kc = (lane & 3) * 2;
    int vrow = lane & 15;
    for (int jbase = 0; jbase < jmax; jbase += 128) {
        int rows = jmax - jbase; if (rows > 128) rows = 128;
        __syncthreads();
        int total = rows * 8;
#pragma unroll
        for (int u = 0; u < 4; u++) {
            int l = t + u * 256;
            if (l < total) {
                int row = l >> 3, ch = l & 7;
                const char* sh = (const char*)(vhi + base_k + (size_t)(jbase+row)*DD) + ch*16;
                const char* sl = (const char*)(vlo + base_k + (size_t)(jbase+row)*DD) + ch*16;
                CPASYNC16(KH + row*144 + ch*16, sh);
                CPASYNC16(KL + row*144 + ch*16, sl);
            }
        }
        CPCOMMIT(); CPWAIT0();
        __syncthreads();

        int nk = rows >> 4;
        for (int kk = 0; kk < nk; kk++) {
            int j0 = jbase + kk*16;
            const float* p0 = &sc[rr*SCP + j0 + kc];
            float f00 = p0[0],        f01 = p0[1];
            float f10 = p0[8*SCP],    f11 = p0[8*SCP+1];
            float f20 = p0[8],        f21 = p0[9];
            float f30 = p0[8*SCP+8],  f31 = p0[8*SCP+9];
            uint32_t a_h[4], a_l[4];
            a_h[0] = packbf2(f00, f01); a_l[0] = packlo2(f00, f01, a_h[0]);
            a_h[1] = packbf2(f10, f11); a_l[1] = packlo2(f10, f11, a_h[1]);
            a_h[2] = packbf2(f20, f21); a_l[2] = packlo2(f20, f21, a_h[2]);
            a_h[3] = packbf2(f30, f31); a_l[3] = packlo2(f30, f31, a_h[3]);

            uint32_t vh[2], vl[2];
            uint32_t va = (uint32_t)(kk*16 + vrow)*144 + (uint32_t)w*16;
            LDSM_X2T(vh, KH + va);
            LDSM_X2T(vl, KL + va);

            mma_bf16(acc, a_h, vh);
            mma_bf16(acc, a_h, vl);
            mma_bf16(acc, a_l, vh);
        }
    }

    // ---- epilogue: out rows (rr, rr+8), cols (d, d+1) -> bf16 hi/lo
    {
        int d = w*8 + (lane & 3)*2;
        size_t o0 = ((size_t)b*SS + i0 + rr)*DD + h*64 + d;
        size_t o1 = o0 + (size_t)8*DD;
        uint32_t h0 = packbf2(acc[0], acc[1]);
        uint32_t l0 = packlo2(acc[0], acc[1], h0);
        uint32_t h1 = packbf2(acc[2], acc[3]);
        uint32_t l1 = packlo2(acc[2], acc[3], h1);
        *(uint32_t*)&ohi[o0] = h0;
        *(uint32_t*)&olo[o0] = l0;
        *(uint32_t*)&ohi[o1] = h1;
        *(uint32_t*)&olo[o1] = l1;
    }
}

// ---------------- residual add + LayerNorm ----------------------------------
template<bool SPLITOUT>
__global__ void __launch_bounds__(256) add_ln_kernel(
    const float* __restrict__ A, const float* __restrict__ Bres,
    const float* __restrict__ w, const float* __restrict__ bias,
    float* __restrict__ outp,
    __nv_bfloat16* __restrict__ ohi, __nv_bfloat16* __restrict__ olo)
{
    __shared__ float red1[8], red2[8];
    int row = blockIdx.x;
    int t   = threadIdx.x;
    const float* pa = A    + (size_t)row*DD;
    const float* pb = Bres + (size_t)row*DD;

    float4 a4 = *(const float4*)&pa[t*4];
    float4 b4 = *(const float4*)&pb[t*4];
    float v0 = a4.x + b4.x, v1 = a4.y + b4.y, v2 = a4.z + b4.z, v3 = a4.w + b4.w;

    int lane = t & 31, wp = t >> 5;
    float s = v0 + v1 + v2 + v3;
#pragma unroll
    for (int o = 16; o > 0; o >>= 1) s += __shfl_xor_sync(0xffffffffu, s, o);
    if (lane == 0) red1[wp] = s;
    __syncthreads();
    float tot = 0.f;
#pragma unroll
    for (int i = 0; i < 8; i++) tot += red1[i];
    float mu = tot * (1.f / DD);

    float d0 = v0-mu, d1 = v1-mu, d2 = v2-mu, d3 = v3-mu;
    float q2 = d0*d0 + d1*d1 + d2*d2 + d3*d3;
#pragma unroll
    for (int o = 16; o > 0; o >>= 1) q2 += __shfl_xor_sync(0xffffffffu, q2, o);
    if (lane == 0) red2[wp] = q2;
    __syncthreads();
    float tv = 0.f;
#pragma unroll
    for (int i = 0; i < 8; i++) tv += red2[i];
    float inv = rsqrtf(tv * (1.f / DD) + 1e-5f);

    float4 w4  = *(const float4*)&w[t*4];
    float4 bi4 = *(const float4*)&bias[t*4];
    float4 o4;
    o4.x = d0*inv*w4.x + bi4.x;
    o4.y = d1*inv*w4.y + bi4.y;
    o4.z = d2*inv*w4.z + bi4.z;
    o4.w = d3*inv*w4.w + bi4.w;
    *(float4*)&outp[(size_t)row*DD + t*4] = o4;

    if (SPLITOUT) {
        uint32_t h0 = packbf2(o4.x, o4.y), h1 = packbf2(o4.z, o4.w);
        uint32_t l0 = packlo2(o4.x, o4.y, h0), l1 = packlo2(o4.z, o4.w, h1);
        size_t base2 = (size_t)row * (DD/2) + t*2;
        ((uint32_t*)ohi)[base2]     = h0;
        ((uint32_t*)ohi)[base2 + 1] = h1;
        ((uint32_t*)olo)[base2]     = l0;
        ((uint32_t*)olo)[base2 + 1] = l1;
    }
}

// ---------------- launcher ---------------------------------------------------
extern "C" void kernel_launch(void* const* d_in, const int* in_sizes, int n_in,
                              void* d_out, int out_size)
{
    int off = (in_sizes[0] == 1) ? 1 : 0;
    const float* query  = (const float*)d_in[off + 0];
    const float* key    = (const float*)d_in[off + 1];
    const float* values = (const float*)d_in[off + 2];
    const float* Wq = (const float*)d_in[off + 3];
    const float* bq = (const float*)d_in[off + 4];
    const float* Wk = (const float*)d_in[off + 5];
    const float* bk = (const float*)d_in[off + 6];
    const float* Wv = (const float*)d_in[off + 7];
    const float* bv = (const float*)d_in[off + 8];
    const float* Wo = (const float*)d_in[off + 9];
    const float* bo = (const float*)d_in[off + 10];
    const float* gammas = (const float*)d_in[off + 11];
    const float* ln1w = (const float*)d_in[off + 12];
    const float* ln1b = (const float*)d_in[off + 13];
    const float* W1 = (const float*)d_in[off + 14];
    const float* b1 = (const float*)d_in[off + 15];
    const float* W2 = (const float*)d_in[off + 16];
    const float* b2 = (const float*)d_in[off + 17];
    const float* ln2w = (const float*)d_in[off + 18];
    const float* ln2b = (const float*)d_in[off + 19];

    float *pattnout, *px, *pf;
    cudaGetSymbolAddress((void**)&pattnout, g_attnout);
    cudaGetSymbolAddress((void**)&px, g_x);
    cudaGetSymbolAddress((void**)&pf, g_f);
    __nv_bfloat16 *ahi, *alo, *whi, *wlo, *hhi, *hlo;
    __nv_bfloat16 *qhi, *qlo, *khi, *klo, *vhi, *vlo;
    cudaGetSymbolAddress((void**)&ahi, g_ahi);
    cudaGetSymbolAddress((void**)&alo, g_alo);
    cudaGetSymbolAddress((void**)&whi, g_whi);
    cudaGetSymbolAddress((void**)&wlo, g_wlo);
    cudaGetSymbolAddress((void**)&hhi, g_hhi);
    cudaGetSymbolAddress((void**)&hlo, g_hlo);
    cudaGetSymbolAddress((void**)&qhi, g_qhi);
    cudaGetSymbolAddress((void**)&qlo, g_qlo);
    cudaGetSymbolAddress((void**)&khi, g_khi);
    cudaGetSymbolAddress((void**)&klo, g_klo);
    cudaGetSymbolAddress((void**)&vhi, g_vhi);
    cudaGetSymbolAddress((void**)&vlo, g_vlo);

    const int M = BB * SS;   // 4096
    const int GEMM_SMEM = 2 * STAGE_B;
    cudaFuncSetAttribute(gemm_mma<false,false>, cudaFuncAttributeMaxDynamicSharedMemorySize, GEMM_SMEM);
    cudaFuncSetAttribute(gemm_mma<false,true>,  cudaFuncAttributeMaxDynamicSharedMemorySize, GEMM_SMEM);
    cudaFuncSetAttribute(gemm_mma<true,true>,   cudaFuncAttributeMaxDynamicSharedMemorySize, GEMM_SMEM);
    cudaFuncSetAttribute(attn_kernel, cudaFuncAttributeMaxDynamicSharedMemorySize, AT_SMEM);

    auto split = [&](const float* src, __nv_bfloat16* hi, __nv_bfloat16* lo, int n) {
        split_kernel<<<(n/4 + 255) / 256, 256>>>(src, hi, lo, n / 4);
    };

    dim3 gD(DD/128, M/128);
    dim3 gF(DFFF/128, M/128);

    // QKV projections -> bf16 hi/lo directly
    split(query, ahi, alo, M*DD);
    split(Wq, whi, wlo, DD*DD);
    gemm_mma<false,true><<<gD, 256, GEMM_SMEM>>>(ahi, alo, whi, wlo, bq, nullptr, qhi, qlo, M, DD, DD);
    split(key, ahi, alo, M*DD);
    split(Wk, whi, wlo, DD*DD);
    gemm_mma<false,true><<<gD, 256, GEMM_SMEM>>>(ahi, alo, whi, wlo, bk, nullptr, khi, klo, M, DD, DD);
    split(values, ahi, alo, M*DD);
    split(Wv, whi, wlo, DD*DD);
    gemm_mma<false,true><<<gD, 256, GEMM_SMEM>>>(ahi, alo, whi, wlo, bv, nullptr, vhi, vlo, M, DD, DD);

    // attention -> concat bf16 hi/lo into (ahi, alo)
    attn_kernel<<<dim3(SS/ROWS, HH, BB), 256, AT_SMEM>>>(qhi, qlo, khi, klo, vhi, vlo,
                                                         gammas, ahi, alo);

    // output projection
    split(Wo, whi, wlo, DD*DD);
    gemm_mma<false,false><<<gD, 256, GEMM_SMEM>>>(ahi, alo, whi, wlo, bo, pattnout, nullptr, nullptr, M, DD, DD);

    // LN1 -> px (fp32) + (ahi, alo)
    add_ln_kernel<true><<<M, 256>>>(query, pattnout, ln1w, ln1b, px, ahi, alo);

    // FFN1 (+ReLU) -> bf16 hi/lo
    split(W1, whi, wlo, DFFF*DD);
    gemm_mma<true,true><<<gF, 256, GEMM_SMEM>>>(ahi, alo, whi, wlo, b1, nullptr, hhi, hlo, M, DFFF, DD);

    // FFN2
    split(W2, whi, wlo, DD*DFFF);
    gemm_mma<false,false><<<gD, 256, GEMM_SMEM>>>(hhi, hlo, whi, wlo, b2, pf, nullptr, nullptr, M, DD, DFFF);

    // LN2 -> final output
    add_ln_kernel<false><<<M, 256>>>(px, pf, ln2w, ln2b, (float*)d_out, nullptr, nullptr);
}

// round 6
// speedup vs baseline: 2.2402x; 1.0110x over previous
#include <cuda_runtime.h>
#include <cuda_bf16.h>
#include <math.h>
#include <stdint.h>

// Problem constants
#define BB 4
#define SS 1024
#define DD 1024
#define HH 16
#define DKK 64
#define DFFF 4096
#define ROWS 16
#define SCP 1032   // score row pitch (floats)

// ---------------- scratch (device globals) -----------------------------------
__device__ float g_attnout[BB*SS*DD];
__device__ float g_x[BB*SS*DD];
__device__ float g_f[BB*SS*DD];
// split inputs (activations)
__device__ __nv_bfloat16 g_aq_hi[BB*SS*DD], g_aq_lo[BB*SS*DD];
__device__ __nv_bfloat16 g_ak_hi[BB*SS*DD], g_ak_lo[BB*SS*DD];
__device__ __nv_bfloat16 g_av_hi[BB*SS*DD], g_av_lo[BB*SS*DD];
// split weights
__device__ __nv_bfloat16 g_wq_hi[DD*DD], g_wq_lo[DD*DD];
__device__ __nv_bfloat16 g_wk_hi[DD*DD], g_wk_lo[DD*DD];
__device__ __nv_bfloat16 g_wv_hi[DD*DD], g_wv_lo[DD*DD];
__device__ __nv_bfloat16 g_wo_hi[DD*DD], g_wo_lo[DD*DD];
__device__ __nv_bfloat16 g_w1_hi[DFFF*DD], g_w1_lo[DFFF*DD];
__device__ __nv_bfloat16 g_w2_hi[DD*DFFF], g_w2_lo[DD*DFFF];
// intermediates
__device__ __nv_bfloat16 g_ahi[BB*SS*DD], g_alo[BB*SS*DD];       // concat / LN1 out
__device__ __nv_bfloat16 g_hhi[BB*SS*DFFF], g_hlo[BB*SS*DFFF];   // FFN1 out
__device__ __nv_bfloat16 g_qhi[BB*SS*DD], g_qlo[BB*SS*DD];
__device__ __nv_bfloat16 g_khi[BB*SS*DD], g_klo[BB*SS*DD];
__device__ __nv_bfloat16 g_vhi[BB*SS*DD], g_vlo[BB*SS*DD];

// ======================= PTX helpers ========================================
__device__ __forceinline__ uint32_t smem_u32(const void* p) {
    uint32_t a;
    asm("{ .reg .u64 t; cvta.to.shared.u64 t, %1; cvt.u32.u64 %0, t; }" : "=r"(a) : "l"(p));
    return a;
}

#define CPASYNC16(dst, src) asm volatile("cp.async.cg.shared.global [%0], [%1], 16;" :: "r"(dst), "l"(src) : "memory")
#define CPCOMMIT() asm volatile("cp.async.commit_group;" ::: "memory")
#define CPWAIT1()  asm volatile("cp.async.wait_group 1;" ::: "memory")
#define CPWAIT0()  asm volatile("cp.async.wait_group 0;" ::: "memory")

#define LDSM_X4(R, A) \
    asm volatile("ldmatrix.sync.aligned.m8n8.x4.shared.b16 {%0,%1,%2,%3}, [%4];" \
        : "=r"((R)[0]), "=r"((R)[1]), "=r"((R)[2]), "=r"((R)[3]) : "r"(A))

#define LDSM_X2T(R, A) \
    asm volatile("ldmatrix.sync.aligned.m8n8.x2.trans.shared.b16 {%0,%1}, [%2];" \
        : "=r"((R)[0]), "=r"((R)[1]) : "r"(A))

__device__ __forceinline__ void mma_bf16(float* c, const uint32_t* a, const uint32_t* b) {
    asm volatile(
        "mma.sync.aligned.m16n8k16.row.col.f32.bf16.bf16.f32 "
        "{%0,%1,%2,%3}, {%4,%5,%6,%7}, {%8,%9}, {%0,%1,%2,%3};"
        : "+f"(c[0]), "+f"(c[1]), "+f"(c[2]), "+f"(c[3])
        : "r"(a[0]), "r"(a[1]), "r"(a[2]), "r"(a[3]), "r"(b[0]), "r"(b[1]));
}

__device__ __forceinline__ uint32_t packbf2(float x, float y) {
    __nv_bfloat162 t = __floats2bfloat162_rn(x, y);
    return *reinterpret_cast<uint32_t*>(&t);
}
__device__ __forceinline__ uint32_t packlo2(float x, float y, uint32_t hi) {
    __nv_bfloat162 h = *reinterpret_cast<__nv_bfloat162*>(&hi);
    return packbf2(x - __bfloat162float(h.x), y - __bfloat162float(h.y));
}

// ================ mega split: all 9 fp32->bf16 hi/lo splits in one launch ====
struct SplitSeg { const float* src; __nv_bfloat16* hi; __nv_bfloat16* lo; };
struct SplitArgs { SplitSeg seg[9]; int start[10]; };

__global__ void __launch_bounds__(256) multi_split_kernel(SplitArgs a)
{
    int bx = blockIdx.x;
    int s = 0;
#pragma unroll
    for (int i = 0; i < 8; i++) if (bx >= a.start[i+1]) s = i+1;
    SplitSeg sg = a.seg[s];
    int i = (bx - a.start[s]) * 256 + threadIdx.x;   // float4 index (exact fit)
    float4 v = ((const float4*)sg.src)[i];
    uint32_t h0 = packbf2(v.x, v.y), h1 = packbf2(v.z, v.w);
    uint32_t l0 = packlo2(v.x, v.y, h0), l1 = packlo2(v.z, v.w, h1);
    ((uint32_t*)sg.hi)[i*2+0] = h0;
    ((uint32_t*)sg.hi)[i*2+1] = h1;
    ((uint32_t*)sg.lo)[i*2+0] = l0;
    ((uint32_t*)sg.lo)[i*2+1] = l1;
}

// ============ mma.sync bf16x3 GEMM: C[M,N] = A @ W^T + bias =================
#define TROW 80
#define TILE_B (128 * TROW)
#define STAGE_B (4 * TILE_B)

struct GemmIO {
    const __nv_bfloat16 *Ah, *Al, *Wh, *Wl;
    const float* bias;
    float* C;
    __nv_bfloat16 *Chi, *Clo;
};

template<bool RELU, bool SPLITOUT>
__global__ void __launch_bounds__(256, 2) gemm_mma(
    GemmIO io0, GemmIO io1, GemmIO io2, int M, int N, int K)
{
    extern __shared__ __align__(128) char smem[];
    uint32_t sb = smem_u32(smem);

    GemmIO io = (blockIdx.z == 0) ? io0 : (blockIdx.z == 1) ? io1 : io2;

    int tid  = threadIdx.x;
    int lane = tid & 31;
    int wid  = tid >> 5;
    int wm   = wid & 3;
    int wn   = wid >> 2;
    int bm = blockIdx.y * 128;
    int bn = blockIdx.x * 128;

    const int nch = K >> 5;

    auto load_stage = [&](int c) {
        uint32_t st = sb + (c & 1) * STAGE_B;
        size_t kof = (size_t)c * 32;
        const __nv_bfloat16* bases[4];
        bases[0] = io.Ah + (size_t)bm * K + kof;
        bases[1] = io.Al + (size_t)bm * K + kof;
        bases[2] = io.Wh + (size_t)bn * K + kof;
        bases[3] = io.Wl + (size_t)bn * K + kof;
#pragma unroll
        for (int tI = 0; tI < 4; tI++) {
            uint32_t smtile = st + tI * TILE_B;
            const __nv_bfloat16* base = bases[tI];
#pragma unroll
            for (int u = 0; u < 2; u++) {
                int l   = tid + u * 256;
                int row = l >> 2;
                int ch  = l & 3;
                uint32_t dst = smtile + row * TROW + ch * 16;
                const char* src = (const char*)(base + (size_t)row * K) + ch * 16;
                CPASYNC16(dst, src);
            }
        }
        CPCOMMIT();
    };

    uint32_t aoff = ((((lane >> 3) & 1) * 8 + (lane & 7)) * TROW) + (lane >> 4) * 16;
    uint32_t boff = (((lane >> 4) * 8 + (lane & 7)) * TROW) + ((lane >> 3) & 1) * 16;

    float acc[2][8][4];
#pragma unroll
    for (int mt = 0; mt < 2; mt++)
#pragma unroll
        for (int n8 = 0; n8 < 8; n8++)
#pragma unroll
            for (int k = 0; k < 4; k++) acc[mt][n8][k] = 0.f;

    load_stage(0);
    for (int c = 0; c < nch; c++) {
        if (c + 1 < nch) { load_stage(c + 1); CPWAIT1(); }
        else             { CPWAIT0(); }
        __syncthreads();

        uint32_t st = sb + (c & 1) * STAGE_B;
        uint32_t aBaseH = st             + (wm * 32) * TROW + aoff;
        uint32_t aBaseL = st + TILE_B    + (wm * 32) * TROW + aoff;
        uint32_t bBaseH = st + 2*TILE_B  + (wn * 64) * TROW + boff;
        uint32_t bBaseL = st + 3*TILE_B  + (wn * 64) * TROW + boff;

#pragma unroll
        for (int ks = 0; ks < 2; ks++) {
            uint32_t ah[2][4], al[2][4];
#pragma unroll
            for (int mt = 0; mt < 2; mt++) {
                LDSM_X4(ah[mt], aBaseH + mt * (16 * TROW) + ks * 32);
                LDSM_X4(al[mt], aBaseL + mt * (16 * TROW) + ks * 32);
            }
#pragma unroll
            for (int g = 0; g < 4; g++) {
                uint32_t bh[4], bl[4];
                LDSM_X4(bh, bBaseH + g * (16 * TROW) + ks * 32);
                LDSM_X4(bl, bBaseL + g * (16 * TROW) + ks * 32);
#pragma unroll
                for (int mt = 0; mt < 2; mt++)
#pragma unroll
                    for (int hf = 0; hf < 2; hf++) {
                        int n8 = g * 2 + hf;
                        mma_bf16(acc[mt][n8], ah[mt], &bh[hf*2]);
                        mma_bf16(acc[mt][n8], ah[mt], &bl[hf*2]);
                        mma_bf16(acc[mt][n8], al[mt], &bh[hf*2]);
                    }
            }
        }
        __syncthreads();
    }

    int r_in = lane >> 2;
    int c_in = (lane & 3) * 2;
#pragma unroll
    for (int mt = 0; mt < 2; mt++) {
        int R0 = bm + wm * 32 + mt * 16 + r_in;
        int R1 = R0 + 8;
#pragma unroll
        for (int n8 = 0; n8 < 8; n8++) {
            int col = bn + wn * 64 + n8 * 8 + c_in;
            float b0 = io.bias[col], b1 = io.bias[col + 1];
            float o00 = acc[mt][n8][0] + b0, o01 = acc[mt][n8][1] + b1;
            float o10 = acc[mt][n8][2] + b0, o11 = acc[mt][n8][3] + b1;
            if (RELU) {
                o00 = fmaxf(o00, 0.f); o01 = fmaxf(o01, 0.f);
                o10 = fmaxf(o10, 0.f); o11 = fmaxf(o11, 0.f);
            }
            if (SPLITOUT) {
                uint32_t h0 = packbf2(o00, o01), h1 = packbf2(o10, o11);
                uint32_t l0 = packlo2(o00, o01, h0), l1 = packlo2(o10, o11, h1);
                *(uint32_t*)&io.Chi[(size_t)R0 * N + col] = h0;
                *(uint32_t*)&io.Chi[(size_t)R1 * N + col] = h1;
                *(uint32_t*)&io.Clo[(size_t)R0 * N + col] = l0;
                *(uint32_t*)&io.Clo[(size_t)R1 * N + col] = l1;
            } else {
                float2 o0, o1;
                o0.x = o00; o0.y = o01; o1.x = o10; o1.y = o11;
                *(float2*)&io.C[(size_t)R0 * N + col] = o0;
                *(float2*)&io.C[(size_t)R1 * N + col] = o1;
            }
        }
    }
}

// ================= tensor-core distance-decay attention ======================
#define AT_QH 66048
#define AT_QL (AT_QH + 2304)
#define AT_KH (AT_QL + 2304)
#define AT_KL (AT_KH + 18432)
#define AT_SMEM (AT_KL + 18432)   // 107520

__global__ void __launch_bounds__(256, 1) attn_kernel(
    const __nv_bfloat16* __restrict__ qhi, const __nv_bfloat16* __restrict__ qlo,
    const __nv_bfloat16* __restrict__ khi, const __nv_bfloat16* __restrict__ klo,
    const __nv_bfloat16* __restrict__ vhi, const __nv_bfloat16* __restrict__ vlo,
    const float* __restrict__ gammas,
    __nv_bfloat16* __restrict__ ohi, __nv_bfloat16* __restrict__ olo)
{
    extern __shared__ __align__(128) char smx[];
    float* sc = (float*)smx;
    uint32_t sb = smem_u32(smx);
    const uint32_t QH = sb + AT_QH;
    const uint32_t QL = sb + AT_QL;
    const uint32_t KH = sb + AT_KH;
    const uint32_t KL = sb + AT_KL;

    int b = blockIdx.z, h = blockIdx.y, i0 = blockIdx.x * 16;
    int t = threadIdx.x, lane = t & 31, w = t >> 5;

    size_t base_q = ((size_t)b*SS + i0)*DD + h*64;
    size_t base_k = (size_t)b*SS*DD + h*64;

    // ---- load Q tile hi/lo
    {
        int sel = t >> 7;
        int idx = t & 127;
        int row = idx >> 3, ch = idx & 7;
        const __nv_bfloat16* src = (sel ? qlo : qhi) + base_q + (size_t)row*DD + ch*8;
        char* dst = smx + (sel ? AT_QL : AT_QH) + row*144 + ch*16;
        *(float4*)dst = *(const float4*)src;
    }
    __syncthreads();

    uint32_t aoff = ((((lane >> 3) & 1) * 8 + (lane & 7)) * 144) + (lane >> 4) * 16;
    uint32_t boff = (((lane >> 4) * 8 + (lane & 7)) * 144) + ((lane >> 3) & 1) * 16;

    uint32_t ah[4][4], al[4][4];
#pragma unroll
    for (int ks = 0; ks < 4; ks++) {
        LDSM_X4(ah[ks], QH + aoff + ks*32);
        LDSM_X4(al[ks], QL + aoff + ks*32);
    }

    // ---- QK^T via bf16x3 MMA: 8 tiles of 128 cols
    for (int jt = 0; jt < 8; jt++) {
        int jbase = jt * 128;
        __syncthreads();
#pragma unroll
        for (int u = 0; u < 4; u++) {
            int l = t + u * 256;
            int row = l >> 3, ch = l & 7;
            const char* sh = (const char*)(khi + base_k + (size_t)(jbase+row)*DD) + ch*16;
            const char* sl = (const char*)(klo + base_k + (size_t)(jbase+row)*DD) + ch*16;
            CPASYNC16(KH + row*144 + ch*16, sh);
            CPASYNC16(KL + row*144 + ch*16, sl);
        }
        CPCOMMIT(); CPWAIT0();
        __syncthreads();

        float c0[4] = {0,0,0,0}, c1[4] = {0,0,0,0};
        uint32_t bb = (uint32_t)(w*16)*144 + boff;
#pragma unroll
        for (int ks = 0; ks < 4; ks++) {
            uint32_t bh[4], bl[4];
            LDSM_X4(bh, KH + bb + ks*32);
            LDSM_X4(bl, KL + bb + ks*32);
            mma_bf16(c0, ah[ks], &bh[0]);
            mma_bf16(c0, ah[ks], &bl[0]);
            mma_bf16(c0, al[ks], &bh[0]);
            mma_bf16(c1, ah[ks], &bh[2]);
            mma_bf16(c1, ah[ks], &bl[2]);
            mma_bf16(c1, al[ks], &bh[2]);
        }
        int r = lane >> 2, cb = jbase + w*16 + (lane & 3)*2;
        float2 v2;
        v2.x = c0[0]*0.125f; v2.y = c0[1]*0.125f; *(float2*)&sc[r*SCP + cb] = v2;
        v2.x = c0[2]*0.125f; v2.y = c0[3]*0.125f; *(float2*)&sc[(r+8)*SCP + cb] = v2;
        v2.x = c1[0]*0.125f; v2.y = c1[1]*0.125f; *(float2*)&sc[r*SCP + cb + 8] = v2;
        v2.x = c1[2]*0.125f; v2.y = c1[3]*0.125f; *(float2*)&sc[(r+8)*SCP + cb + 8] = v2;
    }
    __syncthreads();

    // ---- prefetch V tile 0 (K buffers free; overlaps row math)
    int jmax = i0 + 16;
    {
        int rows0 = jmax < 128 ? jmax : 128;
        int total = rows0 * 8;
#pragma unroll
        for (int u = 0; u < 4; u++) {
            int l = t + u * 256;
            if (l < total) {
                int row = l >> 3, ch = l & 7;
                const char* sh = (const char*)(vhi + base_k + (size_t)row*DD) + ch*16;
                const char* sl = (const char*)(vlo + base_k + (size_t)row*DD) + ch*16;
                CPASYNC16(KH + row*144 + ch*16, sh);
                CPASYNC16(KL + row*144 + ch*16, sl);
            }
        }
        CPCOMMIT();
    }

    // ---- per-row math
    {
        float gamma = -log1pf(__expf(gammas[h]));
        for (int rr2 = 0; rr2 < 2; rr2++) {
            int r  = w*2 + rr2;
            int ig = i0 + r;
            float* row = sc + r*SCP;

            float s[32], p[32];
            float m = -INFINITY;
#pragma unroll
            for (int c = 0; c < 32; c++) {
                s[c] = row[c*32 + lane];
                m = fmaxf(m, s[c]);
            }
#pragma unroll
            for (int o = 16; o > 0; o >>= 1) m = fmaxf(m, __shfl_xor_sync(0xffffffffu, m, o));

            float sum1 = 0.f, summ = 0.f;
#pragma unroll
            for (int c = 0; c < 32; c++) {
                p[c] = __expf(s[c] - m);
                sum1 += p[c];
                if (c*32 + lane <= ig) summ += p[c];
            }
#pragma unroll
            for (int o = 16; o > 0; o >>= 1) {
                sum1 += __shfl_xor_sync(0xffffffffu, sum1, o);
                summ += __shfl_xor_sync(0xffffffffu, summ, o);
            }
            float inv1 = 1.f / sum1;

            float carry = 0.f, m2 = -INFINITY;
#pragma unroll
            for (int c = 0; c < 32; c++) {
                if (c*32 <= ig) {
                    int j = c*32 + lane;
                    float pm = (j <= ig) ? p[c] : 0.f;
                    float x = pm;
#pragma unroll
                    for (int o = 1; o < 32; o <<= 1) {
                        float y = __shfl_up_sync(0xffffffffu, x, o);
                        if (lane >= o) x += y;
                    }
                    float distraw = carry + x;
                    carry += __shfl_sync(0xffffffffu, x, 31);
                    float pos  = fabsf((float)(ig - j));
                    float dd   = (summ - distraw) * inv1 * pos;
                    float dist = sqrtf(fmaxf(dd, 0.f));
                    float eff  = __expf(dist * gamma);
                    eff = fminf(fmaxf(eff, 1e-5f), 1e5f);
                    float s2 = (j <= ig) ? s[c] * eff : -INFINITY;
                    s[c] = s2;
                    m2 = fmaxf(m2, s2);
                } else {
                    s[c] = -INFINITY;
                }
            }
#pragma unroll
            for (int o = 16; o > 0; o >>= 1) m2 = fmaxf(m2, __shfl_xor_sync(0xffffffffu, m2, o));

            float sum2 = 0.f;
#pragma unroll
            for (int c = 0; c < 32; c++) {
                float e = 0.f;
                if (c*32 <= ig) {
                    int j = c*32 + lane;
                    e = (j <= ig) ? __expf(s[c] - m2) : 0.f;
                }
                p[c] = e;
                sum2 += e;
            }
#pragma unroll
            for (int o = 16; o > 0; o >>= 1) sum2 += __shfl_xor_sync(0xffffffffu, sum2, o);
            float inv2 = 1.f / sum2;
#pragma unroll
            for (int c = 0; c < 32; c++) row[c*32 + lane] = p[c] * inv2;
        }
    }

    // ---- PV via bf16x3 MMA (warp w owns cols d = w*8..w*8+7)
    float acc[4] = {0.f, 0.f, 0.f, 0.f};
    int rr = lane >> 2, kc = (lane & 3) * 2;
    int vrow = lane & 15;
    for (int jbase = 0; jbase < jmax; jbase += 128) {
        int rows = jmax - jbase; if (rows > 128) rows = 128;
        if (jbase > 0) {
            __syncthreads();
            int total = rows * 8;
#pragma unroll
            for (int u = 0; u < 4; u++) {
                int l = t + u * 256;
                if (l < total) {
                    int row = l >> 3, ch = l & 7;
                    const char* sh = (const char*)(vhi + base_k + (size_t)(jbase+row)*DD) + ch*16;
                    const char* sl = (const char*)(vlo + base_k + (size_t)(jbase+row)*DD) + ch*16;
                    CPASYNC16(KH + row*144 + ch*16, sh);
                    CPASYNC16(KL + row*144 + ch*16, sl);
                }
            }
            CPCOMMIT();
        }
        CPWAIT0();
        __syncthreads();

        int nk = rows >> 4;
        for (int kk = 0; kk < nk; kk++) {
            int j0 = jbase + kk*16;
            const float* p0 = &sc[rr*SCP + j0 + kc];
            float f00 = p0[0],        f01 = p0[1];
            float f10 = p0[8*SCP],    f11 = p0[8*SCP+1];
            float f20 = p0[8],        f21 = p0[9];
            float f30 = p0[8*SCP+8],  f31 = p0[8*SCP+9];
            uint32_t a_h[4], a_l[4];
            a_h[0] = packbf2(f00, f01); a_l[0] = packlo2(f00, f01, a_h[0]);
            a_h[1] = packbf2(f10, f11); a_l[1] = packlo2(f10, f11, a_h[1]);
            a_h[2] = packbf2(f20, f21); a_l[2] = packlo2(f20, f21, a_h[2]);
            a_h[3] = packbf2(f30, f31); a_l[3] = packlo2(f30, f31, a_h[3]);

            uint32_t vh[2], vl[2];
            uint32_t va = (uint32_t)(kk*16 + vrow)*144 + (uint32_t)w*16;
            LDSM_X2T(vh, KH + va);
            LDSM_X2T(vl, KL + va);

            mma_bf16(acc, a_h, vh);
            mma_bf16(acc, a_h, vl);
            mma_bf16(acc, a_l, vh);
        }
    }

    // ---- epilogue
    {
        size_t o0 = ((size_t)b*SS + i0 + rr)*DD + h*64 + w*8 + kc;
        size_t o1 = o0 + (size_t)8*DD;
        uint32_t h0 = packbf2(acc[0], acc[1]);
        uint32_t l0 = packlo2(acc[0], acc[1], h0);
        uint32_t h1 = packbf2(acc[2], acc[3]);
        uint32_t l1 = packlo2(acc[2], acc[3], h1);
        *(uint32_t*)&ohi[o0] = h0;
        *(uint32_t*)&olo[o0] = l0;
        *(uint32_t*)&ohi[o1] = h1;
        *(uint32_t*)&olo[o1] = l1;
    }
}

// ---------------- residual add + LayerNorm ----------------------------------
template<bool SPLITOUT>
__global__ void __launch_bounds__(256) add_ln_kernel(
    const float* __restrict__ A, const float* __restrict__ Bres,
    const float* __restrict__ w, const float* __restrict__ bias,
    float* __restrict__ outp,
    __nv_bfloat16* __restrict__ ohi, __nv_bfloat16* __restrict__ olo)
{
    __shared__ float red1[8], red2[8];
    int row = blockIdx.x;
    int t   = threadIdx.x;
    const float* pa = A    + (size_t)row*DD;
    const float* pb = Bres + (size_t)row*DD;

    float4 a4 = *(const float4*)&pa[t*4];
    float4 b4 = *(const float4*)&pb[t*4];
    float v0 = a4.x + b4.x, v1 = a4.y + b4.y, v2 = a4.z + b4.z, v3 = a4.w + b4.w;

    int lane = t & 31, wp = t >> 5;
    float s = v0 + v1 + v2 + v3;
#pragma unroll
    for (int o = 16; o > 0; o >>= 1) s += __shfl_xor_sync(0xffffffffu, s, o);
    if (lane == 0) red1[wp] = s;
    __syncthreads();
    float tot = 0.f;
#pragma unroll
    for (int i = 0; i < 8; i++) tot += red1[i];
    float mu = tot * (1.f / DD);

    float d0 = v0-mu, d1 = v1-mu, d2 = v2-mu, d3 = v3-mu;
    float q2 = d0*d0 + d1*d1 + d2*d2 + d3*d3;
#pragma unroll
    for (int o = 16; o > 0; o >>= 1) q2 += __shfl_xor_sync(0xffffffffu, q2, o);
    if (lane == 0) red2[wp] = q2;
    __syncthreads();
    float tv = 0.f;
#pragma unroll
    for (int i = 0; i < 8; i++) tv += red2[i];
    float inv = rsqrtf(tv * (1.f / DD) + 1e-5f);

    float4 w4  = *(const float4*)&w[t*4];
    float4 bi4 = *(const float4*)&bias[t*4];
    float4 o4;
    o4.x = d0*inv*w4.x + bi4.x;
    o4.y = d1*inv*w4.y + bi4.y;
    o4.z = d2*inv*w4.z + bi4.z;
    o4.w = d3*inv*w4.w + bi4.w;
    *(float4*)&outp[(size_t)row*DD + t*4] = o4;

    if (SPLITOUT) {
        uint32_t h0 = packbf2(o4.x, o4.y), h1 = packbf2(o4.z, o4.w);
        uint32_t l0 = packlo2(o4.x, o4.y, h0), l1 = packlo2(o4.z, o4.w, h1);
        size_t base2 = (size_t)row * (DD/2) + t*2;
        ((uint32_t*)ohi)[base2]     = h0;
        ((uint32_t*)ohi)[base2 + 1] = h1;
        ((uint32_t*)olo)[base2]     = l0;
        ((uint32_t*)olo)[base2 + 1] = l1;
    }
}

// ---------------- launcher ---------------------------------------------------
extern "C" void kernel_launch(void* const* d_in, const int* in_sizes, int n_in,
                              void* d_out, int out_size)
{
    int off = (in_sizes[0] == 1) ? 1 : 0;
    const float* query  = (const float*)d_in[off + 0];
    const float* key    = (const float*)d_in[off + 1];
    const float* values = (const float*)d_in[off + 2];
    const float* Wq = (const float*)d_in[off + 3];
    const float* bq = (const float*)d_in[off + 4];
    const float* Wk = (const float*)d_in[off + 5];
    const float* bk = (const float*)d_in[off + 6];
    const float* Wv = (const float*)d_in[off + 7];
    const float* bv = (const float*)d_in[off + 8];
    const float* Wo = (const float*)d_in[off + 9];
    const float* bo = (const float*)d_in[off + 10];
    const float* gammas = (const float*)d_in[off + 11];
    const float* ln1w = (const float*)d_in[off + 12];
    const float* ln1b = (const float*)d_in[off + 13];
    const float* W1 = (const float*)d_in[off + 14];
    const float* b1 = (const float*)d_in[off + 15];
    const float* W2 = (const float*)d_in[off + 16];
    const float* b2 = (const float*)d_in[off + 17];
    const float* ln2w = (const float*)d_in[off + 18];
    const float* ln2b = (const float*)d_in[off + 19];

    float *pattnout, *px, *pf;
    cudaGetSymbolAddress((void**)&pattnout, g_attnout);
    cudaGetSymbolAddress((void**)&px, g_x);
    cudaGetSymbolAddress((void**)&pf, g_f);

    __nv_bfloat16 *aqh,*aql,*akh,*akl,*avh,*avl;
    __nv_bfloat16 *wqh,*wql,*wkh,*wkl,*wvh,*wvl,*woh,*wol,*w1h,*w1l,*w2h,*w2l;
    __nv_bfloat16 *ahi,*alo,*hhi,*hlo,*qhi,*qlo,*khi,*klo,*vhi,*vlo;
    cudaGetSymbolAddress((void**)&aqh, g_aq_hi); cudaGetSymbolAddress((void**)&aql, g_aq_lo);
    cudaGetSymbolAddress((void**)&akh, g_ak_hi); cudaGetSymbolAddress((void**)&akl, g_ak_lo);
    cudaGetSymbolAddress((void**)&avh, g_av_hi); cudaGetSymbolAddress((void**)&avl, g_av_lo);
    cudaGetSymbolAddress((void**)&wqh, g_wq_hi); cudaGetSymbolAddress((void**)&wql, g_wq_lo);
    cudaGetSymbolAddress((void**)&wkh, g_wk_hi); cudaGetSymbolAddress((void**)&wkl, g_wk_lo);
    cudaGetSymbolAddress((void**)&wvh, g_wv_hi); cudaGetSymbolAddress((void**)&wvl, g_wv_lo);
    cudaGetSymbolAddress((void**)&woh, g_wo_hi); cudaGetSymbolAddress((void**)&wol, g_wo_lo);
    cudaGetSymbolAddress((void**)&w1h, g_w1_hi); cudaGetSymbolAddress((void**)&w1l, g_w1_lo);
    cudaGetSymbolAddress((void**)&w2h, g_w2_hi); cudaGetSymbolAddress((void**)&w2l, g_w2_lo);
    cudaGetSymbolAddress((void**)&ahi, g_ahi);   cudaGetSymbolAddress((void**)&alo, g_alo);
    cudaGetSymbolAddress((void**)&hhi, g_hhi);   cudaGetSymbolAddress((void**)&hlo, g_hlo);
    cudaGetSymbolAddress((void**)&qhi, g_qhi);   cudaGetSymbolAddress((void**)&qlo, g_qlo);
    cudaGetSymbolAddress((void**)&khi, g_khi);   cudaGetSymbolAddress((void**)&klo, g_klo);
    cudaGetSymbolAddress((void**)&vhi, g_vhi);   cudaGetSymbolAddress((void**)&vlo, g_vlo);

    const int M = BB * SS;   // 4096
    const int GEMM_SMEM = 2 * STAGE_B;
    cudaFuncSetAttribute(gemm_mma<false,false>, cudaFuncAttributeMaxDynamicSharedMemorySize, GEMM_SMEM);
    cudaFuncSetAttribute(gemm_mma<false,true>,  cudaFuncAttributeMaxDynamicSharedMemorySize, GEMM_SMEM);
    cudaFuncSetAttribute(gemm_mma<true,true>,   cudaFuncAttributeMaxDynamicSharedMemorySize, GEMM_SMEM);
    cudaFuncSetAttribute(attn_kernel, cudaFuncAttributeMaxDynamicSharedMemorySize, AT_SMEM);

    // -------- 1. mega split (all inputs + all weights) --------
    {
        SplitArgs sa;
        const float* srcs[9] = {query, key, values, Wq, Wk, Wv, Wo, W1, W2};
        __nv_bfloat16* his[9] = {aqh, akh, avh, wqh, wkh, wvh, woh, w1h, w2h};
        __nv_bfloat16* los[9] = {aql, akl, avl, wql, wkl, wvl, wol, w1l, w2l};
        int nblk[9] = {4096, 4096, 4096, 1024, 1024, 1024, 1024, 4096, 4096};
        int cum = 0;
        for (int i = 0; i < 9; i++) {
            sa.seg[i].src = srcs[i]; sa.seg[i].hi = his[i]; sa.seg[i].lo = los[i];
            sa.start[i] = cum; cum += nblk[i];
        }
        sa.start[9] = cum;
        multi_split_kernel<<<cum, 256>>>(sa);
    }

    // -------- 2. QKV projections (batched, one launch) --------
    {
        GemmIO q = {aqh, aql, wqh, wql, bq, nullptr, qhi, qlo};
        GemmIO k = {akh, akl, wkh, wkl, bk, nullptr, khi, klo};
        GemmIO v = {avh, avl, wvh, wvl, bv, nullptr, vhi, vlo};
        gemm_mma<false,true><<<dim3(DD/128, M/128, 3), 256, GEMM_SMEM>>>(q, k, v, M, DD, DD);
    }

    // -------- 3. attention -> concat bf16 hi/lo --------
    attn_kernel<<<dim3(SS/ROWS, HH, BB), 256, AT_SMEM>>>(qhi, qlo, khi, klo, vhi, vlo,
                                                         gammas, ahi, alo);

    // -------- 4. output projection --------
    {
        GemmIO o = {ahi, alo, woh, wol, bo, pattnout, nullptr, nullptr};
        gemm_mma<false,false><<<dim3(DD/128, M/128, 1), 256, GEMM_SMEM>>>(o, o, o, M, DD, DD);
    }

    // -------- 5. LN1 -> px + bf16 hi/lo (reuse ahi/alo) --------
    add_ln_kernel<true><<<M, 256>>>(query, pattnout, ln1w, ln1b, px, ahi, alo);

    // -------- 6. FFN1 (+ReLU) --------
    {
        GemmIO f1 = {ahi, alo, w1h, w1l, b1, nullptr, hhi, hlo};
        gemm_mma<true,true><<<dim3(DFFF/128, M/128, 1), 256, GEMM_SMEM>>>(f1, f1, f1, M, DFFF, DD);
    }

    // -------- 7. FFN2 --------
    {
        GemmIO f2 = {hhi, hlo, w2h, w2l, b2, pf, nullptr, nullptr};
        gemm_mma<false,false><<<dim3(DD/128, M/128, 1), 256, GEMM_SMEM>>>(f2, f2, f2, M, DD, DFFF);
    }

    // -------- 8. LN2 -> final output --------
    add_ln_kernel<false><<<M, 256>>>(px, pf, ln2w, ln2b, (float*)d_out, nullptr, nullptr);
}

// round 7
// speedup vs baseline: 2.3727x; 1.0592x over previous
#include <cuda_runtime.h>
#include <cuda_bf16.h>
#include <math.h>
#include <stdint.h>

// Problem constants
#define BB 4
#define SS 1024
#define DD 1024
#define HH 16
#define DKK 64
#define DFFF 4096
#define SCP 1032   // score row pitch (floats)

// ---------------- scratch (device globals) -----------------------------------
__device__ float g_attnout[BB*SS*DD];
__device__ float g_x[BB*SS*DD];
__device__ float g_f[BB*SS*DD];
__device__ __nv_bfloat16 g_aq_hi[BB*SS*DD], g_aq_lo[BB*SS*DD];
__device__ __nv_bfloat16 g_ak_hi[BB*SS*DD], g_ak_lo[BB*SS*DD];
__device__ __nv_bfloat16 g_av_hi[BB*SS*DD], g_av_lo[BB*SS*DD];
__device__ __nv_bfloat16 g_wq_hi[DD*DD], g_wq_lo[DD*DD];
__device__ __nv_bfloat16 g_wk_hi[DD*DD], g_wk_lo[DD*DD];
__device__ __nv_bfloat16 g_wv_hi[DD*DD], g_wv_lo[DD*DD];
__device__ __nv_bfloat16 g_wo_hi[DD*DD], g_wo_lo[DD*DD];
__device__ __nv_bfloat16 g_w1_hi[DFFF*DD], g_w1_lo[DFFF*DD];
__device__ __nv_bfloat16 g_w2_hi[DD*DFFF], g_w2_lo[DD*DFFF];
__device__ __nv_bfloat16 g_ahi[BB*SS*DD], g_alo[BB*SS*DD];
__device__ __nv_bfloat16 g_hhi[BB*SS*DFFF], g_hlo[BB*SS*DFFF];
__device__ __nv_bfloat16 g_qhi[BB*SS*DD], g_qlo[BB*SS*DD];
__device__ __nv_bfloat16 g_khi[BB*SS*DD], g_klo[BB*SS*DD];
__device__ __nv_bfloat16 g_vhi[BB*SS*DD], g_vlo[BB*SS*DD];

// ======================= PTX helpers ========================================
__device__ __forceinline__ uint32_t smem_u32(const void* p) {
    uint32_t a;
    asm("{ .reg .u64 t; cvta.to.shared.u64 t, %1; cvt.u32.u64 %0, t; }" : "=r"(a) : "l"(p));
    return a;
}

#define CPASYNC16(dst, src) asm volatile("cp.async.cg.shared.global [%0], [%1], 16;" :: "r"(dst), "l"(src) : "memory")
#define CPCOMMIT() asm volatile("cp.async.commit_group;" ::: "memory")
#define CPWAIT1()  asm volatile("cp.async.wait_group 1;" ::: "memory")
#define CPWAIT0()  asm volatile("cp.async.wait_group 0;" ::: "memory")

#define LDSM_X4(R, A) \
    asm volatile("ldmatrix.sync.aligned.m8n8.x4.shared.b16 {%0,%1,%2,%3}, [%4];" \
        : "=r"((R)[0]), "=r"((R)[1]), "=r"((R)[2]), "=r"((R)[3]) : "r"(A))

#define LDSM_X2T(R, A) \
    asm volatile("ldmatrix.sync.aligned.m8n8.x2.trans.shared.b16 {%0,%1}, [%2];" \
        : "=r"((R)[0]), "=r"((R)[1]) : "r"(A))

__device__ __forceinline__ void mma_bf16(float* c, const uint32_t* a, const uint32_t* b) {
    asm volatile(
        "mma.sync.aligned.m16n8k16.row.col.f32.bf16.bf16.f32 "
        "{%0,%1,%2,%3}, {%4,%5,%6,%7}, {%8,%9}, {%0,%1,%2,%3};"
        : "+f"(c[0]), "+f"(c[1]), "+f"(c[2]), "+f"(c[3])
        : "r"(a[0]), "r"(a[1]), "r"(a[2]), "r"(a[3]), "r"(b[0]), "r"(b[1]));
}

__device__ __forceinline__ uint32_t packbf2(float x, float y) {
    __nv_bfloat162 t = __floats2bfloat162_rn(x, y);
    return *reinterpret_cast<uint32_t*>(&t);
}
__device__ __forceinline__ uint32_t packlo2(float x, float y, uint32_t hi) {
    __nv_bfloat162 h = *reinterpret_cast<__nv_bfloat162*>(&hi);
    return packbf2(x - __bfloat162float(h.x), y - __bfloat162float(h.y));
}

// ================ mega split ================================================
struct SplitSeg { const float* src; __nv_bfloat16* hi; __nv_bfloat16* lo; };
struct SplitArgs { SplitSeg seg[9]; int start[10]; };

__global__ void __launch_bounds__(256) multi_split_kernel(SplitArgs a)
{
    int bx = blockIdx.x;
    int s = 0;
#pragma unroll
    for (int i = 0; i < 8; i++) if (bx >= a.start[i+1]) s = i+1;
    SplitSeg sg = a.seg[s];
    int i = (bx - a.start[s]) * 256 + threadIdx.x;
    float4 v = ((const float4*)sg.src)[i];
    uint32_t h0 = packbf2(v.x, v.y), h1 = packbf2(v.z, v.w);
    uint32_t l0 = packlo2(v.x, v.y, h0), l1 = packlo2(v.z, v.w, h1);
    ((uint32_t*)sg.hi)[i*2+0] = h0;
    ((uint32_t*)sg.hi)[i*2+1] = h1;
    ((uint32_t*)sg.lo)[i*2+0] = l0;
    ((uint32_t*)sg.lo)[i*2+1] = l1;
}

// ============ bf16x3 GEMM, tile 256x128, 512 thr, 3-stage, 1 sync/chunk =====
// stage layout: Ah[256x80] Al[256x80] Bh[128x80] Bl[128x80] = 61440 B
#define G_AL 20480
#define G_BH 40960
#define G_BL 51200
#define G_STAGE 61440
#define G_SMEM (3 * G_STAGE)   // 184320

struct GemmIO {
    const __nv_bfloat16 *Ah, *Al, *Wh, *Wl;
    const float* bias;
    float* C;
    __nv_bfloat16 *Chi, *Clo;
};

template<bool RELU, bool SPLITOUT>
__global__ void __launch_bounds__(512, 1) gemm_mma(
    GemmIO io0, GemmIO io1, GemmIO io2, int M, int N, int K)
{
    extern __shared__ __align__(128) char smem[];
    uint32_t sb = smem_u32(smem);

    GemmIO io = (blockIdx.z == 0) ? io0 : (blockIdx.z == 1) ? io1 : io2;

    int tid  = threadIdx.x;
    int lane = tid & 31;
    int wid  = tid >> 5;       // 0..15
    int wm   = wid & 3;        // M warp (64 rows)
    int wn   = wid >> 2;       // N warp (32 cols)
    int bm = blockIdx.y * 256;
    int bn = blockIdx.x * 128;

    const int nch = K >> 5;

    auto load_stage = [&](int c) {
        uint32_t st = sb + (c % 3) * G_STAGE;
        size_t kof = (size_t)c * 32;
        const __nv_bfloat16* a_h = io.Ah + (size_t)bm * K + kof;
        const __nv_bfloat16* a_l = io.Al + (size_t)bm * K + kof;
        const __nv_bfloat16* b_h = io.Wh + (size_t)bn * K + kof;
        const __nv_bfloat16* b_l = io.Wl + (size_t)bn * K + kof;
#pragma unroll
        for (int u = 0; u < 2; u++) {
            int l = tid + u * 512;         // 0..1023
            int row = l >> 2, ch = l & 3;
            CPASYNC16(st +         row*80 + ch*16, (const char*)(a_h + (size_t)row*K) + ch*16);
            CPASYNC16(st + G_AL  + row*80 + ch*16, (const char*)(a_l + (size_t)row*K) + ch*16);
        }
        {
            int row = tid >> 2, ch = tid & 3;   // 128 rows x 4
            CPASYNC16(st + G_BH + row*80 + ch*16, (const char*)(b_h + (size_t)row*K) + ch*16);
            CPASYNC16(st + G_BL + row*80 + ch*16, (const char*)(b_l + (size_t)row*K) + ch*16);
        }
        CPCOMMIT();
    };

    uint32_t aoff = ((((lane >> 3) & 1) * 8 + (lane & 7)) * 80) + (lane >> 4) * 16;
    uint32_t boff = (((lane >> 4) * 8 + (lane & 7)) * 80) + ((lane >> 3) & 1) * 16;

    float acc[4][4][4];
#pragma unroll
    for (int mt = 0; mt < 4; mt++)
#pragma unroll
        for (int n8 = 0; n8 < 4; n8++)
#pragma unroll
            for (int k = 0; k < 4; k++) acc[mt][n8][k] = 0.f;

    load_stage(0);
    load_stage(1);
    for (int c = 0; c < nch; c++) {
        if (c + 1 < nch) { CPWAIT1(); } else { CPWAIT0(); }
        __syncthreads();
        if (c + 2 < nch) load_stage(c + 2);

        uint32_t st = sb + (c % 3) * G_STAGE;
        uint32_t aH = st         + (wm * 64) * 80 + aoff;
        uint32_t aL = st + G_AL  + (wm * 64) * 80 + aoff;
        uint32_t bH = st + G_BH  + (wn * 32) * 80 + boff;
        uint32_t bL = st + G_BL  + (wn * 32) * 80 + boff;

#pragma unroll
        for (int ks = 0; ks < 2; ks++) {
            uint32_t ah[4][4], al[4][4];
#pragma unroll
            for (int mt = 0; mt < 4; mt++) {
                LDSM_X4(ah[mt], aH + mt * (16*80) + ks * 32);
                LDSM_X4(al[mt], aL + mt * (16*80) + ks * 32);
            }
#pragma unroll
            for (int g = 0; g < 2; g++) {
                uint32_t bh[4], bl[4];
                LDSM_X4(bh, bH + g * (16*80) + ks * 32);
                LDSM_X4(bl, bL + g * (16*80) + ks * 32);
#pragma unroll
                for (int mt = 0; mt < 4; mt++)
#pragma unroll
                    for (int hf = 0; hf < 2; hf++) {
                        int n8 = g * 2 + hf;
                        mma_bf16(acc[mt][n8], ah[mt], &bh[hf*2]);
                        mma_bf16(acc[mt][n8], ah[mt], &bl[hf*2]);
                        mma_bf16(acc[mt][n8], al[mt], &bh[hf*2]);
                    }
            }
        }
    }

    int r_in = lane >> 2;
    int c_in = (lane & 3) * 2;
#pragma unroll
    for (int mt = 0; mt < 4; mt++) {
        int R0 = bm + wm * 64 + mt * 16 + r_in;
        int R1 = R0 + 8;
#pragma unroll
        for (int n8 = 0; n8 < 4; n8++) {
            int col = bn + wn * 32 + n8 * 8 + c_in;
            float b0 = io.bias[col], b1 = io.bias[col + 1];
            float o00 = acc[mt][n8][0] + b0, o01 = acc[mt][n8][1] + b1;
            float o10 = acc[mt][n8][2] + b0, o11 = acc[mt][n8][3] + b1;
            if (RELU) {
                o00 = fmaxf(o00, 0.f); o01 = fmaxf(o01, 0.f);
                o10 = fmaxf(o10, 0.f); o11 = fmaxf(o11, 0.f);
            }
            if (SPLITOUT) {
                uint32_t h0 = packbf2(o00, o01), h1 = packbf2(o10, o11);
                uint32_t l0 = packlo2(o00, o01, h0), l1 = packlo2(o10, o11, h1);
                *(uint32_t*)&io.Chi[(size_t)R0 * N + col] = h0;
                *(uint32_t*)&io.Chi[(size_t)R1 * N + col] = h1;
                *(uint32_t*)&io.Clo[(size_t)R0 * N + col] = l0;
                *(uint32_t*)&io.Clo[(size_t)R1 * N + col] = l1;
            } else {
                float2 o0, o1;
                o0.x = o00; o0.y = o01; o1.x = o10; o1.y = o11;
                *(float2*)&io.C[(size_t)R0 * N + col] = o0;
                *(float2*)&io.C[(size_t)R1 * N + col] = o1;
            }
        }
    }
}

// ================= tensor-core distance-decay attention (32 rows/CTA) ========
// smem: sc[32][SCP] | QH/QL 32x144 | 2 x (KH,KL) 128x144 double buffer
#define AT_QH 132096
#define AT_QL 136704
#define AT_K  141312
#define AT_KSZ 36864   // per buffer (KH + KL)
#define AT_SMEM 215040

__global__ void __launch_bounds__(256, 1) attn_kernel(
    const __nv_bfloat16* __restrict__ qhi, const __nv_bfloat16* __restrict__ qlo,
    const __nv_bfloat16* __restrict__ khi, const __nv_bfloat16* __restrict__ klo,
    const __nv_bfloat16* __restrict__ vhi, const __nv_bfloat16* __restrict__ vlo,
    const float* __restrict__ gammas,
    __nv_bfloat16* __restrict__ ohi, __nv_bfloat16* __restrict__ olo)
{
    extern __shared__ __align__(128) char smx[];
    float* sc = (float*)smx;
    uint32_t sb = smem_u32(smx);
    const uint32_t QH = sb + AT_QH;
    const uint32_t QL = sb + AT_QL;

    int b = blockIdx.z, h = blockIdx.y, i0 = blockIdx.x * 32;
    int t = threadIdx.x, lane = t & 31, w = t >> 5;

    size_t base_q = ((size_t)b*SS + i0)*DD + h*64;
    size_t base_k = (size_t)b*SS*DD + h*64;

    // ---- load Q tile (32 rows, hi+lo)
#pragma unroll
    for (int u = 0; u < 2; u++) {
        int l = t + u * 256;
        int sel = l >> 8;
        int idx = l & 255;
        int row = idx >> 3, ch = idx & 7;
        const __nv_bfloat16* src = (sel ? qlo : qhi) + base_q + (size_t)row*DD + ch*8;
        char* dst = smx + (sel ? AT_QL : AT_QH) + row*144 + ch*16;
        *(float4*)dst = *(const float4*)src;
    }
    __syncthreads();

    uint32_t aoff = ((((lane >> 3) & 1) * 8 + (lane & 7)) * 144) + (lane >> 4) * 16;
    uint32_t boff = (((lane >> 4) * 8 + (lane & 7)) * 144) + ((lane >> 3) & 1) * 16;

    uint32_t ah[2][4][4], al[2][4][4];
#pragma unroll
    for (int mt = 0; mt < 2; mt++)
#pragma unroll
        for (int ks = 0; ks < 4; ks++) {
            LDSM_X4(ah[mt][ks], QH + mt*(16*144) + aoff + ks*32);
            LDSM_X4(al[mt][ks], QL + mt*(16*144) + aoff + ks*32);
        }

    // K tile loader (128 rows) into buffer bf
    auto loadK = [&](int jt, int bf) {
        uint32_t KH = sb + AT_K + bf * AT_KSZ;
        uint32_t KL = KH + 18432;
        int jbase = jt * 128;
#pragma unroll
        for (int u = 0; u < 4; u++) {
            int l = t + u * 256;
            int row = l >> 3, ch = l & 7;
            const char* sh = (const char*)(khi + base_k + (size_t)(jbase+row)*DD) + ch*16;
            const char* sl = (const char*)(klo + base_k + (size_t)(jbase+row)*DD) + ch*16;
            CPASYNC16(KH + row*144 + ch*16, sh);
            CPASYNC16(KL + row*144 + ch*16, sl);
        }
        CPCOMMIT();
    };

    // ---- QK^T: 8 tiles of 128 cols, double-buffered
    loadK(0, 0);
    for (int jt = 0; jt < 8; jt++) {
        CPWAIT0();
        __syncthreads();
        if (jt + 1 < 8) loadK(jt + 1, (jt + 1) & 1);

        uint32_t KH = sb + AT_K + (jt & 1) * AT_KSZ;
        uint32_t KL = KH + 18432;
        float c[2][2][4];
#pragma unroll
        for (int mt = 0; mt < 2; mt++)
#pragma unroll
            for (int g = 0; g < 2; g++)
#pragma unroll
                for (int k = 0; k < 4; k++) c[mt][g][k] = 0.f;

        uint32_t bb = (uint32_t)(w*16)*144 + boff;
#pragma unroll
        for (int ks = 0; ks < 4; ks++) {
            uint32_t bh[4], bl[4];
            LDSM_X4(bh, KH + bb + ks*32);
            LDSM_X4(bl, KL + bb + ks*32);
#pragma unroll
            for (int mt = 0; mt < 2; mt++) {
                mma_bf16(c[mt][0], ah[mt][ks], &bh[0]);
                mma_bf16(c[mt][0], ah[mt][ks], &bl[0]);
                mma_bf16(c[mt][0], al[mt][ks], &bh[0]);
                mma_bf16(c[mt][1], ah[mt][ks], &bh[2]);
                mma_bf16(c[mt][1], ah[mt][ks], &bl[2]);
                mma_bf16(c[mt][1], al[mt][ks], &bh[2]);
            }
        }
        int r = lane >> 2, cb = jt*128 + w*16 + (lane & 3)*2;
#pragma unroll
        for (int mt = 0; mt < 2; mt++) {
            int r0 = mt*16 + r;
            float2 v2;
            v2.x = c[mt][0][0]*0.125f; v2.y = c[mt][0][1]*0.125f; *(float2*)&sc[r0*SCP + cb] = v2;
            v2.x = c[mt][0][2]*0.125f; v2.y = c[mt][0][3]*0.125f; *(float2*)&sc[(r0+8)*SCP + cb] = v2;
            v2.x = c[mt][1][0]*0.125f; v2.y = c[mt][1][1]*0.125f; *(float2*)&sc[r0*SCP + cb + 8] = v2;
            v2.x = c[mt][1][2]*0.125f; v2.y = c[mt][1][3]*0.125f; *(float2*)&sc[(r0+8)*SCP + cb + 8] = v2;
        }
    }

    // V tile loader
    int jmax = i0 + 32;
    auto loadV = [&](int jbase, int rows, int bf) {
        uint32_t VH = sb + AT_K + bf * AT_KSZ;
        uint32_t VL = VH + 18432;
        int total = rows * 8;
#pragma unroll
        for (int u = 0; u < 4; u++) {
            int l = t + u * 256;
            if (l < total) {
                int row = l >> 3, ch = l & 7;
                const char* sh = (const char*)(vhi + base_k + (size_t)(jbase+row)*DD) + ch*16;
                const char* sl = (const char*)(vlo + base_k + (size_t)(jbase+row)*DD) + ch*16;
                CPASYNC16(VH + row*144 + ch*16, sh);
                CPASYNC16(VL + row*144 + ch*16, sl);
            }
        }
        CPCOMMIT();
    };

    // prefetch V tile 0 into buffer 0 (covered by row math); safe: buf0 last read at jt=6
    loadV(0, jmax < 128 ? jmax : 128, 0);
    __syncthreads();   // sc writes of jt=7 visible before row math

    // ---- per-row math: 4 rows per warp
    {
        float gamma = -log1pf(__expf(gammas[h]));
        for (int rr2 = 0; rr2 < 4; rr2++) {
            int r  = w*4 + rr2;
            int ig = i0 + r;
            float* row = sc + r*SCP;

            float s[32], p[32];
            float m = -INFINITY;
#pragma unroll
            for (int c = 0; c < 32; c++) {
                s[c] = row[c*32 + lane];
                m = fmaxf(m, s[c]);
            }
#pragma unroll
            for (int o = 16; o > 0; o >>= 1) m = fmaxf(m, __shfl_xor_sync(0xffffffffu, m, o));

            float sum1 = 0.f, summ = 0.f;
#pragma unroll
            for (int c = 0; c < 32; c++) {
                p[c] = __expf(s[c] - m);
                sum1 += p[c];
                if (c*32 + lane <= ig) summ += p[c];
            }
#pragma unroll
            for (int o = 16; o > 0; o >>= 1) {
                sum1 += __shfl_xor_sync(0xffffffffu, sum1, o);
                summ += __shfl_xor_sync(0xffffffffu, summ, o);
            }
            float inv1 = 1.f / sum1;

            float carry = 0.f, m2 = -INFINITY;
#pragma unroll
            for (int c = 0; c < 32; c++) {
                if (c*32 <= ig) {
                    int j = c*32 + lane;
                    float pm = (j <= ig) ? p[c] : 0.f;
                    float x = pm;
#pragma unroll
                    for (int o = 1; o < 32; o <<= 1) {
                        float y = __shfl_up_sync(0xffffffffu, x, o);
                        if (lane >= o) x += y;
                    }
                    float distraw = carry + x;
                    carry += __shfl_sync(0xffffffffu, x, 31);
                    float pos  = fabsf((float)(ig - j));
                    float dd   = (summ - distraw) * inv1 * pos;
                    float dist = sqrtf(fmaxf(dd, 0.f));
                    float eff  = __expf(dist * gamma);
                    eff = fminf(fmaxf(eff, 1e-5f), 1e5f);
                    float s2 = (j <= ig) ? s[c] * eff : -INFINITY;
                    s[c] = s2;
                    m2 = fmaxf(m2, s2);
                } else {
                    s[c] = -INFINITY;
                }
            }
#pragma unroll
            for (int o = 16; o > 0; o >>= 1) m2 = fmaxf(m2, __shfl_xor_sync(0xffffffffu, m2, o));

            float sum2 = 0.f;
#pragma unroll
            for (int c = 0; c < 32; c++) {
                float e = 0.f;
                if (c*32 <= ig) {
                    int j = c*32 + lane;
                    e = (j <= ig) ? __expf(s[c] - m2) : 0.f;
                }
                p[c] = e;
                sum2 += e;
            }
#pragma unroll
            for (int o = 16; o > 0; o >>= 1) sum2 += __shfl_xor_sync(0xffffffffu, sum2, o);
            float inv2 = 1.f / sum2;
#pragma unroll
            for (int c = 0; c < 32; c++) row[c*32 + lane] = p[c] * inv2;
        }
    }

    // ---- PV: warp w owns cols w*8..w*8+7; rows 0..31 (2 m-tiles)
    float acc[2][4];
#pragma unroll
    for (int mt = 0; mt < 2; mt++)
#pragma unroll
        for (int k = 0; k < 4; k++) acc[mt][k] = 0.f;

    int rr = lane >> 2, kc = (lane & 3) * 2;
    int vrow = lane & 15;
    int ntiles = (jmax + 127) >> 7;
    for (int ji = 0; ji < ntiles; ji++) {
        int jbase = ji * 128;
        int rows = jmax - jbase; if (rows > 128) rows = 128;
        CPWAIT0();
        __syncthreads();
        if (ji + 1 < ntiles) {
            int nb = jbase + 128;
            int nrows = jmax - nb; if (nrows > 128) nrows = 128;
            loadV(nb, nrows, (ji + 1) & 1);
        }
        uint32_t VH = sb + AT_K + (ji & 1) * AT_KSZ;
        uint32_t VL = VH + 18432;

        int nk = rows >> 4;
        for (int kk = 0; kk < nk; kk++) {
            int j0 = jbase + kk*16;
            uint32_t vh[2], vl[2];
            uint32_t va = (uint32_t)(kk*16 + vrow)*144 + (uint32_t)w*16;
            LDSM_X2T(vh, VH + va);
            LDSM_X2T(vl, VL + va);
#pragma unroll
            for (int mt = 0; mt < 2; mt++) {
                const float* p0 = &sc[(mt*16 + rr)*SCP + j0 + kc];
                float f00 = p0[0],        f01 = p0[1];
                float f10 = p0[8*SCP],    f11 = p0[8*SCP+1];
                float f20 = p0[8],        f21 = p0[9];
                float f30 = p0[8*SCP+8],  f31 = p0[8*SCP+9];
                uint32_t a_h[4], a_l[4];
                a_h[0] = packbf2(f00, f01); a_l[0] = packlo2(f00, f01, a_h[0]);
                a_h[1] = packbf2(f10, f11); a_l[1] = packlo2(f10, f11, a_h[1]);
                a_h[2] = packbf2(f20, f21); a_l[2] = packlo2(f20, f21, a_h[2]);
                a_h[3] = packbf2(f30, f31); a_l[3] = packlo2(f30, f31, a_h[3]);
                mma_bf16(acc[mt], a_h, vh);
                mma_bf16(acc[mt], a_h, vl);
                mma_bf16(acc[mt], a_l, vh);
            }
        }
    }

    // ---- epilogue
#pragma unroll
    for (int mt = 0; mt < 2; mt++) {
        size_t o0 = ((size_t)b*SS + i0 + mt*16 + rr)*DD + h*64 + w*8 + kc;
        size_t o1 = o0 + (size_t)8*DD;
        uint32_t h0 = packbf2(acc[mt][0], acc[mt][1]);
        uint32_t l0 = packlo2(acc[mt][0], acc[mt][1], h0);
        uint32_t h1 = packbf2(acc[mt][2], acc[mt][3]);
        uint32_t l1 = packlo2(acc[mt][2], acc[mt][3], h1);
        *(uint32_t*)&ohi[o0] = h0;
        *(uint32_t*)&olo[o0] = l0;
        *(uint32_t*)&ohi[o1] = h1;
        *(uint32_t*)&olo[o1] = l1;
    }
}

// ---------------- residual add + LayerNorm ----------------------------------
template<bool SPLITOUT>
__global__ void __launch_bounds__(256) add_ln_kernel(
    const float* __restrict__ A, const float* __restrict__ Bres,
    const float* __restrict__ w, const float* __restrict__ bias,
    float* __restrict__ outp,
    __nv_bfloat16* __restrict__ ohi, __nv_bfloat16* __restrict__ olo)
{
    __shared__ float red1[8], red2[8];
    int row = blockIdx.x;
    int t   = threadIdx.x;
    const float* pa = A    + (size_t)row*DD;
    const float* pb = Bres + (size_t)row*DD;

    float4 a4 = *(const float4*)&pa[t*4];
    float4 b4 = *(const float4*)&pb[t*4];
    float v0 = a4.x + b4.x, v1 = a4.y + b4.y, v2 = a4.z + b4.z, v3 = a4.w + b4.w;

    int lane = t & 31, wp = t >> 5;
    float s = v0 + v1 + v2 + v3;
#pragma unroll
    for (int o = 16; o > 0; o >>= 1) s += __shfl_xor_sync(0xffffffffu, s, o);
    if (lane == 0) red1[wp] = s;
    __syncthreads();
    float tot = 0.f;
#pragma unroll
    for (int i = 0; i < 8; i++) tot += red1[i];
    float mu = tot * (1.f / DD);

    float d0 = v0-mu, d1 = v1-mu, d2 = v2-mu, d3 = v3-mu;
    float q2 = d0*d0 + d1*d1 + d2*d2 + d3*d3;
#pragma unroll
    for (int o = 16; o > 0; o >>= 1) q2 += __shfl_xor_sync(0xffffffffu, q2, o);
    if (lane == 0) red2[wp] = q2;
    __syncthreads();
    float tv = 0.f;
#pragma unroll
    for (int i = 0; i < 8; i++) tv += red2[i];
    float inv = rsqrtf(tv * (1.f / DD) + 1e-5f);

    float4 w4  = *(const float4*)&w[t*4];
    float4 bi4 = *(const float4*)&bias[t*4];
    float4 o4;
    o4.x = d0*inv*w4.x + bi4.x;
    o4.y = d1*inv*w4.y + bi4.y;
    o4.z = d2*inv*w4.z + bi4.z;
    o4.w = d3*inv*w4.w + bi4.w;
    *(float4*)&outp[(size_t)row*DD + t*4] = o4;

    if (SPLITOUT) {
        uint32_t h0 = packbf2(o4.x, o4.y), h1 = packbf2(o4.z, o4.w);
        uint32_t l0 = packlo2(o4.x, o4.y, h0), l1 = packlo2(o4.z, o4.w, h1);
        size_t base2 = (size_t)row * (DD/2) + t*2;
        ((uint32_t*)ohi)[base2]     = h0;
        ((uint32_t*)ohi)[base2 + 1] = h1;
        ((uint32_t*)olo)[base2]     = l0;
        ((uint32_t*)olo)[base2 + 1] = l1;
    }
}

// ---------------- launcher ---------------------------------------------------
extern "C" void kernel_launch(void* const* d_in, const int* in_sizes, int n_in,
                              void* d_out, int out_size)
{
    int off = (in_sizes[0] == 1) ? 1 : 0;
    const float* query  = (const float*)d_in[off + 0];
    const float* key    = (const float*)d_in[off + 1];
    const float* values = (const float*)d_in[off + 2];
    const float* Wq = (const float*)d_in[off + 3];
    const float* bq = (const float*)d_in[off + 4];
    const float* Wk = (const float*)d_in[off + 5];
    const float* bk = (const float*)d_in[off + 6];
    const float* Wv = (const float*)d_in[off + 7];
    const float* bv = (const float*)d_in[off + 8];
    const float* Wo = (const float*)d_in[off + 9];
    const float* bo = (const float*)d_in[off + 10];
    const float* gammas = (const float*)d_in[off + 11];
    const float* ln1w = (const float*)d_in[off + 12];
    const float* ln1b = (const float*)d_in[off + 13];
    const float* W1 = (const float*)d_in[off + 14];
    const float* b1 = (const float*)d_in[off + 15];
    const float* W2 = (const float*)d_in[off + 16];
    const float* b2 = (const float*)d_in[off + 17];
    const float* ln2w = (const float*)d_in[off + 18];
    const float* ln2b = (const float*)d_in[off + 19];

    float *pattnout, *px, *pf;
    cudaGetSymbolAddress((void**)&pattnout, g_attnout);
    cudaGetSymbolAddress((void**)&px, g_x);
    cudaGetSymbolAddress((void**)&pf, g_f);

    __nv_bfloat16 *aqh,*aql,*akh,*akl,*avh,*avl;
    __nv_bfloat16 *wqh,*wql,*wkh,*wkl,*wvh,*wvl,*woh,*wol,*w1h,*w1l,*w2h,*w2l;
    __nv_bfloat16 *ahi,*alo,*hhi,*hlo,*qhi,*qlo,*khi,*klo,*vhi,*vlo;
    cudaGetSymbolAddress((void**)&aqh, g_aq_hi); cudaGetSymbolAddress((void**)&aql, g_aq_lo);
    cudaGetSymbolAddress((void**)&akh, g_ak_hi); cudaGetSymbolAddress((void**)&akl, g_ak_lo);
    cudaGetSymbolAddress((void**)&avh, g_av_hi); cudaGetSymbolAddress((void**)&avl, g_av_lo);
    cudaGetSymbolAddress((void**)&wqh, g_wq_hi); cudaGetSymbolAddress((void**)&wql, g_wq_lo);
    cudaGetSymbolAddress((void**)&wkh, g_wk_hi); cudaGetSymbolAddress((void**)&wkl, g_wk_lo);
    cudaGetSymbolAddress((void**)&wvh, g_wv_hi); cudaGetSymbolAddress((void**)&wvl, g_wv_lo);
    cudaGetSymbolAddress((void**)&woh, g_wo_hi); cudaGetSymbolAddress((void**)&wol, g_wo_lo);
    cudaGetSymbolAddress((void**)&w1h, g_w1_hi); cudaGetSymbolAddress((void**)&w1l, g_w1_lo);
    cudaGetSymbolAddress((void**)&w2h, g_w2_hi); cudaGetSymbolAddress((void**)&w2l, g_w2_lo);
    cudaGetSymbolAddress((void**)&ahi, g_ahi);   cudaGetSymbolAddress((void**)&alo, g_alo);
    cudaGetSymbolAddress((void**)&hhi, g_hhi);   cudaGetSymbolAddress((void**)&hlo, g_hlo);
    cudaGetSymbolAddress((void**)&qhi, g_qhi);   cudaGetSymbolAddress((void**)&qlo, g_qlo);
    cudaGetSymbolAddress((void**)&khi, g_khi);   cudaGetSymbolAddress((void**)&klo, g_klo);
    cudaGetSymbolAddress((void**)&vhi, g_vhi);   cudaGetSymbolAddress((void**)&vlo, g_vlo);

    const int M = BB * SS;   // 4096
    cudaFuncSetAttribute(gemm_mma<false,false>, cudaFuncAttributeMaxDynamicSharedMemorySize, G_SMEM);
    cudaFuncSetAttribute(gemm_mma<false,true>,  cudaFuncAttributeMaxDynamicSharedMemorySize, G_SMEM);
    cudaFuncSetAttribute(gemm_mma<true,true>,   cudaFuncAttributeMaxDynamicSharedMemorySize, G_SMEM);
    cudaFuncSetAttribute(attn_kernel, cudaFuncAttributeMaxDynamicSharedMemorySize, AT_SMEM);

    // -------- 1. mega split --------
    {
        SplitArgs sa;
        const float* srcs[9] = {query, key, values, Wq, Wk, Wv, Wo, W1, W2};
        __nv_bfloat16* his[9] = {aqh, akh, avh, wqh, wkh, wvh, woh, w1h, w2h};
        __nv_bfloat16* los[9] = {aql, akl, avl, wql, wkl, wvl, wol, w1l, w2l};
        int nblk[9] = {4096, 4096, 4096, 1024, 1024, 1024, 1024, 4096, 4096};
        int cum = 0;
        for (int i = 0; i < 9; i++) {
            sa.seg[i].src = srcs[i]; sa.seg[i].hi = his[i]; sa.seg[i].lo = los[i];
            sa.start[i] = cum; cum += nblk[i];
        }
        sa.start[9] = cum;
        multi_split_kernel<<<cum, 256>>>(sa);
    }

    // -------- 2. QKV projections (batched) --------
    {
        GemmIO q = {aqh, aql, wqh, wql, bq, nullptr, qhi, qlo};
        GemmIO k = {akh, akl, wkh, wkl, bk, nullptr, khi, klo};
        GemmIO v = {avh, avl, wvh, wvl, bv, nullptr, vhi, vlo};
        gemm_mma<false,true><<<dim3(DD/128, M/256, 3), 512, G_SMEM>>>(q, k, v, M, DD, DD);
    }

    // -------- 3. attention --------
    attn_kernel<<<dim3(SS/32, HH, BB), 256, AT_SMEM>>>(qhi, qlo, khi, klo, vhi, vlo,
                                                       gammas, ahi, alo);

    // -------- 4. output projection --------
    {
        GemmIO o = {ahi, alo, woh, wol, bo, pattnout, nullptr, nullptr};
        gemm_mma<false,false><<<dim3(DD/128, M/256, 1), 512, G_SMEM>>>(o, o, o, M, DD, DD);
    }

    // -------- 5. LN1 --------
    add_ln_kernel<true><<<M, 256>>>(query, pattnout, ln1w, ln1b, px, ahi, alo);

    // -------- 6. FFN1 (+ReLU) --------
    {
        GemmIO f1 = {ahi, alo, w1h, w1l, b1, nullptr, hhi, hlo};
        gemm_mma<true,true><<<dim3(DFFF/128, M/256, 1), 512, G_SMEM>>>(f1, f1, f1, M, DFFF, DD);
    }

    // -------- 7. FFN2 --------
    {
        GemmIO f2 = {hhi, hlo, w2h, w2l, b2, pf, nullptr, nullptr};
        gemm_mma<false,false><<<dim3(DD/128, M/256, 1), 512, G_SMEM>>>(f2, f2, f2, M, DD, DFFF);
    }

    // -------- 8. LN2 --------
    add_ln_kernel<false><<<M, 256>>>(px, pf, ln2w, ln2b, (float*)d_out, nullptr, nullptr);
}

// round 8
// speedup vs baseline: 2.8553x; 1.2034x over previous
#include <cuda_runtime.h>
#include <cuda_fp16.h>
#include <math.h>
#include <stdint.h>

// Problem constants
#define BB 4
#define SS 1024
#define DD 1024
#define HH 16
#define DKK 64
#define DFFF 4096
#define SCP 1032   // score row pitch (floats)

// ---------------- scratch (device globals) -----------------------------------
__device__ float g_attnout[BB*SS*DD];
__device__ float g_x[BB*SS*DD];
__device__ float g_f[BB*SS*DD];
// activations: fp16 hi/lo
__device__ __half g_aq_hi[BB*SS*DD], g_aq_lo[BB*SS*DD];
__device__ __half g_ak_hi[BB*SS*DD], g_ak_lo[BB*SS*DD];
__device__ __half g_av_hi[BB*SS*DD], g_av_lo[BB*SS*DD];
// weights: single fp16
__device__ __half g_wq_h[DD*DD];
__device__ __half g_wk_h[DD*DD];
__device__ __half g_wv_h[DD*DD];
__device__ __half g_wo_h[DD*DD];
__device__ __half g_w1_h[DFFF*DD];
__device__ __half g_w2_h[DD*DFFF];
// intermediates (activations hi/lo)
__device__ __half g_ahi[BB*SS*DD], g_alo[BB*SS*DD];       // concat / LN1 out
__device__ __half g_hhi[BB*SS*DFFF], g_hlo[BB*SS*DFFF];   // FFN1 out
__device__ __half g_qhi[BB*SS*DD], g_qlo[BB*SS*DD];
__device__ __half g_khi[BB*SS*DD], g_klo[BB*SS*DD];
__device__ __half g_vhi[BB*SS*DD], g_vlo[BB*SS*DD];

// ======================= PTX helpers ========================================
__device__ __forceinline__ uint32_t smem_u32(const void* p) {
    uint32_t a;
    asm("{ .reg .u64 t; cvta.to.shared.u64 t, %1; cvt.u32.u64 %0, t; }" : "=r"(a) : "l"(p));
    return a;
}

#define CPASYNC16(dst, src) asm volatile("cp.async.cg.shared.global [%0], [%1], 16;" :: "r"(dst), "l"(src) : "memory")
#define CPCOMMIT() asm volatile("cp.async.commit_group;" ::: "memory")
#define CPWAIT2()  asm volatile("cp.async.wait_group 2;" ::: "memory")
#define CPWAIT1()  asm volatile("cp.async.wait_group 1;" ::: "memory")
#define CPWAIT0()  asm volatile("cp.async.wait_group 0;" ::: "memory")

#define LDSM_X4(R, A) \
    asm volatile("ldmatrix.sync.aligned.m8n8.x4.shared.b16 {%0,%1,%2,%3}, [%4];" \
        : "=r"((R)[0]), "=r"((R)[1]), "=r"((R)[2]), "=r"((R)[3]) : "r"(A))

#define LDSM_X2T(R, A) \
    asm volatile("ldmatrix.sync.aligned.m8n8.x2.trans.shared.b16 {%0,%1}, [%2];" \
        : "=r"((R)[0]), "=r"((R)[1]) : "r"(A))

__device__ __forceinline__ void mma_f16(float* c, const uint32_t* a, const uint32_t* b) {
    asm volatile(
        "mma.sync.aligned.m16n8k16.row.col.f32.f16.f16.f32 "
        "{%0,%1,%2,%3}, {%4,%5,%6,%7}, {%8,%9}, {%0,%1,%2,%3};"
        : "+f"(c[0]), "+f"(c[1]), "+f"(c[2]), "+f"(c[3])
        : "r"(a[0]), "r"(a[1]), "r"(a[2]), "r"(a[3]), "r"(b[0]), "r"(b[1]));
}

__device__ __forceinline__ uint32_t packh2(float x, float y) {
    __half2 t = __floats2half2_rn(x, y);
    return *reinterpret_cast<uint32_t*>(&t);
}
__device__ __forceinline__ uint32_t packloh2(float x, float y, uint32_t hi) {
    __half2 h = *reinterpret_cast<__half2*>(&hi);
    return packh2(x - __half2float(h.x), y - __half2float(h.y));
}

// ================ mega split: fp32 -> fp16 (hi/lo for acts, single for W) ====
struct SplitSeg { const float* src; __half* hi; __half* lo; };
struct SplitArgs { SplitSeg seg[9]; int start[10]; };

__global__ void __launch_bounds__(256) multi_split_kernel(SplitArgs a)
{
    int bx = blockIdx.x;
    int s = 0;
#pragma unroll
    for (int i = 0; i < 8; i++) if (bx >= a.start[i+1]) s = i+1;
    SplitSeg sg = a.seg[s];
    int i = (bx - a.start[s]) * 256 + threadIdx.x;
    float4 v = ((const float4*)sg.src)[i];
    uint32_t h0 = packh2(v.x, v.y), h1 = packh2(v.z, v.w);
    ((uint32_t*)sg.hi)[i*2+0] = h0;
    ((uint32_t*)sg.hi)[i*2+1] = h1;
    if (sg.lo) {
        uint32_t l0 = packloh2(v.x, v.y, h0), l1 = packloh2(v.z, v.w, h1);
        ((uint32_t*)sg.lo)[i*2+0] = l0;
        ((uint32_t*)sg.lo)[i*2+1] = l1;
    }
}

// ====== fp16x2 GEMM: C = (Ah+Al) @ W^T + bias, tile 256x128, 4 stages =======
// stage: Ah[256x80] Al[256x80] Bh[128x80] = 51200 B
#define G_AL 20480
#define G_BH 40960
#define G_STAGE 51200
#define G_SMEM (4 * G_STAGE)   // 204800

struct GemmIO {
    const __half *Ah, *Al, *Wh;
    const float* bias;
    float* C;
    __half *Chi, *Clo;
};

template<bool RELU, bool SPLITOUT>
__global__ void __launch_bounds__(512, 1) gemm_mma(
    GemmIO io0, GemmIO io1, GemmIO io2, int M, int N, int K)
{
    extern __shared__ __align__(128) char smem[];
    uint32_t sb = smem_u32(smem);

    GemmIO io = (blockIdx.z == 0) ? io0 : (blockIdx.z == 1) ? io1 : io2;

    int tid  = threadIdx.x;
    int lane = tid & 31;
    int wid  = tid >> 5;       // 0..15
    int wm   = wid & 3;        // M warp (64 rows)
    int wn   = wid >> 2;       // N warp (32 cols)
    int bm = blockIdx.y * 256;
    int bn = blockIdx.x * 128;

    const int nch = K >> 5;

    auto load_stage = [&](int c) {
        uint32_t st = sb + (c & 3) * G_STAGE;
        size_t kof = (size_t)c * 32;
        const __half* a_h = io.Ah + (size_t)bm * K + kof;
        const __half* a_l = io.Al + (size_t)bm * K + kof;
        const __half* b_h = io.Wh + (size_t)bn * K + kof;
#pragma unroll
        for (int u = 0; u < 2; u++) {
            int l = tid + u * 512;         // 0..1023
            int row = l >> 2, ch = l & 3;
            CPASYNC16(st +        row*80 + ch*16, (const char*)(a_h + (size_t)row*K) + ch*16);
            CPASYNC16(st + G_AL + row*80 + ch*16, (const char*)(a_l + (size_t)row*K) + ch*16);
        }
        {
            int row = tid >> 2, ch = tid & 3;   // 128 rows x 4
            CPASYNC16(st + G_BH + row*80 + ch*16, (const char*)(b_h + (size_t)row*K) + ch*16);
        }
        CPCOMMIT();
    };

    uint32_t aoff = ((((lane >> 3) & 1) * 8 + (lane & 7)) * 80) + (lane >> 4) * 16;
    uint32_t boff = (((lane >> 4) * 8 + (lane & 7)) * 80) + ((lane >> 3) & 1) * 16;

    float acc[4][4][4];
#pragma unroll
    for (int mt = 0; mt < 4; mt++)
#pragma unroll
        for (int n8 = 0; n8 < 4; n8++)
#pragma unroll
            for (int k = 0; k < 4; k++) acc[mt][n8][k] = 0.f;

    load_stage(0);
    load_stage(1);
    load_stage(2);
    for (int c = 0; c < nch; c++) {
        if (c + 2 < nch)      { CPWAIT2(); }
        else if (c + 1 < nch) { CPWAIT1(); }
        else                  { CPWAIT0(); }
        __syncthreads();
        if (c + 3 < nch) load_stage(c + 3);

        uint32_t st = sb + (c & 3) * G_STAGE;
        uint32_t aH = st        + (wm * 64) * 80 + aoff;
        uint32_t aL = st + G_AL + (wm * 64) * 80 + aoff;
        uint32_t bH = st + G_BH + (wn * 32) * 80 + boff;

#pragma unroll
        for (int ks = 0; ks < 2; ks++) {
            uint32_t ah[4][4], al[4][4];
#pragma unroll
            for (int mt = 0; mt < 4; mt++) {
                LDSM_X4(ah[mt], aH + mt * (16*80) + ks * 32);
                LDSM_X4(al[mt], aL + mt * (16*80) + ks * 32);
            }
#pragma unroll
            for (int g = 0; g < 2; g++) {
                uint32_t bh[4];
                LDSM_X4(bh, bH + g * (16*80) + ks * 32);
#pragma unroll
                for (int mt = 0; mt < 4; mt++)
#pragma unroll
                    for (int hf = 0; hf < 2; hf++) {
                        int n8 = g * 2 + hf;
                        mma_f16(acc[mt][n8], ah[mt], &bh[hf*2]);
                        mma_f16(acc[mt][n8], al[mt], &bh[hf*2]);
                    }
            }
        }
    }

    int r_in = lane >> 2;
    int c_in = (lane & 3) * 2;
#pragma unroll
    for (int mt = 0; mt < 4; mt++) {
        int R0 = bm + wm * 64 + mt * 16 + r_in;
        int R1 = R0 + 8;
#pragma unroll
        for (int n8 = 0; n8 < 4; n8++) {
            int col = bn + wn * 32 + n8 * 8 + c_in;
            float b0 = io.bias[col], b1 = io.bias[col + 1];
            float o00 = acc[mt][n8][0] + b0, o01 = acc[mt][n8][1] + b1;
            float o10 = acc[mt][n8][2] + b0, o11 = acc[mt][n8][3] + b1;
            if (RELU) {
                o00 = fmaxf(o00, 0.f); o01 = fmaxf(o01, 0.f);
                o10 = fmaxf(o10, 0.f); o11 = fmaxf(o11, 0.f);
            }
            if (SPLITOUT) {
                uint32_t h0 = packh2(o00, o01), h1 = packh2(o10, o11);
                uint32_t l0 = packloh2(o00, o01, h0), l1 = packloh2(o10, o11, h1);
                *(uint32_t*)&io.Chi[(size_t)R0 * N + col] = h0;
                *(uint32_t*)&io.Chi[(size_t)R1 * N + col] = h1;
                *(uint32_t*)&io.Clo[(size_t)R0 * N + col] = l0;
                *(uint32_t*)&io.Clo[(size_t)R1 * N + col] = l1;
            } else {
                float2 o0, o1;
                o0.x = o00; o0.y = o01; o1.x = o10; o1.y = o11;
                *(float2*)&io.C[(size_t)R0 * N + col] = o0;
                *(float2*)&io.C[(size_t)R1 * N + col] = o1;
            }
        }
    }
}

// ================= tensor-core distance-decay attention (32 rows/CTA) ========
// QK: fp16 3-term (hi/lo x hi/lo). PV: probs hi/lo x V single (2-term).
#define AT_QH 132096
#define AT_QL 136704
#define AT_K  141312
#define AT_KSZ 36864   // per buffer (KH + KL); V uses first half only
#define AT_SMEM 215040

__global__ void __launch_bounds__(256, 1) attn_kernel(
    const __half* __restrict__ qhi, const __half* __restrict__ qlo,
    const __half* __restrict__ khi, const __half* __restrict__ klo,
    const __half* __restrict__ vhi,
    const float* __restrict__ gammas,
    __half* __restrict__ ohi, __half* __restrict__ olo)
{
    extern __shared__ __align__(128) char smx[];
    float* sc = (float*)smx;
    uint32_t sb = smem_u32(smx);
    const uint32_t QH = sb + AT_QH;
    const uint32_t QL = sb + AT_QL;

    int b = blockIdx.z, h = blockIdx.y, i0 = blockIdx.x * 32;
    int t = threadIdx.x, lane = t & 31, w = t >> 5;

    size_t base_q = ((size_t)b*SS + i0)*DD + h*64;
    size_t base_k = (size_t)b*SS*DD + h*64;

    // ---- load Q tile (32 rows, hi+lo)
#pragma unroll
    for (int u = 0; u < 2; u++) {
        int l = t + u * 256;
        int sel = l >> 8;
        int idx = l & 255;
        int row = idx >> 3, ch = idx & 7;
        const __half* src = (sel ? qlo : qhi) + base_q + (size_t)row*DD + ch*8;
        char* dst = smx + (sel ? AT_QL : AT_QH) + row*144 + ch*16;
        *(float4*)dst = *(const float4*)src;
    }
    __syncthreads();

    uint32_t aoff = ((((lane >> 3) & 1) * 8 + (lane & 7)) * 144) + (lane >> 4) * 16;
    uint32_t boff = (((lane >> 4) * 8 + (lane & 7)) * 144) + ((lane >> 3) & 1) * 16;

    uint32_t ah[2][4][4], al[2][4][4];
#pragma unroll
    for (int mt = 0; mt < 2; mt++)
#pragma unroll
        for (int ks = 0; ks < 4; ks++) {
            LDSM_X4(ah[mt][ks], QH + mt*(16*144) + aoff + ks*32);
            LDSM_X4(al[mt][ks], QL + mt*(16*144) + aoff + ks*32);
        }

    // K tile loader (128 rows, hi+lo) into buffer bf
    auto loadK = [&](int jt, int bf) {
        uint32_t KH = sb + AT_K + bf * AT_KSZ;
        uint32_t KL = KH + 18432;
        int jbase = jt * 128;
#pragma unroll
        for (int u = 0; u < 4; u++) {
            int l = t + u * 256;
            int row = l >> 3, ch = l & 7;
            const char* sh = (const char*)(khi + base_k + (size_t)(jbase+row)*DD) + ch*16;
            const char* sl = (const char*)(klo + base_k + (size_t)(jbase+row)*DD) + ch*16;
            CPASYNC16(KH + row*144 + ch*16, sh);
            CPASYNC16(KL + row*144 + ch*16, sl);
        }
        CPCOMMIT();
    };

    // ---- QK^T: 8 tiles of 128 cols, double-buffered (3-term fp16)
    loadK(0, 0);
    for (int jt = 0; jt < 8; jt++) {
        CPWAIT0();
        __syncthreads();
        if (jt + 1 < 8) loadK(jt + 1, (jt + 1) & 1);

        uint32_t KH = sb + AT_K + (jt & 1) * AT_KSZ;
        uint32_t KL = KH + 18432;
        float c[2][2][4];
#pragma unroll
        for (int mt = 0; mt < 2; mt++)
#pragma unroll
            for (int g = 0; g < 2; g++)
#pragma unroll
                for (int k = 0; k < 4; k++) c[mt][g][k] = 0.f;

        uint32_t bb = (uint32_t)(w*16)*144 + boff;
#pragma unroll
        for (int ks = 0; ks < 4; ks++) {
            uint32_t bh[4], bl[4];
            LDSM_X4(bh, KH + bb + ks*32);
            LDSM_X4(bl, KL + bb + ks*32);
#pragma unroll
            for (int mt = 0; mt < 2; mt++) {
                mma_f16(c[mt][0], ah[mt][ks], &bh[0]);
                mma_f16(c[mt][0], ah[mt][ks], &bl[0]);
                mma_f16(c[mt][0], al[mt][ks], &bh[0]);
                mma_f16(c[mt][1], ah[mt][ks], &bh[2]);
                mma_f16(c[mt][1], ah[mt][ks], &bl[2]);
                mma_f16(c[mt][1], al[mt][ks], &bh[2]);
            }
        }
        int r = lane >> 2, cb = jt*128 + w*16 + (lane & 3)*2;
#pragma unroll
        for (int mt = 0; mt < 2; mt++) {
            int r0 = mt*16 + r;
            float2 v2;
            v2.x = c[mt][0][0]*0.125f; v2.y = c[mt][0][1]*0.125f; *(float2*)&sc[r0*SCP + cb] = v2;
            v2.x = c[mt][0][2]*0.125f; v2.y = c[mt][0][3]*0.125f; *(float2*)&sc[(r0+8)*SCP + cb] = v2;
            v2.x = c[mt][1][0]*0.125f; v2.y = c[mt][1][1]*0.125f; *(float2*)&sc[r0*SCP + cb + 8] = v2;
            v2.x = c[mt][1][2]*0.125f; v2.y = c[mt][1][3]*0.125f; *(float2*)&sc[(r0+8)*SCP + cb + 8] = v2;
        }
    }

    // V tile loader (single fp16)
    int jmax = i0 + 32;
    auto loadV = [&](int jbase, int rows, int bf) {
        uint32_t VH = sb + AT_K + bf * AT_KSZ;
        int total = rows * 8;
#pragma unroll
        for (int u = 0; u < 4; u++) {
            int l = t + u * 256;
            if (l < total) {
                int row = l >> 3, ch = l & 7;
                const char* sh = (const char*)(vhi + base_k + (size_t)(jbase+row)*DD) + ch*16;
                CPASYNC16(VH + row*144 + ch*16, sh);
            }
        }
        CPCOMMIT();
    };

    // prefetch V tile 0 into buffer 0 (hidden under row math)
    loadV(0, jmax < 128 ? jmax : 128, 0);
    __syncthreads();   // sc writes of jt=7 visible before row math

    // ---- per-row math: 4 rows per warp
    {
        float gamma = -log1pf(__expf(gammas[h]));
        for (int rr2 = 0; rr2 < 4; rr2++) {
            int r  = w*4 + rr2;
            int ig = i0 + r;
            float* row = sc + r*SCP;

            float s[32], p[32];
            float m = -INFINITY;
#pragma unroll
            for (int c = 0; c < 32; c++) {
                s[c] = row[c*32 + lane];
                m = fmaxf(m, s[c]);
            }
#pragma unroll
            for (int o = 16; o > 0; o >>= 1) m = fmaxf(m, __shfl_xor_sync(0xffffffffu, m, o));

            float sum1 = 0.f, summ = 0.f;
#pragma unroll
            for (int c = 0; c < 32; c++) {
                p[c] = __expf(s[c] - m);
                sum1 += p[c];
                if (c*32 + lane <= ig) summ += p[c];
            }
#pragma unroll
            for (int o = 16; o > 0; o >>= 1) {
                sum1 += __shfl_xor_sync(0xffffffffu, sum1, o);
                summ += __shfl_xor_sync(0xffffffffu, summ, o);
            }
            float inv1 = 1.f / sum1;

            float carry = 0.f, m2 = -INFINITY;
#pragma unroll
            for (int c = 0; c < 32; c++) {
                if (c*32 <= ig) {
                    int j = c*32 + lane;
                    float pm = (j <= ig) ? p[c] : 0.f;
                    float x = pm;
#pragma unroll
                    for (int o = 1; o < 32; o <<= 1) {
                        float y = __shfl_up_sync(0xffffffffu, x, o);
                        if (lane >= o) x += y;
                    }
                    float distraw = carry + x;
                    carry += __shfl_sync(0xffffffffu, x, 31);
                    float pos  = fabsf((float)(ig - j));
                    float dd   = (summ - distraw) * inv1 * pos;
                    float dist = sqrtf(fmaxf(dd, 0.f));
                    float eff  = __expf(dist * gamma);
                    eff = fminf(fmaxf(eff, 1e-5f), 1e5f);
                    float s2 = (j <= ig) ? s[c] * eff : -INFINITY;
                    s[c] = s2;
                    m2 = fmaxf(m2, s2);
                } else {
                    s[c] = -INFINITY;
                }
            }
#pragma unroll
            for (int o = 16; o > 0; o >>= 1) m2 = fmaxf(m2, __shfl_xor_sync(0xffffffffu, m2, o));

            float sum2 = 0.f;
#pragma unroll
            for (int c = 0; c < 32; c++) {
                float e = 0.f;
                if (c*32 <= ig) {
                    int j = c*32 + lane;
                    e = (j <= ig) ? __expf(s[c] - m2) : 0.f;
                }
                p[c] = e;
                sum2 += e;
            }
#pragma unroll
            for (int o = 16; o > 0; o >>= 1) sum2 += __shfl_xor_sync(0xffffffffu, sum2, o);
            float inv2 = 1.f / sum2;
#pragma unroll
            for (int c = 0; c < 32; c++) row[c*32 + lane] = p[c] * inv2;
        }
    }

    // ---- PV: warp w owns cols w*8..w*8+7; 2-term (probs hi/lo x V)
    float acc[2][4];
#pragma unroll
    for (int mt = 0; mt < 2; mt++)
#pragma unroll
        for (int k = 0; k < 4; k++) acc[mt][k] = 0.f;

    int rr = lane >> 2, kc = (lane & 3) * 2;
    int vrow = lane & 15;
    int ntiles = (jmax + 127) >> 7;
    for (int ji = 0; ji < ntiles; ji++) {
        int jbase = ji * 128;
        int rows = jmax - jbase; if (rows > 128) rows = 128;
        CPWAIT0();
        __syncthreads();
        if (ji + 1 < ntiles) {
            int nb = jbase + 128;
            int nrows = jmax - nb; if (nrows > 128) nrows = 128;
            loadV(nb, nrows, (ji + 1) & 1);
        }
        uint32_t VH = sb + AT_K + (ji & 1) * AT_KSZ;

        int nk = rows >> 4;
        for (int kk = 0; kk < nk; kk++) {
            int j0 = jbase + kk*16;
            uint32_t vh[2];
            uint32_t va = (uint32_t)(kk*16 + vrow)*144 + (uint32_t)w*16;
            LDSM_X2T(vh, VH + va);
#pragma unroll
            for (int mt = 0; mt < 2; mt++) {
                const float* p0 = &sc[(mt*16 + rr)*SCP + j0 + kc];
                float f00 = p0[0],        f01 = p0[1];
                float f10 = p0[8*SCP],    f11 = p0[8*SCP+1];
                float f20 = p0[8],        f21 = p0[9];
                float f30 = p0[8*SCP+8],  f31 = p0[8*SCP+9];
                uint32_t a_h[4], a_l[4];
                a_h[0] = packh2(f00, f01); a_l[0] = packloh2(f00, f01, a_h[0]);
                a_h[1] = packh2(f10, f11); a_l[1] = packloh2(f10, f11, a_h[1]);
                a_h[2] = packh2(f20, f21); a_l[2] = packloh2(f20, f21, a_h[2]);
                a_h[3] = packh2(f30, f31); a_l[3] = packloh2(f30, f31, a_h[3]);
                mma_f16(acc[mt], a_h, vh);
                mma_f16(acc[mt], a_l, vh);
            }
        }
    }

    // ---- epilogue -> concat fp16 hi/lo
#pragma unroll
    for (int mt = 0; mt < 2; mt++) {
        size_t o0 = ((size_t)b*SS + i0 + mt*16 + rr)*DD + h*64 + w*8 + kc;
        size_t o1 = o0 + (size_t)8*DD;
        uint32_t h0 = packh2(acc[mt][0], acc[mt][1]);
        uint32_t l0 = packloh2(acc[mt][0], acc[mt][1], h0);
        uint32_t h1 = packh2(acc[mt][2], acc[mt][3]);
        uint32_t l1 = packloh2(acc[mt][2], acc[mt][3], h1);
        *(uint32_t*)&ohi[o0] = h0;
        *(uint32_t*)&olo[o0] = l0;
        *(uint32_t*)&ohi[o1] = h1;
        *(uint32_t*)&olo[o1] = l1;
    }
}

// ---------------- residual add + LayerNorm ----------------------------------
template<bool SPLITOUT>
__global__ void __launch_bounds__(256) add_ln_kernel(
    const float* __restrict__ A, const float* __restrict__ Bres,
    const float* __restrict__ w, const float* __restrict__ bias,
    float* __restrict__ outp,
    __half* __restrict__ ohi, __half* __restrict__ olo)
{
    __shared__ float red1[8], red2[8];
    int row = blockIdx.x;
    int t   = threadIdx.x;
    const float* pa = A    + (size_t)row*DD;
    const float* pb = Bres + (size_t)row*DD;

    float4 a4 = *(const float4*)&pa[t*4];
    float4 b4 = *(const float4*)&pb[t*4];
    float v0 = a4.x + b4.x, v1 = a4.y + b4.y, v2 = a4.z + b4.z, v3 = a4.w + b4.w;

    int lane = t & 31, wp = t >> 5;
    float s = v0 + v1 + v2 + v3;
#pragma unroll
    for (int o = 16; o > 0; o >>= 1) s += __shfl_xor_sync(0xffffffffu, s, o);
    if (lane == 0) red1[wp] = s;
    __syncthreads();
    float tot = 0.f;
#pragma unroll
    for (int i = 0; i < 8; i++) tot += red1[i];
    float mu = tot * (1.f / DD);

    float d0 = v0-mu, d1 = v1-mu, d2 = v2-mu, d3 = v3-mu;
    float q2 = d0*d0 + d1*d1 + d2*d2 + d3*d3;
#pragma unroll
    for (int o = 16; o > 0; o >>= 1) q2 += __shfl_xor_sync(0xffffffffu, q2, o);
    if (lane == 0) red2[wp] = q2;
    __syncthreads();
    float tv = 0.f;
#pragma unroll
    for (int i = 0; i < 8; i++) tv += red2[i];
    float inv = rsqrtf(tv * (1.f / DD) + 1e-5f);

    float4 w4  = *(const float4*)&w[t*4];
    float4 bi4 = *(const float4*)&bias[t*4];
    float4 o4;
    o4.x = d0*inv*w4.x + bi4.x;
    o4.y = d1*inv*w4.y + bi4.y;
    o4.z = d2*inv*w4.z + bi4.z;
    o4.w = d3*inv*w4.w + bi4.w;
    *(float4*)&outp[(size_t)row*DD + t*4] = o4;

    if (SPLITOUT) {
        uint32_t h0 = packh2(o4.x, o4.y), h1 = packh2(o4.z, o4.w);
        uint32_t l0 = packloh2(o4.x, o4.y, h0), l1 = packloh2(o4.z, o4.w, h1);
        size_t base2 = (size_t)row * (DD/2) + t*2;
        ((uint32_t*)ohi)[base2]     = h0;
        ((uint32_t*)ohi)[base2 + 1] = h1;
        ((uint32_t*)olo)[base2]     = l0;
        ((uint32_t*)olo)[base2 + 1] = l1;
    }
}

// ---------------- launcher ---------------------------------------------------
extern "C" void kernel_launch(void* const* d_in, const int* in_sizes, int n_in,
                              void* d_out, int out_size)
{
    int off = (in_sizes[0] == 1) ? 1 : 0;
    const float* query  = (const float*)d_in[off + 0];
    const float* key    = (const float*)d_in[off + 1];
    const float* values = (const float*)d_in[off + 2];
    const float* Wq = (const float*)d_in[off + 3];
    const float* bq = (const float*)d_in[off + 4];
    const float* Wk = (const float*)d_in[off + 5];
    const float* bk = (const float*)d_in[off + 6];
    const float* Wv = (const float*)d_in[off + 7];
    const float* bv = (const float*)d_in[off + 8];
    const float* Wo = (const float*)d_in[off + 9];
    const float* bo = (const float*)d_in[off + 10];
    const float* gammas = (const float*)d_in[off + 11];
    const float* ln1w = (const float*)d_in[off + 12];
    const float* ln1b = (const float*)d_in[off + 13];
    const float* W1 = (const float*)d_in[off + 14];
    const float* b1 = (const float*)d_in[off + 15];
    const float* W2 = (const float*)d_in[off + 16];
    const float* b2 = (const float*)d_in[off + 17];
    const float* ln2w = (const float*)d_in[off + 18];
    const float* ln2b = (const float*)d_in[off + 19];

    float *pattnout, *px, *pf;
    cudaGetSymbolAddress((void**)&pattnout, g_attnout);
    cudaGetSymbolAddress((void**)&px, g_x);
    cudaGetSymbolAddress((void**)&pf, g_f);

    __half *aqh,*aql,*akh,*akl,*avh,*avl;
    __half *wqh,*wkh,*wvh,*woh,*w1h,*w2h;
    __half *ahi,*alo,*hhi,*hlo,*qhi,*qlo,*khi,*klo,*vhi,*vlo;
    cudaGetSymbolAddress((void**)&aqh, g_aq_hi); cudaGetSymbolAddress((void**)&aql, g_aq_lo);
    cudaGetSymbolAddress((void**)&akh, g_ak_hi); cudaGetSymbolAddress((void**)&akl, g_ak_lo);
    cudaGetSymbolAddress((void**)&avh, g_av_hi); cudaGetSymbolAddress((void**)&avl, g_av_lo);
    cudaGetSymbolAddress((void**)&wqh, g_wq_h);
    cudaGetSymbolAddress((void**)&wkh, g_wk_h);
    cudaGetSymbolAddress((void**)&wvh, g_wv_h);
    cudaGetSymbolAddress((void**)&woh, g_wo_h);
    cudaGetSymbolAddress((void**)&w1h, g_w1_h);
    cudaGetSymbolAddress((void**)&w2h, g_w2_h);
    cudaGetSymbolAddress((void**)&ahi, g_ahi);   cudaGetSymbolAddress((void**)&alo, g_alo);
    cudaGetSymbolAddress((void**)&hhi, g_hhi);   cudaGetSymbolAddress((void**)&hlo, g_hlo);
    cudaGetSymbolAddress((void**)&qhi, g_qhi);   cudaGetSymbolAddress((void**)&qlo, g_qlo);
    cudaGetSymbolAddress((void**)&khi, g_khi);   cudaGetSymbolAddress((void**)&klo, g_klo);
    cudaGetSymbolAddress((void**)&vhi, g_vhi);   cudaGetSymbolAddress((void**)&vlo, g_vlo);

    const int M = BB * SS;   // 4096
    cudaFuncSetAttribute(gemm_mma<false,false>, cudaFuncAttributeMaxDynamicSharedMemorySize, G_SMEM);
    cudaFuncSetAttribute(gemm_mma<false,true>,  cudaFuncAttributeMaxDynamicSharedMemorySize, G_SMEM);
    cudaFuncSetAttribute(gemm_mma<true,true>,   cudaFuncAttributeMaxDynamicSharedMemorySize, G_SMEM);
    cudaFuncSetAttribute(attn_kernel, cudaFuncAttributeMaxDynamicSharedMemorySize, AT_SMEM);

    // -------- 1. mega split (acts hi/lo, weights single) --------
    {
        SplitArgs sa;
        const float* srcs[9] = {query, key, values, Wq, Wk, Wv, Wo, W1, W2};
        __half* his[9] = {aqh, akh, avh, wqh, wkh, wvh, woh, w1h, w2h};
        __half* los[9] = {aql, akl, avl, nullptr, nullptr, nullptr, nullptr, nullptr, nullptr};
        int nblk[9] = {4096, 4096, 4096, 1024, 1024, 1024, 1024, 4096, 4096};
        int cum = 0;
        for (int i = 0; i < 9; i++) {
            sa.seg[i].src = srcs[i]; sa.seg[i].hi = his[i]; sa.seg[i].lo = los[i];
            sa.start[i] = cum; cum += nblk[i];
        }
        sa.start[9] = cum;
        multi_split_kernel<<<cum, 256>>>(sa);
    }

    // -------- 2. QKV projections (batched) --------
    {
        GemmIO q = {aqh, aql, wqh, bq, nullptr, qhi, qlo};
        GemmIO k = {akh, akl, wkh, bk, nullptr, khi, klo};
        GemmIO v = {avh, avl, wvh, bv, nullptr, vhi, vlo};
        gemm_mma<false,true><<<dim3(DD/128, M/256, 3), 512, G_SMEM>>>(q, k, v, M, DD, DD);
    }

    // -------- 3. attention --------
    attn_kernel<<<dim3(SS/32, HH, BB), 256, AT_SMEM>>>(qhi, qlo, khi, klo, vhi,
                                                       gammas, ahi, alo);

    // -------- 4. output projection --------
    {
        GemmIO o = {ahi, alo, woh, bo, pattnout, nullptr, nullptr};
        gemm_mma<false,false><<<dim3(DD/128, M/256, 1), 512, G_SMEM>>>(o, o, o, M, DD, DD);
    }

    // -------- 5. LN1 --------
    add_ln_kernel<true><<<M, 256>>>(query, pattnout, ln1w, ln1b, px, ahi, alo);

    // -------- 6. FFN1 (+ReLU) --------
    {
        GemmIO f1 = {ahi, alo, w1h, b1, nullptr, hhi, hlo};
        gemm_mma<true,true><<<dim3(DFFF/128, M/256, 1), 512, G_SMEM>>>(f1, f1, f1, M, DFFF, DD);
    }

    // -------- 7. FFN2 --------
    {
        GemmIO f2 = {hhi, hlo, w2h, b2, pf, nullptr, nullptr};
        gemm_mma<false,false><<<dim3(DD/128, M/256, 1), 512, G_SMEM>>>(f2, f2, f2, M, DD, DFFF);
    }

    // -------- 8. LN2 --------
    add_ln_kernel<false><<<M, 256>>>(px, pf, ln2w, ln2b, (float*)d_out, nullptr, nullptr);
}

// round 9
// speedup vs baseline: 3.7858x; 1.3259x over previous
#include <cuda_runtime.h>
#include <cuda_fp16.h>
#include <math.h>
#include <stdint.h>

// Problem constants
#define BB 4
#define SS 1024
#define DD 1024
#define HH 16
#define DKK 64
#define DFFF 4096
#define SCP 1032   // score row pitch (floats)

// ---------------- scratch (device globals) -----------------------------------
__device__ float g_attnout[BB*SS*DD];
__device__ float g_x[BB*SS*DD];
__device__ float g_f[BB*SS*DD];
// activations: single fp16
__device__ __half g_aq[BB*SS*DD];
__device__ __half g_ak[BB*SS*DD];
__device__ __half g_av[BB*SS*DD];
// weights: single fp16
__device__ __half g_wq_h[DD*DD];
__device__ __half g_wk_h[DD*DD];
__device__ __half g_wv_h[DD*DD];
__device__ __half g_wo_h[DD*DD];
__device__ __half g_w1_h[DFFF*DD];
__device__ __half g_w2_h[DD*DFFF];
// intermediates
__device__ __half g_chi[BB*SS*DD];              // concat (single)
__device__ __half g_xh[BB*SS*DD];               // LN1 out (single)
__device__ __half g_hh[BB*SS*DFFF];             // FFN1 out (single)
__device__ __half g_qhi[BB*SS*DD], g_qlo[BB*SS*DD];
__device__ __half g_khi[BB*SS*DD], g_klo[BB*SS*DD];
__device__ __half g_vhi[BB*SS*DD];

// ======================= PTX helpers ========================================
__device__ __forceinline__ uint32_t smem_u32(const void* p) {
    uint32_t a;
    asm("{ .reg .u64 t; cvta.to.shared.u64 t, %1; cvt.u32.u64 %0, t; }" : "=r"(a) : "l"(p));
    return a;
}

#define CPASYNC16(dst, src) asm volatile("cp.async.cg.shared.global [%0], [%1], 16;" :: "r"(dst), "l"(src) : "memory")
#define CPCOMMIT() asm volatile("cp.async.commit_group;" ::: "memory")
#define CPWAIT2()  asm volatile("cp.async.wait_group 2;" ::: "memory")
#define CPWAIT1()  asm volatile("cp.async.wait_group 1;" ::: "memory")
#define CPWAIT0()  asm volatile("cp.async.wait_group 0;" ::: "memory")

#define LDSM_X4(R, A) \
    asm volatile("ldmatrix.sync.aligned.m8n8.x4.shared.b16 {%0,%1,%2,%3}, [%4];" \
        : "=r"((R)[0]), "=r"((R)[1]), "=r"((R)[2]), "=r"((R)[3]) : "r"(A))

#define LDSM_X2T(R, A) \
    asm volatile("ldmatrix.sync.aligned.m8n8.x2.trans.shared.b16 {%0,%1}, [%2];" \
        : "=r"((R)[0]), "=r"((R)[1]) : "r"(A))

__device__ __forceinline__ void mma_f16(float* c, const uint32_t* a, const uint32_t* b) {
    asm volatile(
        "mma.sync.aligned.m16n8k16.row.col.f32.f16.f16.f32 "
        "{%0,%1,%2,%3}, {%4,%5,%6,%7}, {%8,%9}, {%0,%1,%2,%3};"
        : "+f"(c[0]), "+f"(c[1]), "+f"(c[2]), "+f"(c[3])
        : "r"(a[0]), "r"(a[1]), "r"(a[2]), "r"(a[3]), "r"(b[0]), "r"(b[1]));
}

__device__ __forceinline__ uint32_t packh2(float x, float y) {
    __half2 t = __floats2half2_rn(x, y);
    return *reinterpret_cast<uint32_t*>(&t);
}
__device__ __forceinline__ uint32_t packloh2(float x, float y, uint32_t hi) {
    __half2 h = *reinterpret_cast<__half2*>(&hi);
    return packh2(x - __half2float(h.x), y - __half2float(h.y));
}

// ================ mega split: fp32 -> single fp16 ===========================
struct SplitSeg { const float* src; __half* hi; };
struct SplitArgs { SplitSeg seg[9]; int start[10]; };

__global__ void __launch_bounds__(256) multi_split_kernel(SplitArgs a)
{
    int bx = blockIdx.x;
    int s = 0;
#pragma unroll
    for (int i = 0; i < 8; i++) if (bx >= a.start[i+1]) s = i+1;
    SplitSeg sg = a.seg[s];
    int i = (bx - a.start[s]) * 256 + threadIdx.x;
    float4 v = ((const float4*)sg.src)[i];
    uint32_t h0 = packh2(v.x, v.y), h1 = packh2(v.z, v.w);
    ((uint32_t*)sg.hi)[i*2+0] = h0;
    ((uint32_t*)sg.hi)[i*2+1] = h1;
}

// ====== fp16 single-term GEMM: C = A @ W^T + bias, tile 256x128, 4 stages ===
// stage: A[256x80] B[128x80] = 30720 B
#define G_BH 20480
#define G_STAGE 30720
#define G_SMEM (4 * G_STAGE)   // 122880

struct GemmIO {
    const __half *Ah, *Wh;
    const float* bias;
    float* C;
    __half *Chi, *Clo;   // Clo may be null
};

template<bool RELU, bool SPLITOUT>
__global__ void __launch_bounds__(512, 1) gemm_mma(
    GemmIO io0, GemmIO io1, GemmIO io2, int M, int N, int K)
{
    extern __shared__ __align__(128) char smem[];
    uint32_t sb = smem_u32(smem);

    GemmIO io = (blockIdx.z == 0) ? io0 : (blockIdx.z == 1) ? io1 : io2;

    int tid  = threadIdx.x;
    int lane = tid & 31;
    int wid  = tid >> 5;       // 0..15
    int wm   = wid & 3;        // M warp (64 rows)
    int wn   = wid >> 2;       // N warp (32 cols)
    int bm = blockIdx.y * 256;
    int bn = blockIdx.x * 128;

    const int nch = K >> 5;

    auto load_stage = [&](int c) {
        uint32_t st = sb + (c & 3) * G_STAGE;
        size_t kof = (size_t)c * 32;
        const __half* a_h = io.Ah + (size_t)bm * K + kof;
        const __half* b_h = io.Wh + (size_t)bn * K + kof;
#pragma unroll
        for (int u = 0; u < 2; u++) {
            int l = tid + u * 512;         // 0..1023
            int row = l >> 2, ch = l & 3;
            CPASYNC16(st + row*80 + ch*16, (const char*)(a_h + (size_t)row*K) + ch*16);
        }
        {
            int row = tid >> 2, ch = tid & 3;   // 128 rows x 4
            CPASYNC16(st + G_BH + row*80 + ch*16, (const char*)(b_h + (size_t)row*K) + ch*16);
        }
        CPCOMMIT();
    };

    uint32_t aoff = ((((lane >> 3) & 1) * 8 + (lane & 7)) * 80) + (lane >> 4) * 16;
    uint32_t boff = (((lane >> 4) * 8 + (lane & 7)) * 80) + ((lane >> 3) & 1) * 16;

    float acc[4][4][4];
#pragma unroll
    for (int mt = 0; mt < 4; mt++)
#pragma unroll
        for (int n8 = 0; n8 < 4; n8++)
#pragma unroll
            for (int k = 0; k < 4; k++) acc[mt][n8][k] = 0.f;

    load_stage(0);
    load_stage(1);
    load_stage(2);
    for (int c = 0; c < nch; c++) {
        if (c + 2 < nch)      { CPWAIT2(); }
        else if (c + 1 < nch) { CPWAIT1(); }
        else                  { CPWAIT0(); }
        __syncthreads();
        if (c + 3 < nch) load_stage(c + 3);

        uint32_t st = sb + (c & 3) * G_STAGE;
        uint32_t aH = st        + (wm * 64) * 80 + aoff;
        uint32_t bH = st + G_BH + (wn * 32) * 80 + boff;

#pragma unroll
        for (int ks = 0; ks < 2; ks++) {
            uint32_t ah[4][4];
#pragma unroll
            for (int mt = 0; mt < 4; mt++)
                LDSM_X4(ah[mt], aH + mt * (16*80) + ks * 32);
#pragma unroll
            for (int g = 0; g < 2; g++) {
                uint32_t bh[4];
                LDSM_X4(bh, bH + g * (16*80) + ks * 32);
#pragma unroll
                for (int mt = 0; mt < 4; mt++)
#pragma unroll
                    for (int hf = 0; hf < 2; hf++)
                        mma_f16(acc[mt][g*2+hf], ah[mt], &bh[hf*2]);
            }
        }
    }

    int r_in = lane >> 2;
    int c_in = (lane & 3) * 2;
    bool wlo = SPLITOUT && (io.Clo != nullptr);
#pragma unroll
    for (int mt = 0; mt < 4; mt++) {
        int R0 = bm + wm * 64 + mt * 16 + r_in;
        int R1 = R0 + 8;
#pragma unroll
        for (int n8 = 0; n8 < 4; n8++) {
            int col = bn + wn * 32 + n8 * 8 + c_in;
            float b0 = io.bias[col], b1 = io.bias[col + 1];
            float o00 = acc[mt][n8][0] + b0, o01 = acc[mt][n8][1] + b1;
            float o10 = acc[mt][n8][2] + b0, o11 = acc[mt][n8][3] + b1;
            if (RELU) {
                o00 = fmaxf(o00, 0.f); o01 = fmaxf(o01, 0.f);
                o10 = fmaxf(o10, 0.f); o11 = fmaxf(o11, 0.f);
            }
            if (SPLITOUT) {
                uint32_t h0 = packh2(o00, o01), h1 = packh2(o10, o11);
                *(uint32_t*)&io.Chi[(size_t)R0 * N + col] = h0;
                *(uint32_t*)&io.Chi[(size_t)R1 * N + col] = h1;
                if (wlo) {
                    uint32_t l0 = packloh2(o00, o01, h0), l1 = packloh2(o10, o11, h1);
                    *(uint32_t*)&io.Clo[(size_t)R0 * N + col] = l0;
                    *(uint32_t*)&io.Clo[(size_t)R1 * N + col] = l1;
                }
            } else {
                float2 o0, o1;
                o0.x = o00; o0.y = o01; o1.x = o10; o1.y = o11;
                *(float2*)&io.C[(size_t)R0 * N + col] = o0;
                *(float2*)&io.C[(size_t)R1 * N + col] = o1;
            }
        }
    }
}

// ================= tensor-core distance-decay attention (32 rows/CTA) ========
// QK: fp16 3-term (q hi/lo x k hi/lo). PV: probs hi/lo x V single.
#define AT_QH 132096
#define AT_QL 136704
#define AT_K  141312
#define AT_KSZ 36864   // per buffer (KH + KL); V uses first half only
#define AT_SMEM 215040

__global__ void __launch_bounds__(256, 1) attn_kernel(
    const __half* __restrict__ qhi, const __half* __restrict__ qlo,
    const __half* __restrict__ khi, const __half* __restrict__ klo,
    const __half* __restrict__ vhi,
    const float* __restrict__ gammas,
    __half* __restrict__ ohi)
{
    extern __shared__ __align__(128) char smx[];
    float* sc = (float*)smx;
    uint32_t sb = smem_u32(smx);
    const uint32_t QH = sb + AT_QH;
    const uint32_t QL = sb + AT_QL;

    int b = blockIdx.z, h = blockIdx.y, i0 = blockIdx.x * 32;
    int t = threadIdx.x, lane = t & 31, w = t >> 5;

    size_t base_q = ((size_t)b*SS + i0)*DD + h*64;
    size_t base_k = (size_t)b*SS*DD + h*64;

    // ---- load Q tile (32 rows, hi+lo)
#pragma unroll
    for (int u = 0; u < 2; u++) {
        int l = t + u * 256;
        int sel = l >> 8;
        int idx = l & 255;
        int row = idx >> 3, ch = idx & 7;
        const __half* src = (sel ? qlo : qhi) + base_q + (size_t)row*DD + ch*8;
        char* dst = smx + (sel ? AT_QL : AT_QH) + row*144 + ch*16;
        *(float4*)dst = *(const float4*)src;
    }
    __syncthreads();

    uint32_t aoff = ((((lane >> 3) & 1) * 8 + (lane & 7)) * 144) + (lane >> 4) * 16;
    uint32_t boff = (((lane >> 4) * 8 + (lane & 7)) * 144) + ((lane >> 3) & 1) * 16;

    uint32_t ah[2][4][4], al[2][4][4];
#pragma unroll
    for (int mt = 0; mt < 2; mt++)
#pragma unroll
        for (int ks = 0; ks < 4; ks++) {
            LDSM_X4(ah[mt][ks], QH + mt*(16*144) + aoff + ks*32);
            LDSM_X4(al[mt][ks], QL + mt*(16*144) + aoff + ks*32);
        }

    // K tile loader (128 rows, hi+lo) into buffer bf
    auto loadK = [&](int jt, int bf) {
        uint32_t KH = sb + AT_K + bf * AT_KSZ;
        uint32_t KL = KH + 18432;
        int jbase = jt * 128;
#pragma unroll
        for (int u = 0; u < 4; u++) {
            int l = t + u * 256;
            int row = l >> 3, ch = l & 7;
            const char* sh = (const char*)(khi + base_k + (size_t)(jbase+row)*DD) + ch*16;
            const char* sl = (const char*)(klo + base_k + (size_t)(jbase+row)*DD) + ch*16;
            CPASYNC16(KH + row*144 + ch*16, sh);
            CPASYNC16(KL + row*144 + ch*16, sl);
        }
        CPCOMMIT();
    };

    // ---- QK^T: 8 tiles of 128 cols, double-buffered (3-term fp16)
    loadK(0, 0);
    for (int jt = 0; jt < 8; jt++) {
        CPWAIT0();
        __syncthreads();
        if (jt + 1 < 8) loadK(jt + 1, (jt + 1) & 1);

        uint32_t KH = sb + AT_K + (jt & 1) * AT_KSZ;
        uint32_t KL = KH + 18432;
        float c[2][2][4];
#pragma unroll
        for (int mt = 0; mt < 2; mt++)
#pragma unroll
            for (int g = 0; g < 2; g++)
#pragma unroll
                for (int k = 0; k < 4; k++) c[mt][g][k] = 0.f;

        uint32_t bb = (uint32_t)(w*16)*144 + boff;
#pragma unroll
        for (int ks = 0; ks < 4; ks++) {
            uint32_t bh[4], bl[4];
            LDSM_X4(bh, KH + bb + ks*32);
            LDSM_X4(bl, KL + bb + ks*32);
#pragma unroll
            for (int mt = 0; mt < 2; mt++) {
                mma_f16(c[mt][0], ah[mt][ks], &bh[0]);
                mma_f16(c[mt][0], ah[mt][ks], &bl[0]);
                mma_f16(c[mt][0], al[mt][ks], &bh[0]);
                mma_f16(c[mt][1], ah[mt][ks], &bh[2]);
                mma_f16(c[mt][1], ah[mt][ks], &bl[2]);
                mma_f16(c[mt][1], al[mt][ks], &bh[2]);
            }
        }
        int r = lane >> 2, cb = jt*128 + w*16 + (lane & 3)*2;
#pragma unroll
        for (int mt = 0; mt < 2; mt++) {
            int r0 = mt*16 + r;
            float2 v2;
            v2.x = c[mt][0][0]*0.125f; v2.y = c[mt][0][1]*0.125f; *(float2*)&sc[r0*SCP + cb] = v2;
            v2.x = c[mt][0][2]*0.125f; v2.y = c[mt][0][3]*0.125f; *(float2*)&sc[(r0+8)*SCP + cb] = v2;
            v2.x = c[mt][1][0]*0.125f; v2.y = c[mt][1][1]*0.125f; *(float2*)&sc[r0*SCP + cb + 8] = v2;
            v2.x = c[mt][1][2]*0.125f; v2.y = c[mt][1][3]*0.125f; *(float2*)&sc[(r0+8)*SCP + cb + 8] = v2;
        }
    }

    // V tile loader (single fp16)
    int jmax = i0 + 32;
    auto loadV = [&](int jbase, int rows, int bf) {
        uint32_t VH = sb + AT_K + bf * AT_KSZ;
        int total = rows * 8;
#pragma unroll
        for (int u = 0; u < 4; u++) {
            int l = t + u * 256;
            if (l < total) {
                int row = l >> 3, ch = l & 7;
                const char* sh = (const char*)(vhi + base_k + (size_t)(jbase+row)*DD) + ch*16;
                CPASYNC16(VH + row*144 + ch*16, sh);
            }
        }
        CPCOMMIT();
    };

    // prefetch V tile 0 into buffer 0 (hidden under row math)
    loadV(0, jmax < 128 ? jmax : 128, 0);
    __syncthreads();   // sc writes of jt=7 visible before row math

    // ---- per-row math: 4 rows per warp
    {
        float gamma = -log1pf(__expf(gammas[h]));
        for (int rr2 = 0; rr2 < 4; rr2++) {
            int r  = w*4 + rr2;
            int ig = i0 + r;
            float* row = sc + r*SCP;

            float s[32], p[32];
            float m = -INFINITY;
#pragma unroll
            for (int c = 0; c < 32; c++) {
                s[c] = row[c*32 + lane];
                m = fmaxf(m, s[c]);
            }
#pragma unroll
            for (int o = 16; o > 0; o >>= 1) m = fmaxf(m, __shfl_xor_sync(0xffffffffu, m, o));

            float sum1 = 0.f, summ = 0.f;
#pragma unroll
            for (int c = 0; c < 32; c++) {
                p[c] = __expf(s[c] - m);
                sum1 += p[c];
                if (c*32 + lane <= ig) summ += p[c];
            }
#pragma unroll
            for (int o = 16; o > 0; o >>= 1) {
                sum1 += __shfl_xor_sync(0xffffffffu, sum1, o);
                summ += __shfl_xor_sync(0xffffffffu, summ, o);
            }
            float inv1 = 1.f / sum1;

            float carry = 0.f, m2 = -INFINITY;
#pragma unroll
            for (int c = 0; c < 32; c++) {
                if (c*32 <= ig) {
                    int j = c*32 + lane;
                    float pm = (j <= ig) ? p[c] : 0.f;
                    float x = pm;
#pragma unroll
                    for (int o = 1; o < 32; o <<= 1) {
                        float y = __shfl_up_sync(0xffffffffu, x, o);
                        if (lane >= o) x += y;
                    }
                    float distraw = carry + x;
                    carry += __shfl_sync(0xffffffffu, x, 31);
                    float pos  = fabsf((float)(ig - j));
                    float dd   = (summ - distraw) * inv1 * pos;
                    float dist = sqrtf(fmaxf(dd, 0.f));
                    float eff  = __expf(dist * gamma);
                    eff = fminf(fmaxf(eff, 1e-5f), 1e5f);
                    float s2 = (j <= ig) ? s[c] * eff : -INFINITY;
                    s[c] = s2;
                    m2 = fmaxf(m2, s2);
                } else {
                    s[c] = -INFINITY;
                }
            }
#pragma unroll
            for (int o = 16; o > 0; o >>= 1) m2 = fmaxf(m2, __shfl_xor_sync(0xffffffffu, m2, o));

            float sum2 = 0.f;
#pragma unroll
            for (int c = 0; c < 32; c++) {
                float e = 0.f;
                if (c*32 <= ig) {
                    int j = c*32 + lane;
                    e = (j <= ig) ? __expf(s[c] - m2) : 0.f;
                }
                p[c] = e;
                sum2 += e;
            }
#pragma unroll
            for (int o = 16; o > 0; o >>= 1) sum2 += __shfl_xor_sync(0xffffffffu, sum2, o);
            float inv2 = 1.f / sum2;
#pragma unroll
            for (int c = 0; c < 32; c++) row[c*32 + lane] = p[c] * inv2;
        }
    }

    // ---- PV: warp w owns cols w*8..w*8+7; 2-term (probs hi/lo x V)
    float acc[2][4];
#pragma unroll
    for (int mt = 0; mt < 2; mt++)
#pragma unroll
        for (int k = 0; k < 4; k++) acc[mt][k] = 0.f;

    int rr = lane >> 2, kc = (lane & 3) * 2;
    int vrow = lane & 15;
    int ntiles = (jmax + 127) >> 7;
    for (int ji = 0; ji < ntiles; ji++) {
        int jbase = ji * 128;
        int rows = jmax - jbase; if (rows > 128) rows = 128;
        CPWAIT0();
        __syncthreads();
        if (ji + 1 < ntiles) {
            int nb = jbase + 128;
            int nrows = jmax - nb; if (nrows > 128) nrows = 128;
            loadV(nb, nrows, (ji + 1) & 1);
        }
        uint32_t VH = sb + AT_K + (ji & 1) * AT_KSZ;

        int nk = rows >> 4;
        for (int kk = 0; kk < nk; kk++) {
            int j0 = jbase + kk*16;
            uint32_t vh[2];
            uint32_t va = (uint32_t)(kk*16 + vrow)*144 + (uint32_t)w*16;
            LDSM_X2T(vh, VH + va);
#pragma unroll
            for (int mt = 0; mt < 2; mt++) {
                const float* p0 = &sc[(mt*16 + rr)*SCP + j0 + kc];
                float f00 = p0[0],        f01 = p0[1];
                float f10 = p0[8*SCP],    f11 = p0[8*SCP+1];
                float f20 = p0[8],        f21 = p0[9];
                float f30 = p0[8*SCP+8],  f31 = p0[8*SCP+9];
                uint32_t a_h[4], a_l[4];
                a_h[0] = packh2(f00, f01); a_l[0] = packloh2(f00, f01, a_h[0]);
                a_h[1] = packh2(f10, f11); a_l[1] = packloh2(f10, f11, a_h[1]);
                a_h[2] = packh2(f20, f21); a_l[2] = packloh2(f20, f21, a_h[2]);
                a_h[3] = packh2(f30, f31); a_l[3] = packloh2(f30, f31, a_h[3]);
                mma_f16(acc[mt], a_h, vh);
                mma_f16(acc[mt], a_l, vh);
            }
        }
    }

    // ---- epilogue -> concat single fp16
#pragma unroll
    for (int mt = 0; mt < 2; mt++) {
        size_t o0 = ((size_t)b*SS + i0 + mt*16 + rr)*DD + h*64 + w*8 + kc;
        size_t o1 = o0 + (size_t)8*DD;
        *(uint32_t*)&ohi[o0] = packh2(acc[mt][0], acc[mt][1]);
        *(uint32_t*)&ohi[o1] = packh2(acc[mt][2], acc[mt][3]);
    }
}

// ---------------- residual add + LayerNorm ----------------------------------
template<bool SPLITOUT>
__global__ void __launch_bounds__(256) add_ln_kernel(
    const float* __restrict__ A, const float* __restrict__ Bres,
    const float* __restrict__ w, const float* __restrict__ bias,
    float* __restrict__ outp,
    __half* __restrict__ ohi)
{
    __shared__ float red1[8], red2[8];
    int row = blockIdx.x;
    int t   = threadIdx.x;
    const float* pa = A    + (size_t)row*DD;
    const float* pb = Bres + (size_t)row*DD;

    float4 a4 = *(const float4*)&pa[t*4];
    float4 b4 = *(const float4*)&pb[t*4];
    float v0 = a4.x + b4.x, v1 = a4.y + b4.y, v2 = a4.z + b4.z, v3 = a4.w + b4.w;

    int lane = t & 31, wp = t >> 5;
    float s = v0 + v1 + v2 + v3;
#pragma unroll
    for (int o = 16; o > 0; o >>= 1) s += __shfl_xor_sync(0xffffffffu, s, o);
    if (lane == 0) red1[wp] = s;
    __syncthreads();
    float tot = 0.f;
#pragma unroll
    for (int i = 0; i < 8; i++) tot += red1[i];
    float mu = tot * (1.f / DD);

    float d0 = v0-mu, d1 = v1-mu, d2 = v2-mu, d3 = v3-mu;
    float q2 = d0*d0 + d1*d1 + d2*d2 + d3*d3;
#pragma unroll
    for (int o = 16; o > 0; o >>= 1) q2 += __shfl_xor_sync(0xffffffffu, q2, o);
    if (lane == 0) red2[wp] = q2;
    __syncthreads();
    float tv = 0.f;
#pragma unroll
    for (int i = 0; i < 8; i++) tv += red2[i];
    float inv = rsqrtf(tv * (1.f / DD) + 1e-5f);

    float4 w4  = *(const float4*)&w[t*4];
    float4 bi4 = *(const float4*)&bias[t*4];
    float4 o4;
    o4.x = d0*inv*w4.x + bi4.x;
    o4.y = d1*inv*w4.y + bi4.y;
    o4.z = d2*inv*w4.z + bi4.z;
    o4.w = d3*inv*w4.w + bi4.w;
    *(float4*)&outp[(size_t)row*DD + t*4] = o4;

    if (SPLITOUT) {
        uint32_t h0 = packh2(o4.x, o4.y), h1 = packh2(o4.z, o4.w);
        size_t base2 = (size_t)row * (DD/2) + t*2;
        ((uint32_t*)ohi)[base2]     = h0;
        ((uint32_t*)ohi)[base2 + 1] = h1;
    }
}

// ---------------- launcher ---------------------------------------------------
extern "C" void kernel_launch(void* const* d_in, const int* in_sizes, int n_in,
                              void* d_out, int out_size)
{
    int off = (in_sizes[0] == 1) ? 1 : 0;
    const float* query  = (const float*)d_in[off + 0];
    const float* key    = (const float*)d_in[off + 1];
    const float* values = (const float*)d_in[off + 2];
    const float* Wq = (const float*)d_in[off + 3];
    const float* bq = (const float*)d_in[off + 4];
    const float* Wk = (const float*)d_in[off + 5];
    const float* bk = (const float*)d_in[off + 6];
    const float* Wv = (const float*)d_in[off + 7];
    const float* bv = (const float*)d_in[off + 8];
    const float* Wo = (const float*)d_in[off + 9];
    const float* bo = (const float*)d_in[off + 10];
    const float* gammas = (const float*)d_in[off + 11];
    const float* ln1w = (const float*)d_in[off + 12];
    const float* ln1b = (const float*)d_in[off + 13];
    const float* W1 = (const float*)d_in[off + 14];
    const float* b1 = (const float*)d_in[off + 15];
    const float* W2 = (const float*)d_in[off + 16];
    const float* b2 = (const float*)d_in[off + 17];
    const float* ln2w = (const float*)d_in[off + 18];
    const float* ln2b = (const float*)d_in[off + 19];

    float *pattnout, *px, *pf;
    cudaGetSymbolAddress((void**)&pattnout, g_attnout);
    cudaGetSymbolAddress((void**)&px, g_x);
    cudaGetSymbolAddress((void**)&pf, g_f);

    __half *aq,*ak,*av;
    __half *wqh,*wkh,*wvh,*woh,*w1h,*w2h;
    __half *chi,*xh,*hh,*qhi,*qlo,*khi,*klo,*vhi;
    cudaGetSymbolAddress((void**)&aq, g_aq);
    cudaGetSymbolAddress((void**)&ak, g_ak);
    cudaGetSymbolAddress((void**)&av, g_av);
    cudaGetSymbolAddress((void**)&wqh, g_wq_h);
    cudaGetSymbolAddress((void**)&wkh, g_wk_h);
    cudaGetSymbolAddress((void**)&wvh, g_wv_h);
    cudaGetSymbolAddress((void**)&woh, g_wo_h);
    cudaGetSymbolAddress((void**)&w1h, g_w1_h);
    cudaGetSymbolAddress((void**)&w2h, g_w2_h);
    cudaGetSymbolAddress((void**)&chi, g_chi);
    cudaGetSymbolAddress((void**)&xh, g_xh);
    cudaGetSymbolAddress((void**)&hh, g_hh);
    cudaGetSymbolAddress((void**)&qhi, g_qhi);   cudaGetSymbolAddress((void**)&qlo, g_qlo);
    cudaGetSymbolAddress((void**)&khi, g_khi);   cudaGetSymbolAddress((void**)&klo, g_klo);
    cudaGetSymbolAddress((void**)&vhi, g_vhi);

    const int M = BB * SS;   // 4096
    cudaFuncSetAttribute(gemm_mma<false,false>, cudaFuncAttributeMaxDynamicSharedMemorySize, G_SMEM);
    cudaFuncSetAttribute(gemm_mma<false,true>,  cudaFuncAttributeMaxDynamicSharedMemorySize, G_SMEM);
    cudaFuncSetAttribute(gemm_mma<true,true>,   cudaFuncAttributeMaxDynamicSharedMemorySize, G_SMEM);
    cudaFuncSetAttribute(attn_kernel, cudaFuncAttributeMaxDynamicSharedMemorySize, AT_SMEM);

    // -------- 1. mega split (all single fp16) --------
    {
        SplitArgs sa;
        const float* srcs[9] = {query, key, values, Wq, Wk, Wv, Wo, W1, W2};
        __half* his[9] = {aq, ak, av, wqh, wkh, wvh, woh, w1h, w2h};
        int nblk[9] = {4096, 4096, 4096, 1024, 1024, 1024, 1024, 4096, 4096};
        int cum = 0;
        for (int i = 0; i < 9; i++) {
            sa.seg[i].src = srcs[i]; sa.seg[i].hi = his[i];
            sa.start[i] = cum; cum += nblk[i];
        }
        sa.start[9] = cum;
        multi_split_kernel<<<cum, 256>>>(sa);
    }

    // -------- 2. QKV projections (batched; q/k emit hi+lo, v hi only) --------
    {
        GemmIO q = {aq, wqh, bq, nullptr, qhi, qlo};
        GemmIO k = {ak, wkh, bk, nullptr, khi, klo};
        GemmIO v = {av, wvh, bv, nullptr, vhi, nullptr};
        gemm_mma<false,true><<<dim3(DD/128, M/256, 3), 512, G_SMEM>>>(q, k, v, M, DD, DD);
    }

    // -------- 3. attention -> concat single fp16 --------
    attn_kernel<<<dim3(SS/32, HH, BB), 256, AT_SMEM>>>(qhi, qlo, khi, klo, vhi,
                                                       gammas, chi);

    // -------- 4. output projection --------
    {
        GemmIO o = {chi, woh, bo, pattnout, nullptr, nullptr};
        gemm_mma<false,false><<<dim3(DD/128, M/256, 1), 512, G_SMEM>>>(o, o, o, M, DD, DD);
    }

    // -------- 5. LN1 -> px (fp32) + xh (fp16) --------
    add_ln_kernel<true><<<M, 256>>>(query, pattnout, ln1w, ln1b, px, xh);

    // -------- 6. FFN1 (+ReLU) -> hh (fp16) --------
    {
        GemmIO f1 = {xh, w1h, b1, nullptr, hh, nullptr};
        gemm_mma<true,true><<<dim3(DFFF/128, M/256, 1), 512, G_SMEM>>>(f1, f1, f1, M, DFFF, DD);
    }

    // -------- 7. FFN2 --------
    {
        GemmIO f2 = {hh, w2h, b2, pf, nullptr, nullptr};
        gemm_mma<false,false><<<dim3(DD/128, M/256, 1), 512, G_SMEM>>>(f2, f2, f2, M, DD, DFFF);
    }

    // -------- 8. LN2 --------
    add_ln_kernel<false><<<M, 256>>>(px, pf, ln2w, ln2b, (float*)d_out, nullptr);
}

// round 10
// speedup vs baseline: 4.4807x; 1.1836x over previous
#include <cuda_runtime.h>
#include <cuda_fp16.h>
#include <math.h>
#include <stdint.h>

// Problem constants
#define BB 4
#define SS 1024
#define DD 1024
#define HH 16
#define DKK 64
#define DFFF 4096
#define SCP 1032   // score row pitch (floats)

// ---------------- scratch (device globals) -----------------------------------
__device__ float g_attnout[BB*SS*DD];
__device__ float g_x[BB*SS*DD];
__device__ float g_f[BB*SS*DD];
// activations: single fp16
__device__ __half g_aq[BB*SS*DD];
__device__ __half g_ak[BB*SS*DD];
__device__ __half g_av[BB*SS*DD];
// weights: single fp16
__device__ __half g_wq_h[DD*DD];
__device__ __half g_wk_h[DD*DD];
__device__ __half g_wv_h[DD*DD];
__device__ __half g_wo_h[DD*DD];
__device__ __half g_w1_h[DFFF*DD];
__device__ __half g_w2_h[DD*DFFF];
// intermediates
__device__ __half g_chi[BB*SS*DD];              // concat (single)
__device__ __half g_xh[BB*SS*DD];               // LN1 out (single)
__device__ __half g_hh[BB*SS*DFFF];             // FFN1 out (single)
__device__ __half g_qhi[BB*SS*DD], g_qlo[BB*SS*DD];
__device__ __half g_khi[BB*SS*DD];
__device__ __half g_vhi[BB*SS*DD];

// ======================= PTX helpers ========================================
__device__ __forceinline__ uint32_t smem_u32(const void* p) {
    uint32_t a;
    asm("{ .reg .u64 t; cvta.to.shared.u64 t, %1; cvt.u32.u64 %0, t; }" : "=r"(a) : "l"(p));
    return a;
}

#define CPASYNC16(dst, src) asm volatile("cp.async.cg.shared.global [%0], [%1], 16;" :: "r"(dst), "l"(src) : "memory")
#define CPCOMMIT() asm volatile("cp.async.commit_group;" ::: "memory")
#define CPWAIT2()  asm volatile("cp.async.wait_group 2;" ::: "memory")
#define CPWAIT1()  asm volatile("cp.async.wait_group 1;" ::: "memory")
#define CPWAIT0()  asm volatile("cp.async.wait_group 0;" ::: "memory")

#define LDSM_X4(R, A) \
    asm volatile("ldmatrix.sync.aligned.m8n8.x4.shared.b16 {%0,%1,%2,%3}, [%4];" \
        : "=r"((R)[0]), "=r"((R)[1]), "=r"((R)[2]), "=r"((R)[3]) : "r"(A))

#define LDSM_X2T(R, A) \
    asm volatile("ldmatrix.sync.aligned.m8n8.x2.trans.shared.b16 {%0,%1}, [%2];" \
        : "=r"((R)[0]), "=r"((R)[1]) : "r"(A))

__device__ __forceinline__ void mma_f16(float* c, const uint32_t* a, const uint32_t* b) {
    asm volatile(
        "mma.sync.aligned.m16n8k16.row.col.f32.f16.f16.f32 "
        "{%0,%1,%2,%3}, {%4,%5,%6,%7}, {%8,%9}, {%0,%1,%2,%3};"
        : "+f"(c[0]), "+f"(c[1]), "+f"(c[2]), "+f"(c[3])
        : "r"(a[0]), "r"(a[1]), "r"(a[2]), "r"(a[3]), "r"(b[0]), "r"(b[1]));
}

__device__ __forceinline__ uint32_t packh2(float x, float y) {
    __half2 t = __floats2half2_rn(x, y);
    return *reinterpret_cast<uint32_t*>(&t);
}
__device__ __forceinline__ uint32_t packloh2(float x, float y, uint32_t hi) {
    __half2 h = *reinterpret_cast<__half2*>(&hi);
    return packh2(x - __half2float(h.x), y - __half2float(h.y));
}

// ================ mega split: fp32 -> single fp16 ===========================
struct SplitSeg { const float* src; __half* hi; };
struct SplitArgs { SplitSeg seg[9]; int start[10]; };

__global__ void __launch_bounds__(256) multi_split_kernel(SplitArgs a)
{
    int bx = blockIdx.x;
    int s = 0;
#pragma unroll
    for (int i = 0; i < 8; i++) if (bx >= a.start[i+1]) s = i+1;
    SplitSeg sg = a.seg[s];
    int i = (bx - a.start[s]) * 256 + threadIdx.x;
    float4 v = ((const float4*)sg.src)[i];
    uint32_t h0 = packh2(v.x, v.y), h1 = packh2(v.z, v.w);
    ((uint32_t*)sg.hi)[i*2+0] = h0;
    ((uint32_t*)sg.hi)[i*2+1] = h1;
}

// ====== fp16 single-term GEMM: C = A @ W^T + bias, tile 256x128, 4 stages ===
#define G_BH 20480
#define G_STAGE 30720
#define G_SMEM (4 * G_STAGE)   // 122880

struct GemmIO {
    const __half *Ah, *Wh;
    const float* bias;
    float* C;
    __half *Chi, *Clo;   // Clo may be null
};

template<bool RELU, bool SPLITOUT>
__global__ void __launch_bounds__(512, 1) gemm_mma(
    GemmIO io0, GemmIO io1, GemmIO io2, int M, int N, int K)
{
    extern __shared__ __align__(128) char smem[];
    uint32_t sb = smem_u32(smem);

    GemmIO io = (blockIdx.z == 0) ? io0 : (blockIdx.z == 1) ? io1 : io2;

    int tid  = threadIdx.x;
    int lane = tid & 31;
    int wid  = tid >> 5;
    int wm   = wid & 3;
    int wn   = wid >> 2;
    int bm = blockIdx.y * 256;
    int bn = blockIdx.x * 128;

    const int nch = K >> 5;

    auto load_stage = [&](int c) {
        uint32_t st = sb + (c & 3) * G_STAGE;
        size_t kof = (size_t)c * 32;
        const __half* a_h = io.Ah + (size_t)bm * K + kof;
        const __half* b_h = io.Wh + (size_t)bn * K + kof;
#pragma unroll
        for (int u = 0; u < 2; u++) {
            int l = tid + u * 512;
            int row = l >> 2, ch = l & 3;
            CPASYNC16(st + row*80 + ch*16, (const char*)(a_h + (size_t)row*K) + ch*16);
        }
        {
            int row = tid >> 2, ch = tid & 3;
            CPASYNC16(st + G_BH + row*80 + ch*16, (const char*)(b_h + (size_t)row*K) + ch*16);
        }
        CPCOMMIT();
    };

    uint32_t aoff = ((((lane >> 3) & 1) * 8 + (lane & 7)) * 80) + (lane >> 4) * 16;
    uint32_t boff = (((lane >> 4) * 8 + (lane & 7)) * 80) + ((lane >> 3) & 1) * 16;

    float acc[4][4][4];
#pragma unroll
    for (int mt = 0; mt < 4; mt++)
#pragma unroll
        for (int n8 = 0; n8 < 4; n8++)
#pragma unroll
            for (int k = 0; k < 4; k++) acc[mt][n8][k] = 0.f;

    load_stage(0);
    load_stage(1);
    load_stage(2);
    for (int c = 0; c < nch; c++) {
        if (c + 2 < nch)      { CPWAIT2(); }
        else if (c + 1 < nch) { CPWAIT1(); }
        else                  { CPWAIT0(); }
        __syncthreads();
        if (c + 3 < nch) load_stage(c + 3);

        uint32_t st = sb + (c & 3) * G_STAGE;
        uint32_t aH = st        + (wm * 64) * 80 + aoff;
        uint32_t bH = st + G_BH + (wn * 32) * 80 + boff;

#pragma unroll
        for (int ks = 0; ks < 2; ks++) {
            uint32_t ah[4][4];
#pragma unroll
            for (int mt = 0; mt < 4; mt++)
                LDSM_X4(ah[mt], aH + mt * (16*80) + ks * 32);
#pragma unroll
            for (int g = 0; g < 2; g++) {
                uint32_t bh[4];
                LDSM_X4(bh, bH + g * (16*80) + ks * 32);
#pragma unroll
                for (int mt = 0; mt < 4; mt++)
#pragma unroll
                    for (int hf = 0; hf < 2; hf++)
                        mma_f16(acc[mt][g*2+hf], ah[mt], &bh[hf*2]);
            }
        }
    }

    int r_in = lane >> 2;
    int c_in = (lane & 3) * 2;
    bool wlo = SPLITOUT && (io.Clo != nullptr);
#pragma unroll
    for (int mt = 0; mt < 4; mt++) {
        int R0 = bm + wm * 64 + mt * 16 + r_in;
        int R1 = R0 + 8;
#pragma unroll
        for (int n8 = 0; n8 < 4; n8++) {
            int col = bn + wn * 32 + n8 * 8 + c_in;
            float b0 = io.bias[col], b1 = io.bias[col + 1];
            float o00 = acc[mt][n8][0] + b0, o01 = acc[mt][n8][1] + b1;
            float o10 = acc[mt][n8][2] + b0, o11 = acc[mt][n8][3] + b1;
            if (RELU) {
                o00 = fmaxf(o00, 0.f); o01 = fmaxf(o01, 0.f);
                o10 = fmaxf(o10, 0.f); o11 = fmaxf(o11, 0.f);
            }
            if (SPLITOUT) {
                uint32_t h0 = packh2(o00, o01), h1 = packh2(o10, o11);
                *(uint32_t*)&io.Chi[(size_t)R0 * N + col] = h0;
                *(uint32_t*)&io.Chi[(size_t)R1 * N + col] = h1;
                if (wlo) {
                    uint32_t l0 = packloh2(o00, o01, h0), l1 = packloh2(o10, o11, h1);
                    *(uint32_t*)&io.Clo[(size_t)R0 * N + col] = l0;
                    *(uint32_t*)&io.Clo[(size_t)R1 * N + col] = l1;
                }
            } else {
                float2 o0, o1;
                o0.x = o00; o0.y = o01; o1.x = o10; o1.y = o11;
                *(float2*)&io.C[(size_t)R0 * N + col] = o0;
                *(float2*)&io.C[(size_t)R1 * N + col] = o1;
            }
        }
    }
}

// ================= tensor-core distance-decay attention ======================
// 512 threads (16 warps), 32 rows/CTA.
// QK: 2-term (q hi/lo x k hi). PV: probs hi/lo x V single.
// smem: sc[32][SCP] fp32 | QH/QL 32x144 | 2 x K/V buffer 128x144 (fp16 single)
#define AT_QH 132096
#define AT_QL 136704
#define AT_K  141312
#define AT_KSZ 18432
#define AT_SMEM 178176

__global__ void __launch_bounds__(512, 1) attn_kernel(
    const __half* __restrict__ qhi, const __half* __restrict__ qlo,
    const __half* __restrict__ khi, const __half* __restrict__ vhi,
    const float* __restrict__ gammas,
    __half* __restrict__ ohi)
{
    extern __shared__ __align__(128) char smx[];
    float* sc = (float*)smx;
    uint32_t sb = smem_u32(smx);
    const uint32_t QH = sb + AT_QH;
    const uint32_t QL = sb + AT_QL;

    int b = blockIdx.z, h = blockIdx.y, i0 = blockIdx.x * 32;
    int t = threadIdx.x, lane = t & 31, w = t >> 5;   // w: 0..15
    int mt = w & 1;          // row half (16 rows)
    int cg = w >> 1;         // col group

    size_t base_q = ((size_t)b*SS + i0)*DD + h*64;
    size_t base_k = (size_t)b*SS*DD + h*64;

    // ---- load Q tile (32 rows, hi+lo): 512 chunks of 16B
    {
        int sel = t >> 8;
        int idx = t & 255;
        int row = idx >> 3, ch = idx & 7;
        const __half* src = (sel ? qlo : qhi) + base_q + (size_t)row*DD + ch*8;
        char* dst = smx + (sel ? AT_QL : AT_QH) + row*144 + ch*16;
        *(float4*)dst = *(const float4*)src;
    }
    __syncthreads();

    uint32_t aoff = ((((lane >> 3) & 1) * 8 + (lane & 7)) * 144) + (lane >> 4) * 16;
    uint32_t boff = (((lane >> 4) * 8 + (lane & 7)) * 144) + ((lane >> 3) & 1) * 16;

    // Q fragments for this warp's row half only
    uint32_t ah[4][4], al[4][4];
#pragma unroll
    for (int ks = 0; ks < 4; ks++) {
        LDSM_X4(ah[ks], QH + mt*(16*144) + aoff + ks*32);
        LDSM_X4(al[ks], QL + mt*(16*144) + aoff + ks*32);
    }

    // K tile loader (128 rows, hi only) into buffer bf: 1024 chunks
    auto loadK = [&](int jt, int bf) {
        uint32_t KH = sb + AT_K + bf * AT_KSZ;
        int jbase = jt * 128;
#pragma unroll
        for (int u = 0; u < 2; u++) {
            int l = t + u * 512;
            int row = l >> 3, ch = l & 7;
            const char* sh = (const char*)(khi + base_k + (size_t)(jbase+row)*DD) + ch*16;
            CPASYNC16(KH + row*144 + ch*16, sh);
        }
        CPCOMMIT();
    };

    // ---- QK^T: 8 tiles of 128 cols, double-buffered
    loadK(0, 0);
    for (int jt = 0; jt < 8; jt++) {
        CPWAIT0();
        __syncthreads();
        if (jt + 1 < 8) loadK(jt + 1, (jt + 1) & 1);

        uint32_t KH = sb + AT_K + (jt & 1) * AT_KSZ;
        float c0[4] = {0,0,0,0}, c1[4] = {0,0,0,0};
        uint32_t bb = (uint32_t)(cg*16)*144 + boff;
#pragma unroll
        for (int ks = 0; ks < 4; ks++) {
            uint32_t bh[4];
            LDSM_X4(bh, KH + bb + ks*32);
            mma_f16(c0, ah[ks], &bh[0]);
            mma_f16(c0, al[ks], &bh[0]);
            mma_f16(c1, ah[ks], &bh[2]);
            mma_f16(c1, al[ks], &bh[2]);
        }
        int r0 = mt*16 + (lane >> 2);
        int cb = jt*128 + cg*16 + (lane & 3)*2;
        float2 v2;
        v2.x = c0[0]*0.125f; v2.y = c0[1]*0.125f; *(float2*)&sc[r0*SCP + cb] = v2;
        v2.x = c0[2]*0.125f; v2.y = c0[3]*0.125f; *(float2*)&sc[(r0+8)*SCP + cb] = v2;
        v2.x = c1[0]*0.125f; v2.y = c1[1]*0.125f; *(float2*)&sc[r0*SCP + cb + 8] = v2;
        v2.x = c1[2]*0.125f; v2.y = c1[3]*0.125f; *(float2*)&sc[(r0+8)*SCP + cb + 8] = v2;
    }

    // V tile loader (single fp16)
    int jmax = i0 + 32;
    auto loadV = [&](int jbase, int rows, int bf) {
        uint32_t VH = sb + AT_K + bf * AT_KSZ;
        int total = rows * 8;
#pragma unroll
        for (int u = 0; u < 2; u++) {
            int l = t + u * 512;
            if (l < total) {
                int row = l >> 3, ch = l & 7;
                const char* sh = (const char*)(vhi + base_k + (size_t)(jbase+row)*DD) + ch*16;
                CPASYNC16(VH + row*144 + ch*16, sh);
            }
        }
        CPCOMMIT();
    };

    // prefetch V tile 0 into buffer 0 (jt=7 used buffer 1) — hidden under row math
    loadV(0, jmax < 128 ? jmax : 128, 0);
    __syncthreads();   // sc writes visible before row math

    // ---- per-row math: 2 rows per warp
    {
        float gamma = -log1pf(__expf(gammas[h]));
        for (int rr2 = 0; rr2 < 2; rr2++) {
            int r  = w*2 + rr2;
            int ig = i0 + r;
            float* row = sc + r*SCP;

            float s[32], p[32];
            float m = -INFINITY;
#pragma unroll
            for (int c = 0; c < 32; c++) {
                s[c] = row[c*32 + lane];
                m = fmaxf(m, s[c]);
            }
#pragma unroll
            for (int o = 16; o > 0; o >>= 1) m = fmaxf(m, __shfl_xor_sync(0xffffffffu, m, o));

            float sum1 = 0.f, summ = 0.f;
#pragma unroll
            for (int c = 0; c < 32; c++) {
                p[c] = __expf(s[c] - m);
                sum1 += p[c];
                if (c*32 + lane <= ig) summ += p[c];
            }
#pragma unroll
            for (int o = 16; o > 0; o >>= 1) {
                sum1 += __shfl_xor_sync(0xffffffffu, sum1, o);
                summ += __shfl_xor_sync(0xffffffffu, summ, o);
            }
            float inv1 = 1.f / sum1;

            // independent per-chunk inclusive scans (no carry chain in scans)
#pragma unroll
            for (int c = 0; c < 32; c++) {
                if (c*32 <= ig) {
                    int j = c*32 + lane;
                    float x = (j <= ig) ? p[c] : 0.f;
#pragma unroll
                    for (int o = 1; o < 32; o <<= 1) {
                        float y = __shfl_up_sync(0xffffffffu, x, o);
                        if (lane >= o) x += y;
                    }
                    p[c] = x;
                }
            }
            // decay transform with light serial carry
            float carry = 0.f, m2 = -INFINITY;
#pragma unroll
            for (int c = 0; c < 32; c++) {
                if (c*32 <= ig) {
                    int j = c*32 + lane;
                    float tch = __shfl_sync(0xffffffffu, p[c], 31);
                    float distcum = carry + p[c];
                    carry += tch;
                    float pos  = fabsf((float)(ig - j));
                    float dd   = (summ - distcum) * inv1 * pos;
                    float dist = sqrtf(fmaxf(dd, 0.f));
                    float eff  = __expf(dist * gamma);
                    eff = fminf(fmaxf(eff, 1e-5f), 1e5f);
                    float s2 = (j <= ig) ? s[c] * eff : -INFINITY;
                    s[c] = s2;
                    m2 = fmaxf(m2, s2);
                } else {
                    s[c] = -INFINITY;
                }
            }
#pragma unroll
            for (int o = 16; o > 0; o >>= 1) m2 = fmaxf(m2, __shfl_xor_sync(0xffffffffu, m2, o));

            float sum2 = 0.f;
#pragma unroll
            for (int c = 0; c < 32; c++) {
                float e = 0.f;
                if (c*32 <= ig) {
                    int j = c*32 + lane;
                    e = (j <= ig) ? __expf(s[c] - m2) : 0.f;
                }
                p[c] = e;
                sum2 += e;
            }
#pragma unroll
            for (int o = 16; o > 0; o >>= 1) sum2 += __shfl_xor_sync(0xffffffffu, sum2, o);
            float inv2 = 1.f / sum2;
#pragma unroll
            for (int c = 0; c < 32; c++) row[c*32 + lane] = p[c] * inv2;
        }
    }

    // ---- PV: warp w -> row half mt (16 rows), cols cg*8..cg*8+7
    float acc[4] = {0.f, 0.f, 0.f, 0.f};
    int rr = lane >> 2, kc = (lane & 3) * 2;
    int vrow = lane & 15;
    int ntiles = (jmax + 127) >> 7;
    for (int ji = 0; ji < ntiles; ji++) {
        int jbase = ji * 128;
        int rows = jmax - jbase; if (rows > 128) rows = 128;
        CPWAIT0();
        __syncthreads();
        if (ji + 1 < ntiles) {
            int nb = jbase + 128;
            int nrows = jmax - nb; if (nrows > 128) nrows = 128;
            loadV(nb, nrows, (ji + 1) & 1);
        }
        uint32_t VH = sb + AT_K + (ji & 1) * AT_KSZ;

        int nk = rows >> 4;
        for (int kk = 0; kk < nk; kk++) {
            int j0 = jbase + kk*16;
            uint32_t vh[2];
            uint32_t va = (uint32_t)(kk*16 + vrow)*144 + (uint32_t)cg*16;
            LDSM_X2T(vh, VH + va);
            const float* p0 = &sc[(mt*16 + rr)*SCP + j0 + kc];
            float f00 = p0[0],        f01 = p0[1];
            float f10 = p0[8*SCP],    f11 = p0[8*SCP+1];
            float f20 = p0[8],        f21 = p0[9];
            float f30 = p0[8*SCP+8],  f31 = p0[8*SCP+9];
            uint32_t a_h[4], a_l[4];
            a_h[0] = packh2(f00, f01); a_l[0] = packloh2(f00, f01, a_h[0]);
            a_h[1] = packh2(f10, f11); a_l[1] = packloh2(f10, f11, a_h[1]);
            a_h[2] = packh2(f20, f21); a_l[2] = packloh2(f20, f21, a_h[2]);
            a_h[3] = packh2(f30, f31); a_l[3] = packloh2(f30, f31, a_h[3]);
            mma_f16(acc, a_h, vh);
            mma_f16(acc, a_l, vh);
        }
    }

    // ---- epilogue -> concat single fp16
    {
        size_t o0 = ((size_t)b*SS + i0 + mt*16 + rr)*DD + h*64 + cg*8 + kc;
        size_t o1 = o0 + (size_t)8*DD;
        *(uint32_t*)&ohi[o0] = packh2(acc[0], acc[1]);
        *(uint32_t*)&ohi[o1] = packh2(acc[2], acc[3]);
    }
}

// ---------------- residual add + LayerNorm ----------------------------------
template<bool SPLITOUT>
__global__ void __launch_bounds__(256) add_ln_kernel(
    const float* __restrict__ A, const float* __restrict__ Bres,
    const float* __restrict__ w, const float* __restrict__ bias,
    float* __restrict__ outp,
    __half* __restrict__ ohi)
{
    __shared__ float red1[8], red2[8];
    int row = blockIdx.x;
    int t   = threadIdx.x;
    const float* pa = A    + (size_t)row*DD;
    const float* pb = Bres + (size_t)row*DD;

    float4 a4 = *(const float4*)&pa[t*4];
    float4 b4 = *(const float4*)&pb[t*4];
    float v0 = a4.x + b4.x, v1 = a4.y + b4.y, v2 = a4.z + b4.z, v3 = a4.w + b4.w;

    int lane = t & 31, wp = t >> 5;
    float s = v0 + v1 + v2 + v3;
#pragma unroll
    for (int o = 16; o > 0; o >>= 1) s += __shfl_xor_sync(0xffffffffu, s, o);
    if (lane == 0) red1[wp] = s;
    __syncthreads();
    float tot = 0.f;
#pragma unroll
    for (int i = 0; i < 8; i++) tot += red1[i];
    float mu = tot * (1.f / DD);

    float d0 = v0-mu, d1 = v1-mu, d2 = v2-mu, d3 = v3-mu;
    float q2 = d0*d0 + d1*d1 + d2*d2 + d3*d3;
#pragma unroll
    for (int o = 16; o > 0; o >>= 1) q2 += __shfl_xor_sync(0xffffffffu, q2, o);
    if (lane == 0) red2[wp] = q2;
    __syncthreads();
    float tv = 0.f;
#pragma unroll
    for (int i = 0; i < 8; i++) tv += red2[i];
    float inv = rsqrtf(tv * (1.f / DD) + 1e-5f);

    float4 w4  = *(const float4*)&w[t*4];
    float4 bi4 = *(const float4*)&bias[t*4];
    float4 o4;
    o4.x = d0*inv*w4.x + bi4.x;
    o4.y = d1*inv*w4.y + bi4.y;
    o4.z = d2*inv*w4.z + bi4.z;
    o4.w = d3*inv*w4.w + bi4.w;
    *(float4*)&outp[(size_t)row*DD + t*4] = o4;

    if (SPLITOUT) {
        uint32_t h0 = packh2(o4.x, o4.y), h1 = packh2(o4.z, o4.w);
        size_t base2 = (size_t)row * (DD/2) + t*2;
        ((uint32_t*)ohi)[base2]     = h0;
        ((uint32_t*)ohi)[base2 + 1] = h1;
    }
}

// ---------------- launcher ---------------------------------------------------
extern "C" void kernel_launch(void* const* d_in, const int* in_sizes, int n_in,
                              void* d_out, int out_size)
{
    int off = (in_sizes[0] == 1) ? 1 : 0;
    const float* query  = (const float*)d_in[off + 0];
    const float* key    = (const float*)d_in[off + 1];
    const float* values = (const float*)d_in[off + 2];
    const float* Wq = (const float*)d_in[off + 3];
    const float* bq = (const float*)d_in[off + 4];
    const float* Wk = (const float*)d_in[off + 5];
    const float* bk = (const float*)d_in[off + 6];
    const float* Wv = (const float*)d_in[off + 7];
    const float* bv = (const float*)d_in[off + 8];
    const float* Wo = (const float*)d_in[off + 9];
    const float* bo = (const float*)d_in[off + 10];
    const float* gammas = (const float*)d_in[off + 11];
    const float* ln1w = (const float*)d_in[off + 12];
    const float* ln1b = (const float*)d_in[off + 13];
    const float* W1 = (const float*)d_in[off + 14];
    const float* b1 = (const float*)d_in[off + 15];
    const float* W2 = (const float*)d_in[off + 16];
    const float* b2 = (const float*)d_in[off + 17];
    const float* ln2w = (const float*)d_in[off + 18];
    const float* ln2b = (const float*)d_in[off + 19];

    float *pattnout, *px, *pf;
    cudaGetSymbolAddress((void**)&pattnout, g_attnout);
    cudaGetSymbolAddress((void**)&px, g_x);
    cudaGetSymbolAddress((void**)&pf, g_f);

    __half *aq,*ak,*av;
    __half *wqh,*wkh,*wvh,*woh,*w1h,*w2h;
    __half *chi,*xh,*hh,*qhi,*qlo,*khi,*vhi;
    cudaGetSymbolAddress((void**)&aq, g_aq);
    cudaGetSymbolAddress((void**)&ak, g_ak);
    cudaGetSymbolAddress((void**)&av, g_av);
    cudaGetSymbolAddress((void**)&wqh, g_wq_h);
    cudaGetSymbolAddress((void**)&wkh, g_wk_h);
    cudaGetSymbolAddress((void**)&wvh, g_wv_h);
    cudaGetSymbolAddress((void**)&woh, g_wo_h);
    cudaGetSymbolAddress((void**)&w1h, g_w1_h);
    cudaGetSymbolAddress((void**)&w2h, g_w2_h);
    cudaGetSymbolAddress((void**)&chi, g_chi);
    cudaGetSymbolAddress((void**)&xh, g_xh);
    cudaGetSymbolAddress((void**)&hh, g_hh);
    cudaGetSymbolAddress((void**)&qhi, g_qhi);   cudaGetSymbolAddress((void**)&qlo, g_qlo);
    cudaGetSymbolAddress((void**)&khi, g_khi);
    cudaGetSymbolAddress((void**)&vhi, g_vhi);

    const int M = BB * SS;   // 4096
    cudaFuncSetAttribute(gemm_mma<false,false>, cudaFuncAttributeMaxDynamicSharedMemorySize, G_SMEM);
    cudaFuncSetAttribute(gemm_mma<false,true>,  cudaFuncAttributeMaxDynamicSharedMemorySize, G_SMEM);
    cudaFuncSetAttribute(gemm_mma<true,true>,   cudaFuncAttributeMaxDynamicSharedMemorySize, G_SMEM);
    cudaFuncSetAttribute(attn_kernel, cudaFuncAttributeMaxDynamicSharedMemorySize, AT_SMEM);

    // -------- 1. mega split --------
    {
        SplitArgs sa;
        const float* srcs[9] = {query, key, values, Wq, Wk, Wv, Wo, W1, W2};
        __half* his[9] = {aq, ak, av, wqh, wkh, wvh, woh, w1h, w2h};
        int nblk[9] = {4096, 4096, 4096, 1024, 1024, 1024, 1024, 4096, 4096};
        int cum = 0;
        for (int i = 0; i < 9; i++) {
            sa.seg[i].src = srcs[i]; sa.seg[i].hi = his[i];
            sa.start[i] = cum; cum += nblk[i];
        }
        sa.start[9] = cum;
        multi_split_kernel<<<cum, 256>>>(sa);
    }

    // -------- 2. QKV projections (q emits hi+lo; k, v hi only) --------
    {
        GemmIO q = {aq, wqh, bq, nullptr, qhi, qlo};
        GemmIO k = {ak, wkh, bk, nullptr, khi, nullptr};
        GemmIO v = {av, wvh, bv, nullptr, vhi, nullptr};
        gemm_mma<false,true><<<dim3(DD/128, M/256, 3), 512, G_SMEM>>>(q, k, v, M, DD, DD);
    }

    // -------- 3. attention --------
    attn_kernel<<<dim3(SS/32, HH, BB), 512, AT_SMEM>>>(qhi, qlo, khi, vhi, gammas, chi);

    // -------- 4. output projection --------
    {
        GemmIO o = {chi, woh, bo, pattnout, nullptr, nullptr};
        gemm_mma<false,false><<<dim3(DD/128, M/256, 1), 512, G_SMEM>>>(o, o, o, M, DD, DD);
    }

    // -------- 5. LN1 --------
    add_ln_kernel<true><<<M, 256>>>(query, pattnout, ln1w, ln1b, px, xh);

    // -------- 6. FFN1 (+ReLU) --------
    {
        GemmIO f1 = {xh, w1h, b1, nullptr, hh, nullptr};
        gemm_mma<true,true><<<dim3(DFFF/128, M/256, 1), 512, G_SMEM>>>(f1, f1, f1, M, DFFF, DD);
    }

    // -------- 7. FFN2 --------
    {
        GemmIO f2 = {hh, w2h, b2, pf, nullptr, nullptr};
        gemm_mma<false,false><<<dim3(DD/128, M/256, 1), 512, G_SMEM>>>(f2, f2, f2, M, DD, DFFF);
    }

    // -------- 8. LN2 --------
    add_ln_kernel<false><<<M, 256>>>(px, pf, ln2w, ln2b, (float*)d_out, nullptr);
}

// round 11
// speedup vs baseline: 4.8272x; 1.0773x over previous
#include <cuda_runtime.h>
#include <cuda_fp16.h>
#include <math.h>
#include <stdint.h>

// Problem constants
#define BB 4
#define SS 1024
#define DD 1024
#define HH 16
#define DKK 64
#define DFFF 4096
#define SCP 1032   // score row pitch (floats)

// ---------------- scratch (device globals) -----------------------------------
__device__ float g_attnout[BB*SS*DD];
__device__ float g_x[BB*SS*DD];
__device__ float g_f[BB*SS*DD];
__device__ __half g_aq[BB*SS*DD];
__device__ __half g_ak[BB*SS*DD];
__device__ __half g_av[BB*SS*DD];
__device__ __half g_wq_h[DD*DD];
__device__ __half g_wk_h[DD*DD];
__device__ __half g_wv_h[DD*DD];
__device__ __half g_wo_h[DD*DD];
__device__ __half g_w1_h[DFFF*DD];
__device__ __half g_w2_h[DD*DFFF];
__device__ __half g_chi[BB*SS*DD];
__device__ __half g_xh[BB*SS*DD];
__device__ __half g_hh[BB*SS*DFFF];
__device__ __half g_qhi[BB*SS*DD], g_qlo[BB*SS*DD];
__device__ __half g_khi[BB*SS*DD];
__device__ __half g_vhi[BB*SS*DD];

// ======================= PTX helpers ========================================
__device__ __forceinline__ uint32_t smem_u32(const void* p) {
    uint32_t a;
    asm("{ .reg .u64 t; cvta.to.shared.u64 t, %1; cvt.u32.u64 %0, t; }" : "=r"(a) : "l"(p));
    return a;
}

#define CPASYNC16(dst, src) asm volatile("cp.async.cg.shared.global [%0], [%1], 16;" :: "r"(dst), "l"(src) : "memory")
#define CPCOMMIT() asm volatile("cp.async.commit_group;" ::: "memory")
#define CPWAIT1()  asm volatile("cp.async.wait_group 1;" ::: "memory")
#define CPWAIT0()  asm volatile("cp.async.wait_group 0;" ::: "memory")

#define LDSM_X4(R, A) \
    asm volatile("ldmatrix.sync.aligned.m8n8.x4.shared.b16 {%0,%1,%2,%3}, [%4];" \
        : "=r"((R)[0]), "=r"((R)[1]), "=r"((R)[2]), "=r"((R)[3]) : "r"(A))

#define LDSM_X2T(R, A) \
    asm volatile("ldmatrix.sync.aligned.m8n8.x2.trans.shared.b16 {%0,%1}, [%2];" \
        : "=r"((R)[0]), "=r"((R)[1]) : "r"(A))

__device__ __forceinline__ void mma_f16(float* c, const uint32_t* a, const uint32_t* b) {
    asm volatile(
        "mma.sync.aligned.m16n8k16.row.col.f32.f16.f16.f32 "
        "{%0,%1,%2,%3}, {%4,%5,%6,%7}, {%8,%9}, {%0,%1,%2,%3};"
        : "+f"(c[0]), "+f"(c[1]), "+f"(c[2]), "+f"(c[3])
        : "r"(a[0]), "r"(a[1]), "r"(a[2]), "r"(a[3]), "r"(b[0]), "r"(b[1]));
}

__device__ __forceinline__ uint32_t packh2(float x, float y) {
    __half2 t = __floats2half2_rn(x, y);
    return *reinterpret_cast<uint32_t*>(&t);
}
__device__ __forceinline__ uint32_t packloh2(float x, float y, uint32_t hi) {
    __half2 h = *reinterpret_cast<__half2*>(&hi);
    return packh2(x - __half2float(h.x), y - __half2float(h.y));
}

// ================ mega split: fp32 -> single fp16 ===========================
struct SplitSeg { const float* src; __half* hi; };
struct SplitArgs { SplitSeg seg[9]; int start[10]; };

__global__ void __launch_bounds__(256) multi_split_kernel(SplitArgs a)
{
    int bx = blockIdx.x;
    int s = 0;
#pragma unroll
    for (int i = 0; i < 8; i++) if (bx >= a.start[i+1]) s = i+1;
    SplitSeg sg = a.seg[s];
    int i = (bx - a.start[s]) * 256 + threadIdx.x;
    float4 v = ((const float4*)sg.src)[i];
    uint32_t h0 = packh2(v.x, v.y), h1 = packh2(v.z, v.w);
    ((uint32_t*)sg.hi)[i*2+0] = h0;
    ((uint32_t*)sg.hi)[i*2+1] = h1;
}

// ====== fp16 GEMM: C = A @ W^T + bias, tile 256x128, K-chunk 64, 3 stages ===
// stage: A[256x144B] B[128x144B] = 55296 B (144 = 128B data + 16B pad)
#define G_BH 36864
#define G_STAGE 55296
#define G_SMEM (3 * G_STAGE)   // 165888

struct GemmIO {
    const __half *Ah, *Wh;
    const float* bias;
    float* C;
    __half *Chi, *Clo;   // Clo may be null
};

template<bool RELU, bool SPLITOUT>
__global__ void __launch_bounds__(512, 1) gemm_mma(
    GemmIO io0, GemmIO io1, GemmIO io2, int M, int N, int K)
{
    extern __shared__ __align__(128) char smem[];
    uint32_t sb = smem_u32(smem);

    GemmIO io = (blockIdx.z == 0) ? io0 : (blockIdx.z == 1) ? io1 : io2;

    int tid  = threadIdx.x;
    int lane = tid & 31;
    int wid  = tid >> 5;
    int wm   = wid & 3;        // M warp (64 rows)
    int wn   = wid >> 2;       // N warp (32 cols)
    int bm = blockIdx.y * 256;
    int bn = blockIdx.x * 128;

    const int nch = K >> 6;    // K chunks of 64

    auto load_stage = [&](int c) {
        uint32_t st = sb + (c % 3) * G_STAGE;
        size_t kof = (size_t)c * 64;
        const __half* a_h = io.Ah + (size_t)bm * K + kof;
        const __half* b_h = io.Wh + (size_t)bn * K + kof;
#pragma unroll
        for (int u = 0; u < 4; u++) {
            int l = tid + u * 512;       // 0..2047
            int row = l >> 3, ch = l & 7;
            CPASYNC16(st + row*144 + ch*16, (const char*)(a_h + (size_t)row*K) + ch*16);
        }
#pragma unroll
        for (int u = 0; u < 2; u++) {
            int l = tid + u * 512;       // 0..1023
            int row = l >> 3, ch = l & 7;
            CPASYNC16(st + G_BH + row*144 + ch*16, (const char*)(b_h + (size_t)row*K) + ch*16);
        }
        CPCOMMIT();
    };

    uint32_t aoff = ((((lane >> 3) & 1) * 8 + (lane & 7)) * 144) + (lane >> 4) * 16;
    uint32_t boff = (((lane >> 4) * 8 + (lane & 7)) * 144) + ((lane >> 3) & 1) * 16;

    float acc[4][4][4];
#pragma unroll
    for (int mt = 0; mt < 4; mt++)
#pragma unroll
        for (int n8 = 0; n8 < 4; n8++)
#pragma unroll
            for (int k = 0; k < 4; k++) acc[mt][n8][k] = 0.f;

    load_stage(0);
    load_stage(1);
    for (int c = 0; c < nch; c++) {
        if (c + 1 < nch) { CPWAIT1(); } else { CPWAIT0(); }
        __syncthreads();
        if (c + 2 < nch) load_stage(c + 2);

        uint32_t st = sb + (c % 3) * G_STAGE;
        uint32_t aH = st        + (wm * 64) * 144 + aoff;
        uint32_t bH = st + G_BH + (wn * 32) * 144 + boff;

#pragma unroll
        for (int ks = 0; ks < 4; ks++) {
            uint32_t ah[4][4];
#pragma unroll
            for (int mt = 0; mt < 4; mt++)
                LDSM_X4(ah[mt], aH + mt * (16*144) + ks * 32);
#pragma unroll
            for (int g = 0; g < 2; g++) {
                uint32_t bh[4];
                LDSM_X4(bh, bH + g * (16*144) + ks * 32);
#pragma unroll
                for (int mt = 0; mt < 4; mt++)
#pragma unroll
                    for (int hf = 0; hf < 2; hf++)
                        mma_f16(acc[mt][g*2+hf], ah[mt], &bh[hf*2]);
            }
        }
    }

    int r_in = lane >> 2;
    int c_in = (lane & 3) * 2;
    bool wlo = SPLITOUT && (io.Clo != nullptr);
#pragma unroll
    for (int mt = 0; mt < 4; mt++) {
        int R0 = bm + wm * 64 + mt * 16 + r_in;
        int R1 = R0 + 8;
#pragma unroll
        for (int n8 = 0; n8 < 4; n8++) {
            int col = bn + wn * 32 + n8 * 8 + c_in;
            float b0 = io.bias[col], b1 = io.bias[col + 1];
            float o00 = acc[mt][n8][0] + b0, o01 = acc[mt][n8][1] + b1;
            float o10 = acc[mt][n8][2] + b0, o11 = acc[mt][n8][3] + b1;
            if (RELU) {
                o00 = fmaxf(o00, 0.f); o01 = fmaxf(o01, 0.f);
                o10 = fmaxf(o10, 0.f); o11 = fmaxf(o11, 0.f);
            }
            if (SPLITOUT) {
                uint32_t h0 = packh2(o00, o01), h1 = packh2(o10, o11);
                *(uint32_t*)&io.Chi[(size_t)R0 * N + col] = h0;
                *(uint32_t*)&io.Chi[(size_t)R1 * N + col] = h1;
                if (wlo) {
                    uint32_t l0 = packloh2(o00, o01, h0), l1 = packloh2(o10, o11, h1);
                    *(uint32_t*)&io.Clo[(size_t)R0 * N + col] = l0;
                    *(uint32_t*)&io.Clo[(size_t)R1 * N + col] = l1;
                }
            } else {
                float2 o0, o1;
                o0.x = o00; o0.y = o01; o1.x = o10; o1.y = o11;
                *(float2*)&io.C[(size_t)R0 * N + col] = o0;
                *(float2*)&io.C[(size_t)R1 * N + col] = o1;
            }
        }
    }
}

// ================= tensor-core distance-decay attention ======================
// 512 threads (16 warps), 32 rows/CTA, K/V tiles of 256 rows (2 buffers).
// QK: 2-term (q hi/lo x k hi). PV: probs hi/lo x V single.
#define AT_QH 132096
#define AT_QL 136704
#define AT_K  141312
#define AT_KSZ 36864     // 256 rows x 144B per buffer
#define AT_SMEM 215040

__global__ void __launch_bounds__(512, 1) attn_kernel(
    const __half* __restrict__ qhi, const __half* __restrict__ qlo,
    const __half* __restrict__ khi, const __half* __restrict__ vhi,
    const float* __restrict__ gammas,
    __half* __restrict__ ohi)
{
    extern __shared__ __align__(128) char smx[];
    float* sc = (float*)smx;
    uint32_t sb = smem_u32(smx);
    const uint32_t QH = sb + AT_QH;
    const uint32_t QL = sb + AT_QL;

    int b = blockIdx.z, h = blockIdx.y, i0 = blockIdx.x * 32;
    int t = threadIdx.x, lane = t & 31, w = t >> 5;   // w: 0..15
    int mt = w & 1;          // row half (16 rows)
    int cg = w >> 1;         // col group (16 cols within 128-col block)

    size_t base_q = ((size_t)b*SS + i0)*DD + h*64;
    size_t base_k = (size_t)b*SS*DD + h*64;

    // ---- load Q tile (32 rows, hi+lo)
    {
        int sel = t >> 8;
        int idx = t & 255;
        int row = idx >> 3, ch = idx & 7;
        const __half* src = (sel ? qlo : qhi) + base_q + (size_t)row*DD + ch*8;
        char* dst = smx + (sel ? AT_QL : AT_QH) + row*144 + ch*16;
        *(float4*)dst = *(const float4*)src;
    }
    __syncthreads();

    uint32_t aoff = ((((lane >> 3) & 1) * 8 + (lane & 7)) * 144) + (lane >> 4) * 16;
    uint32_t boff = (((lane >> 4) * 8 + (lane & 7)) * 144) + ((lane >> 3) & 1) * 16;

    uint32_t ah[4][4], al[4][4];
#pragma unroll
    for (int ks = 0; ks < 4; ks++) {
        LDSM_X4(ah[ks], QH + mt*(16*144) + aoff + ks*32);
        LDSM_X4(al[ks], QL + mt*(16*144) + aoff + ks*32);
    }

    // K tile loader (256 rows) into buffer bf
    auto loadK = [&](int jt, int bf) {
        uint32_t KH = sb + AT_K + bf * AT_KSZ;
        int jbase = jt * 256;
#pragma unroll
        for (int u = 0; u < 4; u++) {
            int l = t + u * 512;                 // 0..2047
            int row = l >> 3, ch = l & 7;
            const char* sh = (const char*)(khi + base_k + (size_t)(jbase+row)*DD) + ch*16;
            CPASYNC16(KH + row*144 + ch*16, sh);
        }
        CPCOMMIT();
    };

    // ---- QK^T: 4 tiles of 256 cols, double-buffered
    loadK(0, 0);
    for (int jt = 0; jt < 4; jt++) {
        CPWAIT0();
        __syncthreads();
        if (jt + 1 < 4) loadK(jt + 1, (jt + 1) & 1);

        uint32_t KH = sb + AT_K + (jt & 1) * AT_KSZ;
#pragma unroll
        for (int half = 0; half < 2; half++) {
            float c0[4] = {0,0,0,0}, c1[4] = {0,0,0,0};
            uint32_t bb = (uint32_t)(half*128 + cg*16)*144 + boff;
#pragma unroll
            for (int ks = 0; ks < 4; ks++) {
                uint32_t bh[4];
                LDSM_X4(bh, KH + bb + ks*32);
                mma_f16(c0, ah[ks], &bh[0]);
                mma_f16(c0, al[ks], &bh[0]);
                mma_f16(c1, ah[ks], &bh[2]);
                mma_f16(c1, al[ks], &bh[2]);
            }
            int r0 = mt*16 + (lane >> 2);
            int cb = jt*256 + half*128 + cg*16 + (lane & 3)*2;
            float2 v2;
            v2.x = c0[0]*0.125f; v2.y = c0[1]*0.125f; *(float2*)&sc[r0*SCP + cb] = v2;
            v2.x = c0[2]*0.125f; v2.y = c0[3]*0.125f; *(float2*)&sc[(r0+8)*SCP + cb] = v2;
            v2.x = c1[0]*0.125f; v2.y = c1[1]*0.125f; *(float2*)&sc[r0*SCP + cb + 8] = v2;
            v2.x = c1[2]*0.125f; v2.y = c1[3]*0.125f; *(float2*)&sc[(r0+8)*SCP + cb + 8] = v2;
        }
    }

    // V tile loader (single fp16, up to 256 rows)
    int jmax = i0 + 32;
    auto loadV = [&](int jbase, int rows, int bf) {
        uint32_t VH = sb + AT_K + bf * AT_KSZ;
        int total = rows * 8;
#pragma unroll
        for (int u = 0; u < 4; u++) {
            int l = t + u * 512;
            if (l < total) {
                int row = l >> 3, ch = l & 7;
                const char* sh = (const char*)(vhi + base_k + (size_t)(jbase+row)*DD) + ch*16;
                CPASYNC16(VH + row*144 + ch*16, sh);
            }
        }
        CPCOMMIT();
    };

    // prefetch V tile 0 into buffer 0 (jt=3 used buffer 1) — hidden under row math
    loadV(0, jmax < 256 ? jmax : 256, 0);
    __syncthreads();   // sc writes visible before row math

    // ---- per-row math: 2 rows per warp
    {
        float gamma = -log1pf(__expf(gammas[h]));
        for (int rr2 = 0; rr2 < 2; rr2++) {
            int r  = w*2 + rr2;
            int ig = i0 + r;
            float* row = sc + r*SCP;

            float s[32], p[32];
            float m = -INFINITY;
#pragma unroll
            for (int c = 0; c < 32; c++) {
                s[c] = row[c*32 + lane];
                m = fmaxf(m, s[c]);
            }
#pragma unroll
            for (int o = 16; o > 0; o >>= 1) m = fmaxf(m, __shfl_xor_sync(0xffffffffu, m, o));

            float sum1 = 0.f, summ = 0.f;
#pragma unroll
            for (int c = 0; c < 32; c++) {
                p[c] = __expf(s[c] - m);
                sum1 += p[c];
                if (c*32 + lane <= ig) summ += p[c];
            }
#pragma unroll
            for (int o = 16; o > 0; o >>= 1) {
                sum1 += __shfl_xor_sync(0xffffffffu, sum1, o);
                summ += __shfl_xor_sync(0xffffffffu, summ, o);
            }
            float inv1 = 1.f / sum1;

            // independent per-chunk inclusive scans
#pragma unroll
            for (int c = 0; c < 32; c++) {
                if (c*32 <= ig) {
                    int j = c*32 + lane;
                    float x = (j <= ig) ? p[c] : 0.f;
#pragma unroll
                    for (int o = 1; o < 32; o <<= 1) {
                        float y = __shfl_up_sync(0xffffffffu, x, o);
                        if (lane >= o) x += y;
                    }
                    p[c] = x;
                }
            }
            // decay transform with light serial carry
            float carry = 0.f, m2 = -INFINITY;
#pragma unroll
            for (int c = 0; c < 32; c++) {
                if (c*32 <= ig) {
                    int j = c*32 + lane;
                    float tch = __shfl_sync(0xffffffffu, p[c], 31);
                    float distcum = carry + p[c];
                    carry += tch;
                    float pos  = fabsf((float)(ig - j));
                    float dd   = (summ - distcum) * inv1 * pos;
                    float dist = sqrtf(fmaxf(dd, 0.f));
                    float eff  = __expf(dist * gamma);
                    eff = fminf(fmaxf(eff, 1e-5f), 1e5f);
                    float s2 = (j <= ig) ? s[c] * eff : -INFINITY;
                    s[c] = s2;
                    m2 = fmaxf(m2, s2);
                } else {
                    s[c] = -INFINITY;
                }
            }
#pragma unroll
            for (int o = 16; o > 0; o >>= 1) m2 = fmaxf(m2, __shfl_xor_sync(0xffffffffu, m2, o));

            float sum2 = 0.f;
#pragma unroll
            for (int c = 0; c < 32; c++) {
                float e = 0.f;
                if (c*32 <= ig) {
                    int j = c*32 + lane;
                    e = (j <= ig) ? __expf(s[c] - m2) : 0.f;
                }
                p[c] = e;
                sum2 += e;
            }
#pragma unroll
            for (int o = 16; o > 0; o >>= 1) sum2 += __shfl_xor_sync(0xffffffffu, sum2, o);
            float inv2 = 1.f / sum2;
#pragma unroll
            for (int c = 0; c < 32; c++) row[c*32 + lane] = p[c] * inv2;
        }
    }

    // ---- PV: warp w -> row half mt (16 rows), cols cg*8..cg*8+7
    float acc[4] = {0.f, 0.f, 0.f, 0.f};
    int rr = lane >> 2, kc = (lane & 3) * 2;
    int vrow = lane & 15;
    int ntiles = (jmax + 255) >> 8;
    for (int ji = 0; ji < ntiles; ji++) {
        int jbase = ji * 256;
        int rows = jmax - jbase; if (rows > 256) rows = 256;
        CPWAIT0();
        __syncthreads();
        if (ji + 1 < ntiles) {
            int nb = jbase + 256;
            int nrows = jmax - nb; if (nrows > 256) nrows = 256;
            loadV(nb, nrows, (ji + 1) & 1);
        }
        uint32_t VH = sb + AT_K + (ji & 1) * AT_KSZ;

        int nk = rows >> 4;
        for (int kk = 0; kk < nk; kk++) {
            int j0 = jbase + kk*16;
            uint32_t vh[2];
            uint32_t va = (uint32_t)(kk*16 + vrow)*144 + (uint32_t)cg*16;
            LDSM_X2T(vh, VH + va);
            const float* p0 = &sc[(mt*16 + rr)*SCP + j0 + kc];
            float f00 = p0[0],        f01 = p0[1];
            float f10 = p0[8*SCP],    f11 = p0[8*SCP+1];
            float f20 = p0[8],        f21 = p0[9];
            float f30 = p0[8*SCP+8],  f31 = p0[8*SCP+9];
            uint32_t a_h[4], a_l[4];
            a_h[0] = packh2(f00, f01); a_l[0] = packloh2(f00, f01, a_h[0]);
            a_h[1] = packh2(f10, f11); a_l[1] = packloh2(f10, f11, a_h[1]);
            a_h[2] = packh2(f20, f21); a_l[2] = packloh2(f20, f21, a_h[2]);
            a_h[3] = packh2(f30, f31); a_l[3] = packloh2(f30, f31, a_h[3]);
            mma_f16(acc, a_h, vh);
            mma_f16(acc, a_l, vh);
        }
    }

    // ---- epilogue -> concat single fp16
    {
        size_t o0 = ((size_t)b*SS + i0 + mt*16 + rr)*DD + h*64 + cg*8 + kc;
        size_t o1 = o0 + (size_t)8*DD;
        *(uint32_t*)&ohi[o0] = packh2(acc[0], acc[1]);
        *(uint32_t*)&ohi[o1] = packh2(acc[2], acc[3]);
    }
}

// ---------------- residual add + LayerNorm ----------------------------------
template<bool SPLITOUT>
__global__ void __launch_bounds__(256) add_ln_kernel(
    const float* __restrict__ A, const float* __restrict__ Bres,
    const float* __restrict__ w, const float* __restrict__ bias,
    float* __restrict__ outp,
    __half* __restrict__ ohi)
{
    __shared__ float red1[8], red2[8];
    int row = blockIdx.x;
    int t   = threadIdx.x;
    const float* pa = A    + (size_t)row*DD;
    const float* pb = Bres + (size_t)row*DD;

    float4 a4 = *(const float4*)&pa[t*4];
    float4 b4 = *(const float4*)&pb[t*4];
    float v0 = a4.x + b4.x, v1 = a4.y + b4.y, v2 = a4.z + b4.z, v3 = a4.w + b4.w;

    int lane = t & 31, wp = t >> 5;
    float s = v0 + v1 + v2 + v3;
#pragma unroll
    for (int o = 16; o > 0; o >>= 1) s += __shfl_xor_sync(0xffffffffu, s, o);
    if (lane == 0) red1[wp] = s;
    __syncthreads();
    float tot = 0.f;
#pragma unroll
    for (int i = 0; i < 8; i++) tot += red1[i];
    float mu = tot * (1.f / DD);

    float d0 = v0-mu, d1 = v1-mu, d2 = v2-mu, d3 = v3-mu;
    float q2 = d0*d0 + d1*d1 + d2*d2 + d3*d3;
#pragma unroll
    for (int o = 16; o > 0; o >>= 1) q2 += __shfl_xor_sync(0xffffffffu, q2, o);
    if (lane == 0) red2[wp] = q2;
    __syncthreads();
    float tv = 0.f;
#pragma unroll
    for (int i = 0; i < 8; i++) tv += red2[i];
    float inv = rsqrtf(tv * (1.f / DD) + 1e-5f);

    float4 w4  = *(const float4*)&w[t*4];
    float4 bi4 = *(const float4*)&bias[t*4];
    float4 o4;
    o4.x = d0*inv*w4.x + bi4.x;
    o4.y = d1*inv*w4.y + bi4.y;
    o4.z = d2*inv*w4.z + bi4.z;
    o4.w = d3*inv*w4.w + bi4.w;
    *(float4*)&outp[(size_t)row*DD + t*4] = o4;

    if (SPLITOUT) {
        uint32_t h0 = packh2(o4.x, o4.y), h1 = packh2(o4.z, o4.w);
        size_t base2 = (size_t)row * (DD/2) + t*2;
        ((uint32_t*)ohi)[base2]     = h0;
        ((uint32_t*)ohi)[base2 + 1] = h1;
    }
}

// ---------------- launcher ---------------------------------------------------
extern "C" void kernel_launch(void* const* d_in, const int* in_sizes, int n_in,
                              void* d_out, int out_size)
{
    int off = (in_sizes[0] == 1) ? 1 : 0;
    const float* query  = (const float*)d_in[off + 0];
    const float* key    = (const float*)d_in[off + 1];
    const float* values = (const float*)d_in[off + 2];
    const float* Wq = (const float*)d_in[off + 3];
    const float* bq = (const float*)d_in[off + 4];
    const float* Wk = (const float*)d_in[off + 5];
    const float* bk = (const float*)d_in[off + 6];
    const float* Wv = (const float*)d_in[off + 7];
    const float* bv = (const float*)d_in[off + 8];
    const float* Wo = (const float*)d_in[off + 9];
    const float* bo = (const float*)d_in[off + 10];
    const float* gammas = (const float*)d_in[off + 11];
    const float* ln1w = (const float*)d_in[off + 12];
    const float* ln1b = (const float*)d_in[off + 13];
    const float* W1 = (const float*)d_in[off + 14];
    const float* b1 = (const float*)d_in[off + 15];
    const float* W2 = (const float*)d_in[off + 16];
    const float* b2 = (const float*)d_in[off + 17];
    const float* ln2w = (const float*)d_in[off + 18];
    const float* ln2b = (const float*)d_in[off + 19];

    float *pattnout, *px, *pf;
    cudaGetSymbolAddress((void**)&pattnout, g_attnout);
    cudaGetSymbolAddress((void**)&px, g_x);
    cudaGetSymbolAddress((void**)&pf, g_f);

    __half *aq,*ak,*av;
    __half *wqh,*wkh,*wvh,*woh,*w1h,*w2h;
    __half *chi,*xh,*hh,*qhi,*qlo,*khi,*vhi;
    cudaGetSymbolAddress((void**)&aq, g_aq);
    cudaGetSymbolAddress((void**)&ak, g_ak);
    cudaGetSymbolAddress((void**)&av, g_av);
    cudaGetSymbolAddress((void**)&wqh, g_wq_h);
    cudaGetSymbolAddress((void**)&wkh, g_wk_h);
    cudaGetSymbolAddress((void**)&wvh, g_wv_h);
    cudaGetSymbolAddress((void**)&woh, g_wo_h);
    cudaGetSymbolAddress((void**)&w1h, g_w1_h);
    cudaGetSymbolAddress((void**)&w2h, g_w2_h);
    cudaGetSymbolAddress((void**)&chi, g_chi);
    cudaGetSymbolAddress((void**)&xh, g_xh);
    cudaGetSymbolAddress((void**)&hh, g_hh);
    cudaGetSymbolAddress((void**)&qhi, g_qhi);   cudaGetSymbolAddress((void**)&qlo, g_qlo);
    cudaGetSymbolAddress((void**)&khi, g_khi);
    cudaGetSymbolAddress((void**)&vhi, g_vhi);

    const int M = BB * SS;   // 4096
    cudaFuncSetAttribute(gemm_mma<false,false>, cudaFuncAttributeMaxDynamicSharedMemorySize, G_SMEM);
    cudaFuncSetAttribute(gemm_mma<false,true>,  cudaFuncAttributeMaxDynamicSharedMemorySize, G_SMEM);
    cudaFuncSetAttribute(gemm_mma<true,true>,   cudaFuncAttributeMaxDynamicSharedMemorySize, G_SMEM);
    cudaFuncSetAttribute(attn_kernel, cudaFuncAttributeMaxDynamicSharedMemorySize, AT_SMEM);

    // -------- 1. mega split --------
    {
        SplitArgs sa;
        const float* srcs[9] = {query, key, values, Wq, Wk, Wv, Wo, W1, W2};
        __half* his[9] = {aq, ak, av, wqh, wkh, wvh, woh, w1h, w2h};
        int nblk[9] = {4096, 4096, 4096, 1024, 1024, 1024, 1024, 4096, 4096};
        int cum = 0;
        for (int i = 0; i < 9; i++) {
            sa.seg[i].src = srcs[i]; sa.seg[i].hi = his[i];
            sa.start[i] = cum; cum += nblk[i];
        }
        sa.start[9] = cum;
        multi_split_kernel<<<cum, 256>>>(sa);
    }

    // -------- 2. QKV projections (q emits hi+lo; k, v hi only) --------
    {
        GemmIO q = {aq, wqh, bq, nullptr, qhi, qlo};
        GemmIO k = {ak, wkh, bk, nullptr, khi, nullptr};
        GemmIO v = {av, wvh, bv, nullptr, vhi, nullptr};
        gemm_mma<false,true><<<dim3(DD/128, M/256, 3), 512, G_SMEM>>>(q, k, v, M, DD, DD);
    }

    // -------- 3. attention --------
    attn_kernel<<<dim3(SS/32, HH, BB), 512, AT_SMEM>>>(qhi, qlo, khi, vhi, gammas, chi);

    // -------- 4. output projection --------
    {
        GemmIO o = {chi, woh, bo, pattnout, nullptr, nullptr};
        gemm_mma<false,false><<<dim3(DD/128, M/256, 1), 512, G_SMEM>>>(o, o, o, M, DD, DD);
    }

    // -------- 5. LN1 --------
    add_ln_kernel<true><<<M, 256>>>(query, pattnout, ln1w, ln1b, px, xh);

    // -------- 6. FFN1 (+ReLU) --------
    {
        GemmIO f1 = {xh, w1h, b1, nullptr, hh, nullptr};
        gemm_mma<true,true><<<dim3(DFFF/128, M/256, 1), 512, G_SMEM>>>(f1, f1, f1, M, DFFF, DD);
    }

    // -------- 7. FFN2 --------
    {
        GemmIO f2 = {hh, w2h, b2, pf, nullptr, nullptr};
        gemm_mma<false,false><<<dim3(DD/128, M/256, 1), 512, G_SMEM>>>(f2, f2, f2, M, DD, DFFF);
    }

    // -------- 8. LN2 --------
    add_ln_kernel<false><<<M, 256>>>(px, pf, ln2w, ln2b, (float*)d_out, nullptr);
}

// round 12
// speedup vs baseline: 4.9709x; 1.0298x over previous
#include <cuda_runtime.h>
#include <cuda_fp16.h>
#include <math.h>
#include <stdint.h>

// Problem constants
#define BB 4
#define SS 1024
#define DD 1024
#define HH 16
#define DKK 64
#define DFFF 4096
#define SCP 1032   // score row pitch (floats)

// ---------------- scratch (device globals) -----------------------------------
__device__ float g_attnout[BB*SS*DD];
__device__ float g_x[BB*SS*DD];
__device__ float g_f[BB*SS*DD];
__device__ __half g_aq[BB*SS*DD];
__device__ __half g_ak[BB*SS*DD];
__device__ __half g_av[BB*SS*DD];
__device__ __half g_wq_h[DD*DD];
__device__ __half g_wk_h[DD*DD];
__device__ __half g_wv_h[DD*DD];
__device__ __half g_wo_h[DD*DD];
__device__ __half g_w1_h[DFFF*DD];
__device__ __half g_w2_h[DD*DFFF];
__device__ __half g_chi[BB*SS*DD];
__device__ __half g_xh[BB*SS*DD];
__device__ __half g_hh[BB*SS*DFFF];
__device__ __half g_qhi[BB*SS*DD], g_qlo[BB*SS*DD];
__device__ __half g_khi[BB*SS*DD];
__device__ __half g_vhi[BB*SS*DD];

// ======================= PTX helpers ========================================
__device__ __forceinline__ uint32_t smem_u32(const void* p) {
    uint32_t a;
    asm("{ .reg .u64 t; cvta.to.shared.u64 t, %1; cvt.u32.u64 %0, t; }" : "=r"(a) : "l"(p));
    return a;
}

#define CPASYNC16(dst, src) asm volatile("cp.async.cg.shared.global [%0], [%1], 16;" :: "r"(dst), "l"(src) : "memory")
#define CPCOMMIT() asm volatile("cp.async.commit_group;" ::: "memory")
#define CPWAIT1()  asm volatile("cp.async.wait_group 1;" ::: "memory")
#define CPWAIT0()  asm volatile("cp.async.wait_group 0;" ::: "memory")

#define LDSM_X4(R, A) \
    asm volatile("ldmatrix.sync.aligned.m8n8.x4.shared.b16 {%0,%1,%2,%3}, [%4];" \
        : "=r"((R)[0]), "=r"((R)[1]), "=r"((R)[2]), "=r"((R)[3]) : "r"(A))

#define LDSM_X2T(R, A) \
    asm volatile("ldmatrix.sync.aligned.m8n8.x2.trans.shared.b16 {%0,%1}, [%2];" \
        : "=r"((R)[0]), "=r"((R)[1]) : "r"(A))

__device__ __forceinline__ void mma_f16(float* c, const uint32_t* a, const uint32_t* b) {
    asm volatile(
        "mma.sync.aligned.m16n8k16.row.col.f32.f16.f16.f32 "
        "{%0,%1,%2,%3}, {%4,%5,%6,%7}, {%8,%9}, {%0,%1,%2,%3};"
        : "+f"(c[0]), "+f"(c[1]), "+f"(c[2]), "+f"(c[3])
        : "r"(a[0]), "r"(a[1]), "r"(a[2]), "r"(a[3]), "r"(b[0]), "r"(b[1]));
}

__device__ __forceinline__ uint32_t packh2(float x, float y) {
    __half2 t = __floats2half2_rn(x, y);
    return *reinterpret_cast<uint32_t*>(&t);
}
__device__ __forceinline__ uint32_t packloh2(float x, float y, uint32_t hi) {
    __half2 h = *reinterpret_cast<__half2*>(&hi);
    return packh2(x - __half2float(h.x), y - __half2float(h.y));
}

// ================ mega split: fp32 -> single fp16 ===========================
struct SplitSeg { const float* src; __half* hi; };
struct SplitArgs { SplitSeg seg[9]; int start[10]; };

__global__ void __launch_bounds__(256) multi_split_kernel(SplitArgs a)
{
    int bx = blockIdx.x;
    int s = 0;
#pragma unroll
    for (int i = 0; i < 8; i++) if (bx >= a.start[i+1]) s = i+1;
    SplitSeg sg = a.seg[s];
    int i = (bx - a.start[s]) * 256 + threadIdx.x;
    float4 v = ((const float4*)sg.src)[i];
    uint32_t h0 = packh2(v.x, v.y), h1 = packh2(v.z, v.w);
    ((uint32_t*)sg.hi)[i*2+0] = h0;
    ((uint32_t*)sg.hi)[i*2+1] = h1;
}

// ====== fp16 GEMM: C = A @ W^T + bias, tile 256x128, K-chunk 64, 3 stages ===
#define G_BH 36864
#define G_STAGE 55296
#define G_SMEM (3 * G_STAGE)   // 165888

struct GemmIO {
    const __half *Ah, *Wh;
    const float* bias;
    float* C;
    __half *Chi, *Clo;   // Clo may be null
};

template<bool RELU, bool SPLITOUT>
__global__ void __launch_bounds__(512, 1) gemm_mma(
    GemmIO io0, GemmIO io1, GemmIO io2, int M, int N, int K)
{
    extern __shared__ __align__(128) char smem[];
    uint32_t sb = smem_u32(smem);

    GemmIO io = (blockIdx.z == 0) ? io0 : (blockIdx.z == 1) ? io1 : io2;

    int tid  = threadIdx.x;
    int lane = tid & 31;
    int wid  = tid >> 5;
    int wm   = wid & 3;
    int wn   = wid >> 2;
    int bm = blockIdx.y * 256;
    int bn = blockIdx.x * 128;

    const int nch = K >> 6;

    auto load_stage = [&](int c) {
        uint32_t st = sb + (c % 3) * G_STAGE;
        size_t kof = (size_t)c * 64;
        const __half* a_h = io.Ah + (size_t)bm * K + kof;
        const __half* b_h = io.Wh + (size_t)bn * K + kof;
#pragma unroll
        for (int u = 0; u < 4; u++) {
            int l = tid + u * 512;
            int row = l >> 3, ch = l & 7;
            CPASYNC16(st + row*144 + ch*16, (const char*)(a_h + (size_t)row*K) + ch*16);
        }
#pragma unroll
        for (int u = 0; u < 2; u++) {
            int l = tid + u * 512;
            int row = l >> 3, ch = l & 7;
            CPASYNC16(st + G_BH + row*144 + ch*16, (const char*)(b_h + (size_t)row*K) + ch*16);
        }
        CPCOMMIT();
    };

    uint32_t aoff = ((((lane >> 3) & 1) * 8 + (lane & 7)) * 144) + (lane >> 4) * 16;
    uint32_t boff = (((lane >> 4) * 8 + (lane & 7)) * 144) + ((lane >> 3) & 1) * 16;

    float acc[4][4][4];
#pragma unroll
    for (int mt = 0; mt < 4; mt++)
#pragma unroll
        for (int n8 = 0; n8 < 4; n8++)
#pragma unroll
            for (int k = 0; k < 4; k++) acc[mt][n8][k] = 0.f;

    load_stage(0);
    load_stage(1);
    for (int c = 0; c < nch; c++) {
        if (c + 1 < nch) { CPWAIT1(); } else { CPWAIT0(); }
        __syncthreads();
        if (c + 2 < nch) load_stage(c + 2);

        uint32_t st = sb + (c % 3) * G_STAGE;
        uint32_t aH = st        + (wm * 64) * 144 + aoff;
        uint32_t bH = st + G_BH + (wn * 32) * 144 + boff;

#pragma unroll
        for (int ks = 0; ks < 4; ks++) {
            uint32_t ah[4][4];
#pragma unroll
            for (int mt = 0; mt < 4; mt++)
                LDSM_X4(ah[mt], aH + mt * (16*144) + ks * 32);
#pragma unroll
            for (int g = 0; g < 2; g++) {
                uint32_t bh[4];
                LDSM_X4(bh, bH + g * (16*144) + ks * 32);
#pragma unroll
                for (int mt = 0; mt < 4; mt++)
#pragma unroll
                    for (int hf = 0; hf < 2; hf++)
                        mma_f16(acc[mt][g*2+hf], ah[mt], &bh[hf*2]);
            }
        }
    }

    int r_in = lane >> 2;
    int c_in = (lane & 3) * 2;
    bool wlo = SPLITOUT && (io.Clo != nullptr);
#pragma unroll
    for (int mt = 0; mt < 4; mt++) {
        int R0 = bm + wm * 64 + mt * 16 + r_in;
        int R1 = R0 + 8;
#pragma unroll
        for (int n8 = 0; n8 < 4; n8++) {
            int col = bn + wn * 32 + n8 * 8 + c_in;
            float b0 = io.bias[col], b1 = io.bias[col + 1];
            float o00 = acc[mt][n8][0] + b0, o01 = acc[mt][n8][1] + b1;
            float o10 = acc[mt][n8][2] + b0, o11 = acc[mt][n8][3] + b1;
            if (RELU) {
                o00 = fmaxf(o00, 0.f); o01 = fmaxf(o01, 0.f);
                o10 = fmaxf(o10, 0.f); o11 = fmaxf(o11, 0.f);
            }
            if (SPLITOUT) {
                uint32_t h0 = packh2(o00, o01), h1 = packh2(o10, o11);
                *(uint32_t*)&io.Chi[(size_t)R0 * N + col] = h0;
                *(uint32_t*)&io.Chi[(size_t)R1 * N + col] = h1;
                if (wlo) {
                    uint32_t l0 = packloh2(o00, o01, h0), l1 = packloh2(o10, o11, h1);
                    *(uint32_t*)&io.Clo[(size_t)R0 * N + col] = l0;
                    *(uint32_t*)&io.Clo[(size_t)R1 * N + col] = l1;
                }
            } else {
                float2 o0, o1;
                o0.x = o00; o0.y = o01; o1.x = o10; o1.y = o11;
                *(float2*)&io.C[(size_t)R0 * N + col] = o0;
                *(float2*)&io.C[(size_t)R1 * N + col] = o1;
            }
        }
    }
}

// ================= tensor-core distance-decay attention ======================
// 512 threads (16 warps), 32 rows/CTA, K/V tiles of 256 rows (2 buffers).
// QK: 2-term (q hi/lo x k hi). PV: probs hi/lo x V single.
// Row math is ARRAY-FREE: streams from smem, recomputes exp (no reg spills).
#define AT_QH 132096
#define AT_QL 136704
#define AT_K  141312
#define AT_KSZ 36864
#define AT_SMEM 215040

__global__ void __launch_bounds__(512, 1) attn_kernel(
    const __half* __restrict__ qhi, const __half* __restrict__ qlo,
    const __half* __restrict__ khi, const __half* __restrict__ vhi,
    const float* __restrict__ gammas,
    __half* __restrict__ ohi)
{
    extern __shared__ __align__(128) char smx[];
    float* sc = (float*)smx;
    uint32_t sb = smem_u32(smx);
    const uint32_t QH = sb + AT_QH;
    const uint32_t QL = sb + AT_QL;

    int b = blockIdx.z, h = blockIdx.y, i0 = blockIdx.x * 32;
    int t = threadIdx.x, lane = t & 31, w = t >> 5;
    int mt = w & 1;
    int cg = w >> 1;

    size_t base_q = ((size_t)b*SS + i0)*DD + h*64;
    size_t base_k = (size_t)b*SS*DD + h*64;

    // ---- load Q tile (32 rows, hi+lo)
    {
        int sel = t >> 8;
        int idx = t & 255;
        int row = idx >> 3, ch = idx & 7;
        const __half* src = (sel ? qlo : qhi) + base_q + (size_t)row*DD + ch*8;
        char* dst = smx + (sel ? AT_QL : AT_QH) + row*144 + ch*16;
        *(float4*)dst = *(const float4*)src;
    }
    __syncthreads();

    uint32_t aoff = ((((lane >> 3) & 1) * 8 + (lane & 7)) * 144) + (lane >> 4) * 16;
    uint32_t boff = (((lane >> 4) * 8 + (lane & 7)) * 144) + ((lane >> 3) & 1) * 16;

    uint32_t ah[4][4], al[4][4];
#pragma unroll
    for (int ks = 0; ks < 4; ks++) {
        LDSM_X4(ah[ks], QH + mt*(16*144) + aoff + ks*32);
        LDSM_X4(al[ks], QL + mt*(16*144) + aoff + ks*32);
    }

    auto loadK = [&](int jt, int bf) {
        uint32_t KH = sb + AT_K + bf * AT_KSZ;
        int jbase = jt * 256;
#pragma unroll
        for (int u = 0; u < 4; u++) {
            int l = t + u * 512;
            int row = l >> 3, ch = l & 7;
            const char* sh = (const char*)(khi + base_k + (size_t)(jbase+row)*DD) + ch*16;
            CPASYNC16(KH + row*144 + ch*16, sh);
        }
        CPCOMMIT();
    };

    // ---- QK^T: 4 tiles of 256 cols, double-buffered
    loadK(0, 0);
    for (int jt = 0; jt < 4; jt++) {
        CPWAIT0();
        __syncthreads();
        if (jt + 1 < 4) loadK(jt + 1, (jt + 1) & 1);

        uint32_t KH = sb + AT_K + (jt & 1) * AT_KSZ;
#pragma unroll
        for (int half = 0; half < 2; half++) {
            float c0[4] = {0,0,0,0}, c1[4] = {0,0,0,0};
            uint32_t bb = (uint32_t)(half*128 + cg*16)*144 + boff;
#pragma unroll
            for (int ks = 0; ks < 4; ks++) {
                uint32_t bh[4];
                LDSM_X4(bh, KH + bb + ks*32);
                mma_f16(c0, ah[ks], &bh[0]);
                mma_f16(c0, al[ks], &bh[0]);
                mma_f16(c1, ah[ks], &bh[2]);
                mma_f16(c1, al[ks], &bh[2]);
            }
            int r0 = mt*16 + (lane >> 2);
            int cb = jt*256 + half*128 + cg*16 + (lane & 3)*2;
            float2 v2;
            v2.x = c0[0]*0.125f; v2.y = c0[1]*0.125f; *(float2*)&sc[r0*SCP + cb] = v2;
            v2.x = c0[2]*0.125f; v2.y = c0[3]*0.125f; *(float2*)&sc[(r0+8)*SCP + cb] = v2;
            v2.x = c1[0]*0.125f; v2.y = c1[1]*0.125f; *(float2*)&sc[r0*SCP + cb + 8] = v2;
            v2.x = c1[2]*0.125f; v2.y = c1[3]*0.125f; *(float2*)&sc[(r0+8)*SCP + cb + 8] = v2;
        }
    }

    int jmax = i0 + 32;
    auto loadV = [&](int jbase, int rows, int bf) {
        uint32_t VH = sb + AT_K + bf * AT_KSZ;
        int total = rows * 8;
#pragma unroll
        for (int u = 0; u < 4; u++) {
            int l = t + u * 512;
            if (l < total) {
                int row = l >> 3, ch = l & 7;
                const char* sh = (const char*)(vhi + base_k + (size_t)(jbase+row)*DD) + ch*16;
                CPASYNC16(VH + row*144 + ch*16, sh);
            }
        }
        CPCOMMIT();
    };

    // prefetch V tile 0 into buffer 0 (jt=3 used buffer 1) — hidden under row math
    loadV(0, jmax < 256 ? jmax : 256, 0);
    __syncthreads();   // sc writes visible before row math

    // ---- per-row math: 2 rows per warp, ARRAY-FREE (stream from smem)
    {
        float gamma = -log1pf(__expf(gammas[h]));
        for (int rr2 = 0; rr2 < 2; rr2++) {
            int r  = w*2 + rr2;
            int ig = i0 + r;
            float* row = sc + r*SCP;
            int cmask = (ig - i0 >= 0) ? (ig >> 5) : -1;       // last chunk index containing <=ig
            cmask = ig >> 5;                                    // chunks 0..cmask touch masked region

            // pass A: row max
            float m = -INFINITY;
            for (int c = 0; c < 32; c++) m = fmaxf(m, row[c*32 + lane]);
#pragma unroll
            for (int o = 16; o > 0; o >>= 1) m = fmaxf(m, __shfl_xor_sync(0xffffffffu, m, o));

            // pass B: sums (recompute exp)
            float sum1 = 0.f, summ = 0.f;
            for (int c = 0; c < 32; c++) {
                int j = c*32 + lane;
                float pfull = __expf(row[j] - m);
                sum1 += pfull;
                if (j <= ig) summ += pfull;
            }
#pragma unroll
            for (int o = 16; o > 0; o >>= 1) {
                sum1 += __shfl_xor_sync(0xffffffffu, sum1, o);
                summ += __shfl_xor_sync(0xffffffffu, summ, o);
            }
            float inv1 = 1.f / sum1;

            // pass C: fused scan + decay, overwrite s2 into smem
            float carry = 0.f, m2 = -INFINITY;
            for (int c = 0; c <= cmask; c++) {
                int j = c*32 + lane;
                float s = row[j];
                float x = (j <= ig) ? __expf(s - m) : 0.f;
#pragma unroll
                for (int o = 1; o < 32; o <<= 1) {
                    float y = __shfl_up_sync(0xffffffffu, x, o);
                    if (lane >= o) x += y;
                }
                float distcum = carry + x;
                carry += __shfl_sync(0xffffffffu, x, 31);
                float pos  = fabsf((float)(ig - j));
                float dd   = (summ - distcum) * inv1 * pos;
                float dist = sqrtf(fmaxf(dd, 0.f));
                float eff  = __expf(dist * gamma);
                eff = fminf(fmaxf(eff, 1e-5f), 1e5f);
                float s2 = (j <= ig) ? s * eff : -INFINITY;
                row[j] = s2;
                m2 = fmaxf(m2, s2);
            }
#pragma unroll
            for (int o = 16; o > 0; o >>= 1) m2 = fmaxf(m2, __shfl_xor_sync(0xffffffffu, m2, o));

            // pass D: sum2 (recompute exp of stored s2)
            float sum2 = 0.f;
            for (int c = 0; c <= cmask; c++) {
                int j = c*32 + lane;
                sum2 += (j <= ig) ? __expf(row[j] - m2) : 0.f;
            }
#pragma unroll
            for (int o = 16; o > 0; o >>= 1) sum2 += __shfl_xor_sync(0xffffffffu, sum2, o);
            float inv2 = 1.f / sum2;

            // pass E: final probs into smem; zero the tail up to jmax
            int clim = (jmax + 31) >> 5;     // chunks needed by PV
            for (int c = 0; c < clim; c++) {
                int j = c*32 + lane;
                float val = 0.f;
                if (c <= cmask && j <= ig) val = __expf(row[j] - m2) * inv2;
                row[j] = val;
            }
        }
    }

    // ---- PV: warp w -> row half mt (16 rows), cols cg*8..cg*8+7
    float acc[4] = {0.f, 0.f, 0.f, 0.f};
    int rr = lane >> 2, kc = (lane & 3) * 2;
    int vrow = lane & 15;
    int ntiles = (jmax + 255) >> 8;
    for (int ji = 0; ji < ntiles; ji++) {
        int jbase = ji * 256;
        int rows = jmax - jbase; if (rows > 256) rows = 256;
        CPWAIT0();
        __syncthreads();
        if (ji + 1 < ntiles) {
            int nb = jbase + 256;
            int nrows = jmax - nb; if (nrows > 256) nrows = 256;
            loadV(nb, nrows, (ji + 1) & 1);
        }
        uint32_t VH = sb + AT_K + (ji & 1) * AT_KSZ;

        int nk = rows >> 4;
        for (int kk = 0; kk < nk; kk++) {
            int j0 = jbase + kk*16;
            uint32_t vh[2];
            uint32_t va = (uint32_t)(kk*16 + vrow)*144 + (uint32_t)cg*16;
            LDSM_X2T(vh, VH + va);
            const float* p0 = &sc[(mt*16 + rr)*SCP + j0 + kc];
            float f00 = p0[0],        f01 = p0[1];
            float f10 = p0[8*SCP],    f11 = p0[8*SCP+1];
            float f20 = p0[8],        f21 = p0[9];
            float f30 = p0[8*SCP+8],  f31 = p0[8*SCP+9];
            uint32_t a_h[4], a_l[4];
            a_h[0] = packh2(f00, f01); a_l[0] = packloh2(f00, f01, a_h[0]);
            a_h[1] = packh2(f10, f11); a_l[1] = packloh2(f10, f11, a_h[1]);
            a_h[2] = packh2(f20, f21); a_l[2] = packloh2(f20, f21, a_h[2]);
            a_h[3] = packh2(f30, f31); a_l[3] = packloh2(f30, f31, a_h[3]);
            mma_f16(acc, a_h, vh);
            mma_f16(acc, a_l, vh);
        }
    }

    // ---- epilogue -> concat single fp16
    {
        size_t o0 = ((size_t)b*SS + i0 + mt*16 + rr)*DD + h*64 + cg*8 + kc;
        size_t o1 = o0 + (size_t)8*DD;
        *(uint32_t*)&ohi[o0] = packh2(acc[0], acc[1]);
        *(uint32_t*)&ohi[o1] = packh2(acc[2], acc[3]);
    }
}

// ---------------- residual add + LayerNorm ----------------------------------
template<bool SPLITOUT>
__global__ void __launch_bounds__(256) add_ln_kernel(
    const float* __restrict__ A, const float* __restrict__ Bres,
    const float* __restrict__ w, const float* __restrict__ bias,
    float* __restrict__ outp,
    __half* __restrict__ ohi)
{
    __shared__ float red1[8], red2[8];
    int row = blockIdx.x;
    int t   = threadIdx.x;
    const float* pa = A    + (size_t)row*DD;
    const float* pb = Bres + (size_t)row*DD;

    float4 a4 = *(const float4*)&pa[t*4];
    float4 b4 = *(const float4*)&pb[t*4];
    float v0 = a4.x + b4.x, v1 = a4.y + b4.y, v2 = a4.z + b4.z, v3 = a4.w + b4.w;

    int lane = t & 31, wp = t >> 5;
    float s = v0 + v1 + v2 + v3;
#pragma unroll
    for (int o = 16; o > 0; o >>= 1) s += __shfl_xor_sync(0xffffffffu, s, o);
    if (lane == 0) red1[wp] = s;
    __syncthreads();
    float tot = 0.f;
#pragma unroll
    for (int i = 0; i < 8; i++) tot += red1[i];
    float mu = tot * (1.f / DD);

    float d0 = v0-mu, d1 = v1-mu, d2 = v2-mu, d3 = v3-mu;
    float q2 = d0*d0 + d1*d1 + d2*d2 + d3*d3;
#pragma unroll
    for (int o = 16; o > 0; o >>= 1) q2 += __shfl_xor_sync(0xffffffffu, q2, o);
    if (lane == 0) red2[wp] = q2;
    __syncthreads();
    float tv = 0.f;
#pragma unroll
    for (int i = 0; i < 8; i++) tv += red2[i];
    float inv = rsqrtf(tv * (1.f / DD) + 1e-5f);

    float4 w4  = *(const float4*)&w[t*4];
    float4 bi4 = *(const float4*)&bias[t*4];
    float4 o4;
    o4.x = d0*inv*w4.x + bi4.x;
    o4.y = d1*inv*w4.y + bi4.y;
    o4.z = d2*inv*w4.z + bi4.z;
    o4.w = d3*inv*w4.w + bi4.w;
    *(float4*)&outp[(size_t)row*DD + t*4] = o4;

    if (SPLITOUT) {
        uint32_t h0 = packh2(o4.x, o4.y), h1 = packh2(o4.z, o4.w);
        size_t base2 = (size_t)row * (DD/2) + t*2;
        ((uint32_t*)ohi)[base2]     = h0;
        ((uint32_t*)ohi)[base2 + 1] = h1;
    }
}

// ---------------- launcher ---------------------------------------------------
extern "C" void kernel_launch(void* const* d_in, const int* in_sizes, int n_in,
                              void* d_out, int out_size)
{
    int off = (in_sizes[0] == 1) ? 1 : 0;
    const float* query  = (const float*)d_in[off + 0];
    const float* key    = (const float*)d_in[off + 1];
    const float* values = (const float*)d_in[off + 2];
    const float* Wq = (const float*)d_in[off + 3];
    const float* bq = (const float*)d_in[off + 4];
    const float* Wk = (const float*)d_in[off + 5];
    const float* bk = (const float*)d_in[off + 6];
    const float* Wv = (const float*)d_in[off + 7];
    const float* bv = (const float*)d_in[off + 8];
    const float* Wo = (const float*)d_in[off + 9];
    const float* bo = (const float*)d_in[off + 10];
    const float* gammas = (const float*)d_in[off + 11];
    const float* ln1w = (const float*)d_in[off + 12];
    const float* ln1b = (const float*)d_in[off + 13];
    const float* W1 = (const float*)d_in[off + 14];
    const float* b1 = (const float*)d_in[off + 15];
    const float* W2 = (const float*)d_in[off + 16];
    const float* b2 = (const float*)d_in[off + 17];
    const float* ln2w = (const float*)d_in[off + 18];
    const float* ln2b = (const float*)d_in[off + 19];

    float *pattnout, *px, *pf;
    cudaGetSymbolAddress((void**)&pattnout, g_attnout);
    cudaGetSymbolAddress((void**)&px, g_x);
    cudaGetSymbolAddress((void**)&pf, g_f);

    __half *aq,*ak,*av;
    __half *wqh,*wkh,*wvh,*woh,*w1h,*w2h;
    __half *chi,*xh,*hh,*qhi,*qlo,*khi,*vhi;
    cudaGetSymbolAddress((void**)&aq, g_aq);
    cudaGetSymbolAddress((void**)&ak, g_ak);
    cudaGetSymbolAddress((void**)&av, g_av);
    cudaGetSymbolAddress((void**)&wqh, g_wq_h);
    cudaGetSymbolAddress((void**)&wkh, g_wk_h);
    cudaGetSymbolAddress((void**)&wvh, g_wv_h);
    cudaGetSymbolAddress((void**)&woh, g_wo_h);
    cudaGetSymbolAddress((void**)&w1h, g_w1_h);
    cudaGetSymbolAddress((void**)&w2h, g_w2_h);
    cudaGetSymbolAddress((void**)&chi, g_chi);
    cudaGetSymbolAddress((void**)&xh, g_xh);
    cudaGetSymbolAddress((void**)&hh, g_hh);
    cudaGetSymbolAddress((void**)&qhi, g_qhi);   cudaGetSymbolAddress((void**)&qlo, g_qlo);
    cudaGetSymbolAddress((void**)&khi, g_khi);
    cudaGetSymbolAddress((void**)&vhi, g_vhi);

    const int M = BB * SS;   // 4096
    cudaFuncSetAttribute(gemm_mma<false,false>, cudaFuncAttributeMaxDynamicSharedMemorySize, G_SMEM);
    cudaFuncSetAttribute(gemm_mma<false,true>,  cudaFuncAttributeMaxDynamicSharedMemorySize, G_SMEM);
    cudaFuncSetAttribute(gemm_mma<true,true>,   cudaFuncAttributeMaxDynamicSharedMemorySize, G_SMEM);
    cudaFuncSetAttribute(attn_kernel, cudaFuncAttributeMaxDynamicSharedMemorySize, AT_SMEM);

    // -------- 1. mega split --------
    {
        SplitArgs sa;
        const float* srcs[9] = {query, key, values, Wq, Wk, Wv, Wo, W1, W2};
        __half* his[9] = {aq, ak, av, wqh, wkh, wvh, woh, w1h, w2h};
        int nblk[9] = {4096, 4096, 4096, 1024, 1024, 1024, 1024, 4096, 4096};
        int cum = 0;
        for (int i = 0; i < 9; i++) {
            sa.seg[i].src = srcs[i]; sa.seg[i].hi = his[i];
            sa.start[i] = cum; cum += nblk[i];
        }
        sa.start[9] = cum;
        multi_split_kernel<<<cum, 256>>>(sa);
    }

    // -------- 2. QKV projections (q emits hi+lo; k, v hi only) --------
    {
        GemmIO q = {aq, wqh, bq, nullptr, qhi, qlo};
        GemmIO k = {ak, wkh, bk, nullptr, khi, nullptr};
        GemmIO v = {av, wvh, bv, nullptr, vhi, nullptr};
        gemm_mma<false,true><<<dim3(DD/128, M/256, 3), 512, G_SMEM>>>(q, k, v, M, DD, DD);
    }

    // -------- 3. attention --------
    attn_kernel<<<dim3(SS/32, HH, BB), 512, AT_SMEM>>>(qhi, qlo, khi, vhi, gammas, chi);

    // -------- 4. output projection --------
    {
        GemmIO o = {chi, woh, bo, pattnout, nullptr, nullptr};
        gemm_mma<false,false><<<dim3(DD/128, M/256, 1), 512, G_SMEM>>>(o, o, o, M, DD, DD);
    }

    // -------- 5. LN1 --------
    add_ln_kernel<true><<<M, 256>>>(query, pattnout, ln1w, ln1b, px, xh);

    // -------- 6. FFN1 (+ReLU) --------
    {
        GemmIO f1 = {xh, w1h, b1, nullptr, hh, nullptr};
        gemm_mma<true,true><<<dim3(DFFF/128, M/256, 1), 512, G_SMEM>>>(f1, f1, f1, M, DFFF, DD);
    }

    // -------- 7. FFN2 --------
    {
        GemmIO f2 = {hh, w2h, b2, pf, nullptr, nullptr};
        gemm_mma<false,false><<<dim3(DD/128, M/256, 1), 512, G_SMEM>>>(f2, f2, f2, M, DD, DFFF);
    }

    // -------- 8. LN2 --------
    add_ln_kernel<false><<<M, 256>>>(px, pf, ln2w, ln2b, (float*)d_out, nullptr);
}

// round 13
// speedup vs baseline: 5.1264x; 1.0313x over previous
#include <cuda_runtime.h>
#include <cuda_fp16.h>
#include <math.h>
#include <stdint.h>

// Problem constants
#define BB 4
#define SS 1024
#define DD 1024
#define HH 16
#define DKK 64
#define DFFF 4096
#define SCP 1032   // score row pitch (floats)

// ---------------- scratch (device globals) -----------------------------------
__device__ float g_attnout[BB*SS*DD];
__device__ float g_x[BB*SS*DD];
__device__ float g_f[BB*SS*DD];
__device__ __half g_aq[BB*SS*DD];
__device__ __half g_ak[BB*SS*DD];
__device__ __half g_av[BB*SS*DD];
__device__ __half g_wq_h[DD*DD];
__device__ __half g_wk_h[DD*DD];
__device__ __half g_wv_h[DD*DD];
__device__ __half g_wo_h[DD*DD];
__device__ __half g_w1_h[DFFF*DD];
__device__ __half g_w2_h[DD*DFFF];
__device__ __half g_chi[BB*SS*DD];
__device__ __half g_xh[BB*SS*DD];
__device__ __half g_hh[BB*SS*DFFF];
__device__ __half g_qhi[BB*SS*DD], g_qlo[BB*SS*DD];
__device__ __half g_khi[BB*SS*DD];
__device__ __half g_vhi[BB*SS*DD];

// ======================= PTX helpers ========================================
__device__ __forceinline__ uint32_t smem_u32(const void* p) {
    uint32_t a;
    asm("{ .reg .u64 t; cvta.to.shared.u64 t, %1; cvt.u32.u64 %0, t; }" : "=r"(a) : "l"(p));
    return a;
}

#define CPASYNC16(dst, src) asm volatile("cp.async.cg.shared.global [%0], [%1], 16;" :: "r"(dst), "l"(src) : "memory")
#define CPCOMMIT() asm volatile("cp.async.commit_group;" ::: "memory")
#define CPWAIT1()  asm volatile("cp.async.wait_group 1;" ::: "memory")
#define CPWAIT0()  asm volatile("cp.async.wait_group 0;" ::: "memory")

#define LDSM_X4(R, A) \
    asm volatile("ldmatrix.sync.aligned.m8n8.x4.shared.b16 {%0,%1,%2,%3}, [%4];" \
        : "=r"((R)[0]), "=r"((R)[1]), "=r"((R)[2]), "=r"((R)[3]) : "r"(A))

#define LDSM_X2T(R, A) \
    asm volatile("ldmatrix.sync.aligned.m8n8.x2.trans.shared.b16 {%0,%1}, [%2];" \
        : "=r"((R)[0]), "=r"((R)[1]) : "r"(A))

__device__ __forceinline__ void mma_f16(float* c, const uint32_t* a, const uint32_t* b) {
    asm volatile(
        "mma.sync.aligned.m16n8k16.row.col.f32.f16.f16.f32 "
        "{%0,%1,%2,%3}, {%4,%5,%6,%7}, {%8,%9}, {%0,%1,%2,%3};"
        : "+f"(c[0]), "+f"(c[1]), "+f"(c[2]), "+f"(c[3])
        : "r"(a[0]), "r"(a[1]), "r"(a[2]), "r"(a[3]), "r"(b[0]), "r"(b[1]));
}

__device__ __forceinline__ uint32_t packh2(float x, float y) {
    __half2 t = __floats2half2_rn(x, y);
    return *reinterpret_cast<uint32_t*>(&t);
}
__device__ __forceinline__ uint32_t packloh2(float x, float y, uint32_t hi) {
    __half2 h = *reinterpret_cast<__half2*>(&hi);
    return packh2(x - __half2float(h.x), y - __half2float(h.y));
}

// ================ mega split: fp32 -> single fp16 ===========================
struct SplitSeg { const float* src; __half* hi; };
struct SplitArgs { SplitSeg seg[9]; int start[10]; };

__global__ void __launch_bounds__(256) multi_split_kernel(SplitArgs a)
{
    int bx = blockIdx.x;
    int s = 0;
#pragma unroll
    for (int i = 0; i < 8; i++) if (bx >= a.start[i+1]) s = i+1;
    SplitSeg sg = a.seg[s];
    int i = (bx - a.start[s]) * 256 + threadIdx.x;
    float4 v = ((const float4*)sg.src)[i];
    uint32_t h0 = packh2(v.x, v.y), h1 = packh2(v.z, v.w);
    ((uint32_t*)sg.hi)[i*2+0] = h0;
    ((uint32_t*)sg.hi)[i*2+1] = h1;
}

// ====== fp16 GEMM: C = A @ W^T + bias, tile 256x128, K-chunk 64, 3 stages ===
#define G_BH 36864
#define G_STAGE 55296
#define G_SMEM (3 * G_STAGE)   // 165888

struct GemmIO {
    const __half *Ah, *Wh;
    const float* bias;
    float* C;
    __half *Chi, *Clo;   // Clo may be null
};

template<bool RELU, bool SPLITOUT>
__global__ void __launch_bounds__(512, 1) gemm_mma(
    GemmIO io0, GemmIO io1, GemmIO io2, int M, int N, int K)
{
    extern __shared__ __align__(128) char smem[];
    uint32_t sb = smem_u32(smem);

    GemmIO io = (blockIdx.z == 0) ? io0 : (blockIdx.z == 1) ? io1 : io2;

    int tid  = threadIdx.x;
    int lane = tid & 31;
    int wid  = tid >> 5;
    int wm   = wid & 3;
    int wn   = wid >> 2;
    int bm = blockIdx.y * 256;
    int bn = blockIdx.x * 128;

    const int nch = K >> 6;

    auto load_stage = [&](int c) {
        uint32_t st = sb + (c % 3) * G_STAGE;
        size_t kof = (size_t)c * 64;
        const __half* a_h = io.Ah + (size_t)bm * K + kof;
        const __half* b_h = io.Wh + (size_t)bn * K + kof;
#pragma unroll
        for (int u = 0; u < 4; u++) {
            int l = tid + u * 512;
            int row = l >> 3, ch = l & 7;
            CPASYNC16(st + row*144 + ch*16, (const char*)(a_h + (size_t)row*K) + ch*16);
        }
#pragma unroll
        for (int u = 0; u < 2; u++) {
            int l = tid + u * 512;
            int row = l >> 3, ch = l & 7;
            CPASYNC16(st + G_BH + row*144 + ch*16, (const char*)(b_h + (size_t)row*K) + ch*16);
        }
        CPCOMMIT();
    };

    uint32_t aoff = ((((lane >> 3) & 1) * 8 + (lane & 7)) * 144) + (lane >> 4) * 16;
    uint32_t boff = (((lane >> 4) * 8 + (lane & 7)) * 144) + ((lane >> 3) & 1) * 16;

    float acc[4][4][4];
#pragma unroll
    for (int mt = 0; mt < 4; mt++)
#pragma unroll
        for (int n8 = 0; n8 < 4; n8++)
#pragma unroll
            for (int k = 0; k < 4; k++) acc[mt][n8][k] = 0.f;

    load_stage(0);
    load_stage(1);
    for (int c = 0; c < nch; c++) {
        if (c + 1 < nch) { CPWAIT1(); } else { CPWAIT0(); }
        __syncthreads();
        if (c + 2 < nch) load_stage(c + 2);

        uint32_t st = sb + (c % 3) * G_STAGE;
        uint32_t aH = st        + (wm * 64) * 144 + aoff;
        uint32_t bH = st + G_BH + (wn * 32) * 144 + boff;

#pragma unroll
        for (int ks = 0; ks < 4; ks++) {
            uint32_t ah[4][4];
#pragma unroll
            for (int mt = 0; mt < 4; mt++)
                LDSM_X4(ah[mt], aH + mt * (16*144) + ks * 32);
#pragma unroll
            for (int g = 0; g < 2; g++) {
                uint32_t bh[4];
                LDSM_X4(bh, bH + g * (16*144) + ks * 32);
#pragma unroll
                for (int mt = 0; mt < 4; mt++)
#pragma unroll
                    for (int hf = 0; hf < 2; hf++)
                        mma_f16(acc[mt][g*2+hf], ah[mt], &bh[hf*2]);
            }
        }
    }

    int r_in = lane >> 2;
    int c_in = (lane & 3) * 2;
    bool wlo = SPLITOUT && (io.Clo != nullptr);
#pragma unroll
    for (int mt = 0; mt < 4; mt++) {
        int R0 = bm + wm * 64 + mt * 16 + r_in;
        int R1 = R0 + 8;
#pragma unroll
        for (int n8 = 0; n8 < 4; n8++) {
            int col = bn + wn * 32 + n8 * 8 + c_in;
            float b0 = io.bias[col], b1 = io.bias[col + 1];
            float o00 = acc[mt][n8][0] + b0, o01 = acc[mt][n8][1] + b1;
            float o10 = acc[mt][n8][2] + b0, o11 = acc[mt][n8][3] + b1;
            if (RELU) {
                o00 = fmaxf(o00, 0.f); o01 = fmaxf(o01, 0.f);
                o10 = fmaxf(o10, 0.f); o11 = fmaxf(o11, 0.f);
            }
            if (SPLITOUT) {
                uint32_t h0 = packh2(o00, o01), h1 = packh2(o10, o11);
                *(uint32_t*)&io.Chi[(size_t)R0 * N + col] = h0;
                *(uint32_t*)&io.Chi[(size_t)R1 * N + col] = h1;
                if (wlo) {
                    uint32_t l0 = packloh2(o00, o01, h0), l1 = packloh2(o10, o11, h1);
                    *(uint32_t*)&io.Clo[(size_t)R0 * N + col] = l0;
                    *(uint32_t*)&io.Clo[(size_t)R1 * N + col] = l1;
                }
            } else {
                float2 o0, o1;
                o0.x = o00; o0.y = o01; o1.x = o10; o1.y = o11;
                *(float2*)&io.C[(size_t)R0 * N + col] = o0;
                *(float2*)&io.C[(size_t)R1 * N + col] = o1;
            }
        }
    }
}

// ================= tensor-core distance-decay attention ======================
// 512 threads, 32 rows/CTA. Grid (64, 32): x = h + 16*b, y = i0 tile —
// consecutive block ids share i0 so each wave is load-balanced.
#define AT_QH 132096
#define AT_QL 136704
#define AT_K  141312
#define AT_KSZ 36864
#define AT_SMEM 215040

__global__ void __launch_bounds__(512, 1) attn_kernel(
    const __half* __restrict__ qhi, const __half* __restrict__ qlo,
    const __half* __restrict__ khi, const __half* __restrict__ vhi,
    const float* __restrict__ gammas,
    __half* __restrict__ ohi)
{
    extern __shared__ __align__(128) char smx[];
    float* sc = (float*)smx;
    uint32_t sb = smem_u32(smx);
    const uint32_t QH = sb + AT_QH;
    const uint32_t QL = sb + AT_QL;

    int h = blockIdx.x & 15, b = blockIdx.x >> 4;
    int i0 = blockIdx.y * 32;
    int t = threadIdx.x, lane = t & 31, w = t >> 5;
    int mt = w & 1;
    int cg = w >> 1;

    size_t base_q = ((size_t)b*SS + i0)*DD + h*64;
    size_t base_k = (size_t)b*SS*DD + h*64;

    // ---- load Q tile (32 rows, hi+lo)
    {
        int sel = t >> 8;
        int idx = t & 255;
        int row = idx >> 3, ch = idx & 7;
        const __half* src = (sel ? qlo : qhi) + base_q + (size_t)row*DD + ch*8;
        char* dst = smx + (sel ? AT_QL : AT_QH) + row*144 + ch*16;
        *(float4*)dst = *(const float4*)src;
    }
    __syncthreads();

    uint32_t aoff = ((((lane >> 3) & 1) * 8 + (lane & 7)) * 144) + (lane >> 4) * 16;
    uint32_t boff = (((lane >> 4) * 8 + (lane & 7)) * 144) + ((lane >> 3) & 1) * 16;

    uint32_t ah[4][4], al[4][4];
#pragma unroll
    for (int ks = 0; ks < 4; ks++) {
        LDSM_X4(ah[ks], QH + mt*(16*144) + aoff + ks*32);
        LDSM_X4(al[ks], QL + mt*(16*144) + aoff + ks*32);
    }

    auto loadK = [&](int jt, int bf) {
        uint32_t KH = sb + AT_K + bf * AT_KSZ;
        int jbase = jt * 256;
#pragma unroll
        for (int u = 0; u < 4; u++) {
            int l = t + u * 512;
            int row = l >> 3, ch = l & 7;
            const char* sh = (const char*)(khi + base_k + (size_t)(jbase+row)*DD) + ch*16;
            CPASYNC16(KH + row*144 + ch*16, sh);
        }
        CPCOMMIT();
    };

    // ---- QK^T: 4 tiles of 256 cols, double-buffered
    loadK(0, 0);
    for (int jt = 0; jt < 4; jt++) {
        CPWAIT0();
        __syncthreads();
        if (jt + 1 < 4) loadK(jt + 1, (jt + 1) & 1);

        uint32_t KH = sb + AT_K + (jt & 1) * AT_KSZ;
#pragma unroll
        for (int half = 0; half < 2; half++) {
            float c0[4] = {0,0,0,0}, c1[4] = {0,0,0,0};
            uint32_t bb = (uint32_t)(half*128 + cg*16)*144 + boff;
#pragma unroll
            for (int ks = 0; ks < 4; ks++) {
                uint32_t bh[4];
                LDSM_X4(bh, KH + bb + ks*32);
                mma_f16(c0, ah[ks], &bh[0]);
                mma_f16(c0, al[ks], &bh[0]);
                mma_f16(c1, ah[ks], &bh[2]);
                mma_f16(c1, al[ks], &bh[2]);
            }
            int r0 = mt*16 + (lane >> 2);
            int cb = jt*256 + half*128 + cg*16 + (lane & 3)*2;
            float2 v2;
            v2.x = c0[0]*0.125f; v2.y = c0[1]*0.125f; *(float2*)&sc[r0*SCP + cb] = v2;
            v2.x = c0[2]*0.125f; v2.y = c0[3]*0.125f; *(float2*)&sc[(r0+8)*SCP + cb] = v2;
            v2.x = c1[0]*0.125f; v2.y = c1[1]*0.125f; *(float2*)&sc[r0*SCP + cb + 8] = v2;
            v2.x = c1[2]*0.125f; v2.y = c1[3]*0.125f; *(float2*)&sc[(r0+8)*SCP + cb + 8] = v2;
        }
    }

    int jmax = i0 + 32;
    auto loadV = [&](int jbase, int rows, int bf) {
        uint32_t VH = sb + AT_K + bf * AT_KSZ;
        int total = rows * 8;
#pragma unroll
        for (int u = 0; u < 4; u++) {
            int l = t + u * 512;
            if (l < total) {
                int row = l >> 3, ch = l & 7;
                const char* sh = (const char*)(vhi + base_k + (size_t)(jbase+row)*DD) + ch*16;
                CPASYNC16(VH + row*144 + ch*16, sh);
            }
        }
        CPCOMMIT();
    };

    // prefetch V tile 0 into buffer 0 (jt=3 used buffer 1) — hidden under row math
    loadV(0, jmax < 256 ? jmax : 256, 0);
    __syncthreads();   // sc writes visible before row math

    // ---- per-row math: 2 rows per warp, array-free, pass-C unrolled x2
    {
        float gamma = -log1pf(__expf(gammas[h]));
        for (int rr2 = 0; rr2 < 2; rr2++) {
            int r  = w*2 + rr2;
            int ig = i0 + r;
            float* row = sc + r*SCP;
            int cmask = ig >> 5;

            // pass A: row max
            float m = -INFINITY;
            for (int c = 0; c < 32; c++) m = fmaxf(m, row[c*32 + lane]);
#pragma unroll
            for (int o = 16; o > 0; o >>= 1) m = fmaxf(m, __shfl_xor_sync(0xffffffffu, m, o));

            // pass B: sums
            float sum1 = 0.f, summ = 0.f;
            for (int c = 0; c < 32; c++) {
                int j = c*32 + lane;
                float pfull = __expf(row[j] - m);
                sum1 += pfull;
                if (j <= ig) summ += pfull;
            }
#pragma unroll
            for (int o = 16; o > 0; o >>= 1) {
                sum1 += __shfl_xor_sync(0xffffffffu, sum1, o);
                summ += __shfl_xor_sync(0xffffffffu, summ, o);
            }
            float inv1 = 1.f / sum1;

            // pass C: fused scan + decay, 2 chunks per iteration with
            // independent interleaved scans (serial chain = carry adds only)
            float carry = 0.f, m2 = -INFINITY;
            for (int c = 0; c <= cmask; c += 2) {
                int j0 = c*32 + lane;
                int j1 = j0 + 32;
                bool has1 = (c + 1 <= cmask);
                float s0 = row[j0];
                float s1v = has1 ? row[j1] : -INFINITY;
                float x0 = (j0 <= ig) ? __expf(s0 - m) : 0.f;
                float x1 = (has1 && j1 <= ig) ? __expf(s1v - m) : 0.f;
#pragma unroll
                for (int o = 1; o < 32; o <<= 1) {
                    float y0 = __shfl_up_sync(0xffffffffu, x0, o);
                    float y1 = __shfl_up_sync(0xffffffffu, x1, o);
                    if (lane >= o) { x0 += y0; x1 += y1; }
                }
                float t0 = __shfl_sync(0xffffffffu, x0, 31);
                float t1 = __shfl_sync(0xffffffffu, x1, 31);
                float d0 = carry + x0;
                float d1 = carry + t0 + x1;
                carry += t0 + t1;
                {
                    float pos  = fabsf((float)(ig - j0));
                    float dd   = (summ - d0) * inv1 * pos;
                    float dist = sqrtf(fmaxf(dd, 0.f));
                    float eff  = fminf(fmaxf(__expf(dist * gamma), 1e-5f), 1e5f);
                    float s2 = (j0 <= ig) ? s0 * eff : -INFINITY;
                    row[j0] = s2;
                    m2 = fmaxf(m2, s2);
                }
                if (has1) {
                    float pos  = fabsf((float)(ig - j1));
                    float dd   = (summ - d1) * inv1 * pos;
                    float dist = sqrtf(fmaxf(dd, 0.f));
                    float eff  = fminf(fmaxf(__expf(dist * gamma), 1e-5f), 1e5f);
                    float s2 = (j1 <= ig) ? s1v * eff : -INFINITY;
                    row[j1] = s2;
                    m2 = fmaxf(m2, s2);
                }
            }
#pragma unroll
            for (int o = 16; o > 0; o >>= 1) m2 = fmaxf(m2, __shfl_xor_sync(0xffffffffu, m2, o));

            // pass D: sum2
            float sum2 = 0.f;
            for (int c = 0; c <= cmask; c++) {
                int j = c*32 + lane;
                sum2 += (j <= ig) ? __expf(row[j] - m2) : 0.f;
            }
#pragma unroll
            for (int o = 16; o > 0; o >>= 1) sum2 += __shfl_xor_sync(0xffffffffu, sum2, o);
            float inv2 = 1.f / sum2;

            // pass E: final probs; zero tail up to jmax
            int clim = (jmax + 31) >> 5;
            for (int c = 0; c < clim; c++) {
                int j = c*32 + lane;
                float val = 0.f;
                if (c <= cmask && j <= ig) val = __expf(row[j] - m2) * inv2;
                row[j] = val;
            }
        }
    }

    // ---- PV
    float acc[4] = {0.f, 0.f, 0.f, 0.f};
    int rr = lane >> 2, kc = (lane & 3) * 2;
    int vrow = lane & 15;
    int ntiles = (jmax + 255) >> 8;
    for (int ji = 0; ji < ntiles; ji++) {
        int jbase = ji * 256;
        int rows = jmax - jbase; if (rows > 256) rows = 256;
        CPWAIT0();
        __syncthreads();
        if (ji + 1 < ntiles) {
            int nb = jbase + 256;
            int nrows = jmax - nb; if (nrows > 256) nrows = 256;
            loadV(nb, nrows, (ji + 1) & 1);
        }
        uint32_t VH = sb + AT_K + (ji & 1) * AT_KSZ;

        int nk = rows >> 4;
        for (int kk = 0; kk < nk; kk++) {
            int j0 = jbase + kk*16;
            uint32_t vh[2];
            uint32_t va = (uint32_t)(kk*16 + vrow)*144 + (uint32_t)cg*16;
            LDSM_X2T(vh, VH + va);
            const float* p0 = &sc[(mt*16 + rr)*SCP + j0 + kc];
            float f00 = p0[0],        f01 = p0[1];
            float f10 = p0[8*SCP],    f11 = p0[8*SCP+1];
            float f20 = p0[8],        f21 = p0[9];
            float f30 = p0[8*SCP+8],  f31 = p0[8*SCP+9];
            uint32_t a_h[4], a_l[4];
            a_h[0] = packh2(f00, f01); a_l[0] = packloh2(f00, f01, a_h[0]);
            a_h[1] = packh2(f10, f11); a_l[1] = packloh2(f10, f11, a_h[1]);
            a_h[2] = packh2(f20, f21); a_l[2] = packloh2(f20, f21, a_h[2]);
            a_h[3] = packh2(f30, f31); a_l[3] = packloh2(f30, f31, a_h[3]);
            mma_f16(acc, a_h, vh);
            mma_f16(acc, a_l, vh);
        }
    }

    // ---- epilogue -> concat single fp16
    {
        size_t o0 = ((size_t)b*SS + i0 + mt*16 + rr)*DD + h*64 + cg*8 + kc;
        size_t o1 = o0 + (size_t)8*DD;
        *(uint32_t*)&ohi[o0] = packh2(acc[0], acc[1]);
        *(uint32_t*)&ohi[o1] = packh2(acc[2], acc[3]);
    }
}

// ---------------- residual add + LayerNorm ----------------------------------
template<bool SPLITOUT>
__global__ void __launch_bounds__(256) add_ln_kernel(
    const float* __restrict__ A, const float* __restrict__ Bres,
    const float* __restrict__ w, const float* __restrict__ bias,
    float* __restrict__ outp,
    __half* __restrict__ ohi)
{
    __shared__ float red1[8], red2[8];
    int row = blockIdx.x;
    int t   = threadIdx.x;
    const float* pa = A    + (size_t)row*DD;
    const float* pb = Bres + (size_t)row*DD;

    float4 a4 = *(const float4*)&pa[t*4];
    float4 b4 = *(const float4*)&pb[t*4];
    float v0 = a4.x + b4.x, v1 = a4.y + b4.y, v2 = a4.z + b4.z, v3 = a4.w + b4.w;

    int lane = t & 31, wp = t >> 5;
    float s = v0 + v1 + v2 + v3;
#pragma unroll
    for (int o = 16; o > 0; o >>= 1) s += __shfl_xor_sync(0xffffffffu, s, o);
    if (lane == 0) red1[wp] = s;
    __syncthreads();
    float tot = 0.f;
#pragma unroll
    for (int i = 0; i < 8; i++) tot += red1[i];
    float mu = tot * (1.f / DD);

    float d0 = v0-mu, d1 = v1-mu, d2 = v2-mu, d3 = v3-mu;
    float q2 = d0*d0 + d1*d1 + d2*d2 + d3*d3;
#pragma unroll
    for (int o = 16; o > 0; o >>= 1) q2 += __shfl_xor_sync(0xffffffffu, q2, o);
    if (lane == 0) red2[wp] = q2;
    __syncthreads();
    float tv = 0.f;
#pragma unroll
    for (int i = 0; i < 8; i++) tv += red2[i];
    float inv = rsqrtf(tv * (1.f / DD) + 1e-5f);

    float4 w4  = *(const float4*)&w[t*4];
    float4 bi4 = *(const float4*)&bias[t*4];
    float4 o4;
    o4.x = d0*inv*w4.x + bi4.x;
    o4.y = d1*inv*w4.y + bi4.y;
    o4.z = d2*inv*w4.z + bi4.z;
    o4.w = d3*inv*w4.w + bi4.w;
    *(float4*)&outp[(size_t)row*DD + t*4] = o4;

    if (SPLITOUT) {
        uint32_t h0 = packh2(o4.x, o4.y), h1 = packh2(o4.z, o4.w);
        size_t base2 = (size_t)row * (DD/2) + t*2;
        ((uint32_t*)ohi)[base2]     = h0;
        ((uint32_t*)ohi)[base2 + 1] = h1;
    }
}

// ---------------- launcher ---------------------------------------------------
extern "C" void kernel_launch(void* const* d_in, const int* in_sizes, int n_in,
                              void* d_out, int out_size)
{
    int off = (in_sizes[0] == 1) ? 1 : 0;
    const float* query  = (const float*)d_in[off + 0];
    const float* key    = (const float*)d_in[off + 1];
    const float* values = (const float*)d_in[off + 2];
    const float* Wq = (const float*)d_in[off + 3];
    const float* bq = (const float*)d_in[off + 4];
    const float* Wk = (const float*)d_in[off + 5];
    const float* bk = (const float*)d_in[off + 6];
    const float* Wv = (const float*)d_in[off + 7];
    const float* bv = (const float*)d_in[off + 8];
    const float* Wo = (const float*)d_in[off + 9];
    const float* bo = (const float*)d_in[off + 10];
    const float* gammas = (const float*)d_in[off + 11];
    const float* ln1w = (const float*)d_in[off + 12];
    const float* ln1b = (const float*)d_in[off + 13];
    const float* W1 = (const float*)d_in[off + 14];
    const float* b1 = (const float*)d_in[off + 15];
    const float* W2 = (const float*)d_in[off + 16];
    const float* b2 = (const float*)d_in[off + 17];
    const float* ln2w = (const float*)d_in[off + 18];
    const float* ln2b = (const float*)d_in[off + 19];

    float *pattnout, *px, *pf;
    cudaGetSymbolAddress((void**)&pattnout, g_attnout);
    cudaGetSymbolAddress((void**)&px, g_x);
    cudaGetSymbolAddress((void**)&pf, g_f);

    __half *aq,*ak,*av;
    __half *wqh,*wkh,*wvh,*woh,*w1h,*w2h;
    __half *chi,*xh,*hh,*qhi,*qlo,*khi,*vhi;
    cudaGetSymbolAddress((void**)&aq, g_aq);
    cudaGetSymbolAddress((void**)&ak, g_ak);
    cudaGetSymbolAddress((void**)&av, g_av);
    cudaGetSymbolAddress((void**)&wqh, g_wq_h);
    cudaGetSymbolAddress((void**)&wkh, g_wk_h);
    cudaGetSymbolAddress((void**)&wvh, g_wv_h);
    cudaGetSymbolAddress((void**)&woh, g_wo_h);
    cudaGetSymbolAddress((void**)&w1h, g_w1_h);
    cudaGetSymbolAddress((void**)&w2h, g_w2_h);
    cudaGetSymbolAddress((void**)&chi, g_chi);
    cudaGetSymbolAddress((void**)&xh, g_xh);
    cudaGetSymbolAddress((void**)&hh, g_hh);
    cudaGetSymbolAddress((void**)&qhi, g_qhi);   cudaGetSymbolAddress((void**)&qlo, g_qlo);
    cudaGetSymbolAddress((void**)&khi, g_khi);
    cudaGetSymbolAddress((void**)&vhi, g_vhi);

    const int M = BB * SS;   // 4096
    cudaFuncSetAttribute(gemm_mma<false,false>, cudaFuncAttributeMaxDynamicSharedMemorySize, G_SMEM);
    cudaFuncSetAttribute(gemm_mma<false,true>,  cudaFuncAttributeMaxDynamicSharedMemorySize, G_SMEM);
    cudaFuncSetAttribute(gemm_mma<true,true>,   cudaFuncAttributeMaxDynamicSharedMemorySize, G_SMEM);
    cudaFuncSetAttribute(attn_kernel, cudaFuncAttributeMaxDynamicSharedMemorySize, AT_SMEM);

    // -------- 1. mega split --------
    {
        SplitArgs sa;
        const float* srcs[9] = {query, key, values, Wq, Wk, Wv, Wo, W1, W2};
        __half* his[9] = {aq, ak, av, wqh, wkh, wvh, woh, w1h, w2h};
        int nblk[9] = {4096, 4096, 4096, 1024, 1024, 1024, 1024, 4096, 4096};
        int cum = 0;
        for (int i = 0; i < 9; i++) {
            sa.seg[i].src = srcs[i]; sa.seg[i].hi = his[i];
            sa.start[i] = cum; cum += nblk[i];
        }
        sa.start[9] = cum;
        multi_split_kernel<<<cum, 256>>>(sa);
    }

    // -------- 2. QKV projections (q emits hi+lo; k, v hi only) --------
    {
        GemmIO q = {aq, wqh, bq, nullptr, qhi, qlo};
        GemmIO k = {ak, wkh, bk, nullptr, khi, nullptr};
        GemmIO v = {av, wvh, bv, nullptr, vhi, nullptr};
        gemm_mma<false,true><<<dim3(DD/128, M/256, 3), 512, G_SMEM>>>(q, k, v, M, DD, DD);
    }

    // -------- 3. attention (wave-balanced grid) --------
    attn_kernel<<<dim3(HH*BB, SS/32, 1), 512, AT_SMEM>>>(qhi, qlo, khi, vhi, gammas, chi);

    // -------- 4. output projection --------
    {
        GemmIO o = {chi, woh, bo, pattnout, nullptr, nullptr};
        gemm_mma<false,false><<<dim3(DD/128, M/256, 1), 512, G_SMEM>>>(o, o, o, M, DD, DD);
    }

    // -------- 5. LN1 --------
    add_ln_kernel<true><<<M, 256>>>(query, pattnout, ln1w, ln1b, px, xh);

    // -------- 6. FFN1 (+ReLU) --------
    {
        GemmIO f1 = {xh, w1h, b1, nullptr, hh, nullptr};
        gemm_mma<true,true><<<dim3(DFFF/128, M/256, 1), 512, G_SMEM>>>(f1, f1, f1, M, DFFF, DD);
    }

    // -------- 7. FFN2 --------
    {
        GemmIO f2 = {hh, w2h, b2, pf, nullptr, nullptr};
        gemm_mma<false,false><<<dim3(DD/128, M/256, 1), 512, G_SMEM>>>(f2, f2, f2, M, DD, DFFF);
    }

    // -------- 8. LN2 --------
    add_ln_kernel<false><<<M, 256>>>(px, pf, ln2w, ln2b, (float*)d_out, nullptr);
}